// round 8
// baseline (speedup 1.0000x reference)
#include <cuda_runtime.h>
#include <math.h>
#include <stdint.h>

#define Nn 2048
#define Cc 1024
#define Hh 8
#define HD 128
#define SCALE_F 25.0f

// ---------------- scratch ----------------
__device__ float g_qkv[Nn * 3 * Cc];
__device__ float g_q[Hh * Nn * HD];
__device__ float g_k[Hh * Nn * HD];
__device__ float g_vn[Nn * Cc];
__device__ float g_vT[Hh * HD * Nn];
__device__ float g_rowsum[Hh * Nn];
__device__ float g_part[(size_t)16 * Nn * HD];   // attn@V split-K partials (kz=2)
__device__ float g_es[(size_t)Nn * Nn];
__device__ float g_srow[Nn];
__device__ uint8_t g_mask[(size_t)Nn * Nn];

// packed 2-term bf16 fragment images; tile = 128 rows x 16 k (stride 768 uint4)
__device__ uint4 g_xp [(size_t)16 * 64 * 768];
__device__ uint4 g_Wp [(size_t)24 * 64 * 768];
__device__ uint4 g_qp [(size_t)8 * 16 * 8 * 768];
__device__ uint4 g_kp [(size_t)8 * 16 * 8 * 768];
__device__ uint4 g_vnpA[(size_t)16 * 64 * 768];
__device__ uint4 g_vnpB[(size_t)16 * 64 * 768];
__device__ uint4 g_vTp[(size_t)8 * 128 * 768];
__device__ uint4 g_epk[(size_t)8 * 16 * 128 * 768];

// ---------------- helpers ----------------
__device__ __forceinline__ uint32_t packbf(float x, float y)
{
    uint32_t h;
    asm("cvt.rn.bf16x2.f32 %0, %1, %2;" : "=r"(h) : "f"(y), "f"(x));
    return h;
}
__device__ __forceinline__ float blo(uint32_t u) { return __uint_as_float(u << 16); }
__device__ __forceinline__ float bhi(uint32_t u) { return __uint_as_float(u & 0xFFFF0000u); }
__device__ __forceinline__ void split2(float x, float y, uint32_t& s0, uint32_t& s1)
{
    s0 = packbf(x, y);
    s1 = packbf(x - blo(s0), y - bhi(s0));
}

__device__ __forceinline__ void mma_bf16(float c[4], const uint32_t a[4],
                                         uint32_t b0, uint32_t b1)
{
    asm volatile(
        "mma.sync.aligned.m16n8k16.row.col.f32.bf16.bf16.f32 "
        "{%0,%1,%2,%3}, {%4,%5,%6,%7}, {%8,%9}, {%0,%1,%2,%3};"
        : "+f"(c[0]), "+f"(c[1]), "+f"(c[2]), "+f"(c[3])
        : "r"(a[0]), "r"(a[1]), "r"(a[2]), "r"(a[3]), "r"(b0), "r"(b1));
}

__device__ __forceinline__ void cpa16(void* smem, const void* gmem)
{
    uint32_t s = (uint32_t)__cvta_generic_to_shared(smem);
    asm volatile("cp.async.cg.shared.global [%0], [%1], 16;" :: "r"(s), "l"(gmem));
}
#define CP_COMMIT() asm volatile("cp.async.commit_group;")
#define CP_WAIT1()  asm volatile("cp.async.wait_group 1;")
#define CP_WAIT0()  asm volatile("cp.async.wait_group 0;")

// ---------------- pack kernels ----------------
__global__ __launch_bounds__(256) void pack_a2(
    const float* __restrict__ src, int lda, long long zstride, uint4* __restrict__ dst, int nKb)
{
    const int kb = blockIdx.x, rb = blockIdx.y, z = blockIdx.z;
    src += (long long)z * zstride;
    uint32_t* tb = (uint32_t*)(dst + ((size_t)(z * gridDim.y + rb) * nKb + kb) * 768);
    const int tid = threadIdx.x;
    #pragma unroll
    for (int t = 0; t < 2; t++) {
        int idx = tid + t * 256;
        int row = idx >> 2, k4 = (idx & 3) * 4;
        float4 v = *reinterpret_cast<const float4*>(
            &src[(long long)(rb * 128 + row) * lda + kb * 16 + k4]);
        int m = row >> 4, r16 = row & 15, g = r16 & 7, half = r16 >> 3;
        int tt = (k4 & 7) >> 1, reg = half + 2 * (k4 >> 3);
        int base = (m * 32 + g * 4 + tt) * 4 + reg;
        uint32_t s0, s1;
        split2(v.x, v.y, s0, s1);
        tb[base] = s0; tb[1024 + base] = s1;
        split2(v.z, v.w, s0, s1);
        tb[base + 4] = s0; tb[1024 + base + 4] = s1;
    }
}

__global__ __launch_bounds__(256) void pack_b2(
    const float* __restrict__ src, int ldb, long long zstride, uint4* __restrict__ dst, int nKb)
{
    const int kb = blockIdx.x, rb = blockIdx.y, z = blockIdx.z;
    src += (long long)z * zstride;
    uint32_t* tb = (uint32_t*)(dst + ((size_t)(z * gridDim.y + rb) * nKb + kb) * 768);
    const int tid = threadIdx.x;
    #pragma unroll
    for (int t = 0; t < 2; t++) {
        int idx = tid + t * 256;
        int row = idx >> 2, k4 = (idx & 3) * 4;
        float4 v = *reinterpret_cast<const float4*>(
            &src[(long long)(rb * 128 + row) * ldb + kb * 16 + k4]);
        int nb = row >> 3, g = row & 7;
        int tt = (k4 & 7) >> 1, reg = k4 >> 3;
        int base = (nb * 32 + g * 4 + tt) * 2 + reg;
        uint32_t s0, s1;
        split2(v.x, v.y, s0, s1);
        tb[base] = s0; tb[1024 + base] = s1;
        split2(v.z, v.w, s0, s1);
        tb[base + 2] = s0; tb[1024 + base + 2] = s1;
    }
}

// ---------------- packed 2-term bf16 GEMM, cp.async 3-stage, product-major mma ----------------
template<int MODE>
__global__ __launch_bounds__(256, 2) void gemm_pk(
    const uint4* __restrict__ At, const uint4* __restrict__ Bt,
    int nK, int nKtotA, int nKtotB, int nRbA, int nRbB, int kzBits,
    float* __restrict__ C, int ldc, long long cZ,
    const float* __restrict__ cls, uint4* __restrict__ epk,
    float* __restrict__ rsOut, uint8_t* __restrict__ maskOut)
{
    int bx, by;
    if (MODE == 3) {
        int r = blockIdx.x, row = 0;
        while (r >= 16 - row) { r -= 16 - row; row++; }
        by = row; bx = row + r;
    } else { bx = blockIdx.x; by = blockIdx.y; }

    const int hz = blockIdx.z >> kzBits;
    const int kz = blockIdx.z & ((1 << kzBits) - 1);
    const uint4* Ab = At + ((size_t)(hz * nRbA + by) * nKtotA + (size_t)kz * nK) * 768;
    const uint4* Bb = Bt + ((size_t)(hz * nRbB + bx) * nKtotB + (size_t)kz * nK) * 768;

    __shared__ uint4 smA[3][512], smB[3][512];

    const int tid = threadIdx.x, lane = tid & 31, wid = tid >> 5;
    const int wm = wid >> 1, wn = wid & 1;

    float acc[2][8][4];
    #pragma unroll
    for (int mt = 0; mt < 2; mt++)
        #pragma unroll
        for (int nt = 0; nt < 8; nt++)
            #pragma unroll
            for (int r = 0; r < 4; r++) acc[mt][nt][r] = 0.f;

    {
        cpa16(&smA[0][tid], Ab + tid);             cpa16(&smA[0][256 + tid], Ab + 256 + tid);
        cpa16(&smB[0][tid], Bb + tid);             cpa16(&smB[0][256 + tid], Bb + 256 + tid);
        CP_COMMIT();
        const uint4* A1 = Ab + 768;                const uint4* B1 = Bb + 768;
        cpa16(&smA[1][tid], A1 + tid);             cpa16(&smA[1][256 + tid], A1 + 256 + tid);
        cpa16(&smB[1][tid], B1 + tid);             cpa16(&smB[1][256 + tid], B1 + 256 + tid);
        CP_COMMIT();
    }

    int cur = 0;
    for (int kb = 0; kb < nK; kb++) {
        if (kb + 2 <= nK) CP_WAIT1(); else CP_WAIT0();
        __syncthreads();

        uint32_t af[2][2][4];
        #pragma unroll
        for (int i = 0; i < 2; i++)
            #pragma unroll
            for (int mt = 0; mt < 2; mt++)
                *reinterpret_cast<uint4*>(af[i][mt]) =
                    smA[cur][i * 256 + (wm * 2 + mt) * 32 + lane];

        const uint2* B2 = reinterpret_cast<const uint2*>(smB[cur]);

        // product-major: each acc is touched once per 16-mma round
        uint2 b0[8];
        #pragma unroll
        for (int nt = 0; nt < 8; nt++) b0[nt] = B2[(wn * 8 + nt) * 32 + lane];
        #pragma unroll
        for (int nt = 0; nt < 8; nt++)
            #pragma unroll
            for (int mt = 0; mt < 2; mt++)
                mma_bf16(acc[mt][nt], af[0][mt], b0[nt].x, b0[nt].y);   // hi*hi
        #pragma unroll
        for (int nt = 0; nt < 8; nt++)
            #pragma unroll
            for (int mt = 0; mt < 2; mt++)
                mma_bf16(acc[mt][nt], af[1][mt], b0[nt].x, b0[nt].y);   // lo*hi
        uint2 b1[8];
        #pragma unroll
        for (int nt = 0; nt < 8; nt++) b1[nt] = B2[512 + (wn * 8 + nt) * 32 + lane];
        #pragma unroll
        for (int nt = 0; nt < 8; nt++)
            #pragma unroll
            for (int mt = 0; mt < 2; mt++)
                mma_bf16(acc[mt][nt], af[0][mt], b1[nt].x, b1[nt].y);   // hi*lo

        if (kb + 2 < nK) {
            const int st = (kb + 2) % 3;
            const uint4* An = Ab + (size_t)(kb + 2) * 768;
            const uint4* Bn = Bb + (size_t)(kb + 2) * 768;
            cpa16(&smA[st][tid], An + tid);        cpa16(&smA[st][256 + tid], An + 256 + tid);
            cpa16(&smB[st][tid], Bn + tid);        cpa16(&smB[st][256 + tid], Bn + 256 + tid);
        }
        CP_COMMIT();
        cur = (cur + 1 == 3) ? 0 : cur + 1;
    }

    const int g = lane >> 2, tq = lane & 3;

    if (MODE == 2) {
        #pragma unroll
        for (int mt = 0; mt < 2; mt++) {
            const int m = wm * 2 + mt;
            const int i0 = by * 128 + m * 16 + g;
            const int i1 = i0 + 8;
            const float tha = cls[i0] - 0.1f;
            const float thb = cls[i1] - 0.1f;
            float rs0 = 0.f, rs1 = 0.f;
            #pragma unroll
            for (int nt = 0; nt < 8; nt++) {
                const int j = bx * 128 + wn * 64 + nt * 8 + tq * 2;
                const float cj0 = cls[j], cj1 = cls[j + 1];
                float e00 = (cj0 > tha) ? __expf(acc[mt][nt][0] * cj0) : 1.f;
                float e01 = (cj1 > tha) ? __expf(acc[mt][nt][1] * cj1) : 1.f;
                float e10 = (cj0 > thb) ? __expf(acc[mt][nt][2] * cj0) : 1.f;
                float e11 = (cj1 > thb) ? __expf(acc[mt][nt][3] * cj1) : 1.f;
                rs0 += e00 + e01;
                rs1 += e10 + e11;
                const size_t tIdx = (size_t)(hz * 16 + by) * 128
                                  + bx * 8 + ((wn * 8 + nt) >> 1);
                uint32_t* tb = (uint32_t*)(epk + tIdx * 768);
                const int w = (m * 32 + g * 4 + tq) * 4 + 2 * (nt & 1);
                uint32_t h0, l0, h1, l1;
                split2(e00, e01, h0, l0);
                split2(e10, e11, h1, l1);
                tb[w]            = h0;
                tb[1024 + w]     = l0;
                tb[w + 1]        = h1;
                tb[1024 + w + 1] = l1;
            }
            rs0 += __shfl_xor_sync(0xffffffffu, rs0, 1);
            rs0 += __shfl_xor_sync(0xffffffffu, rs0, 2);
            rs1 += __shfl_xor_sync(0xffffffffu, rs1, 1);
            rs1 += __shfl_xor_sync(0xffffffffu, rs1, 2);
            if (tq == 0) {
                atomicAdd(&rsOut[hz * Nn + i0], rs0);
                atomicAdd(&rsOut[hz * Nn + i1], rs1);
            }
        }
    } else if (MODE == 3) {
        __syncthreads();
        uint8_t* sb = reinterpret_cast<uint8_t*>(smA);
        #pragma unroll
        for (int mt = 0; mt < 2; mt++)
            #pragma unroll
            for (int nt = 0; nt < 8; nt++) {
                const int r0 = wm * 32 + mt * 16 + g;
                const int c0 = wn * 64 + nt * 8 + tq * 2;
                sb[r0 * 144 + c0]           = acc[mt][nt][0] > 6.f;
                sb[r0 * 144 + c0 + 1]       = acc[mt][nt][1] > 6.f;
                sb[(r0 + 8) * 144 + c0]     = acc[mt][nt][2] > 6.f;
                sb[(r0 + 8) * 144 + c0 + 1] = acc[mt][nt][3] > 6.f;
            }
        __syncthreads();
        const int r = tid >> 1, hf = tid & 1;
        {
            const uint8_t* srcp = sb + r * 144 + hf * 64;
            uint4 v0 = *reinterpret_cast<const uint4*>(srcp);
            uint4 v1 = *reinterpret_cast<const uint4*>(srcp + 16);
            uint4 v2 = *reinterpret_cast<const uint4*>(srcp + 32);
            uint4 v3 = *reinterpret_cast<const uint4*>(srcp + 48);
            uint8_t* dst = maskOut + (size_t)(by * 128 + r) * Nn + bx * 128 + hf * 64;
            *reinterpret_cast<uint4*>(dst)      = v0;
            *reinterpret_cast<uint4*>(dst + 16) = v1;
            *reinterpret_cast<uint4*>(dst + 32) = v2;
            *reinterpret_cast<uint4*>(dst + 48) = v3;
        }
        {
            uint32_t wv[16];
            #pragma unroll
            for (int q = 0; q < 16; q++) {
                uint32_t b0 = sb[(hf * 64 + q * 4 + 0) * 144 + r];
                uint32_t b1 = sb[(hf * 64 + q * 4 + 1) * 144 + r];
                uint32_t b2 = sb[(hf * 64 + q * 4 + 2) * 144 + r];
                uint32_t b3 = sb[(hf * 64 + q * 4 + 3) * 144 + r];
                wv[q] = b0 | (b1 << 8) | (b2 << 16) | (b3 << 24);
            }
            uint8_t* dst = maskOut + (size_t)(bx * 128 + r) * Nn + by * 128 + hf * 64;
            #pragma unroll
            for (int q = 0; q < 4; q++)
                *reinterpret_cast<uint4*>(dst + q * 16) =
                    make_uint4(wv[q*4], wv[q*4+1], wv[q*4+2], wv[q*4+3]);
        }
    } else {
        float* Cz = C + (long long)blockIdx.z * cZ;
        #pragma unroll
        for (int mt = 0; mt < 2; mt++) {
            const int row0 = by * 128 + wm * 32 + mt * 16 + g;
            #pragma unroll
            for (int nt = 0; nt < 8; nt++) {
                const int col = bx * 128 + wn * 64 + nt * 8 + tq * 2;
                *reinterpret_cast<float2*>(&Cz[(long long)row0 * ldc + col]) =
                    make_float2(acc[mt][nt][0], acc[mt][nt][1]);
                *reinterpret_cast<float2*>(&Cz[(long long)(row0 + 8) * ldc + col]) =
                    make_float2(acc[mt][nt][2], acc[mt][nt][3]);
            }
        }
    }
}

// ---------------- normalize ----------------
__global__ __launch_bounds__(256) void normalize_kernel()
{
    const int n = blockIdx.x;
    const int w = threadIdx.x >> 5;
    const int lane = threadIdx.x & 31;
    const float* base = g_qkv + (long long)n * (3 * Cc);

    float qv[4], kv[4], vv[4];
    #pragma unroll
    for (int r = 0; r < 4; r++) {
        int d = lane + 32 * r;
        qv[r] = base[0 * Cc + w * HD + d];
        kv[r] = base[1 * Cc + w * HD + d];
        vv[r] = base[2 * Cc + w * HD + d];
    }
    float sq = 0.f, sk = 0.f, sv = 0.f;
    #pragma unroll
    for (int r = 0; r < 4; r++) { sq += qv[r]*qv[r]; sk += kv[r]*kv[r]; sv += vv[r]*vv[r]; }
    #pragma unroll
    for (int o = 16; o > 0; o >>= 1) {
        sq += __shfl_xor_sync(0xffffffffu, sq, o);
        sk += __shfl_xor_sync(0xffffffffu, sk, o);
        sv += __shfl_xor_sync(0xffffffffu, sv, o);
    }
    const float iq = SCALE_F / sqrtf(sq);
    const float ik = 1.0f / sqrtf(sk);
    const float iv = 1.0f / sqrtf(sv);
    #pragma unroll
    for (int r = 0; r < 4; r++) {
        int d = lane + 32 * r;
        g_q[(long long)w * Nn * HD + (long long)n * HD + d] = qv[r] * iq;
        g_k[(long long)w * Nn * HD + (long long)n * HD + d] = kv[r] * ik;
        g_vn[(long long)n * Cc + w * HD + d] = vv[r] * iv;
        g_vT[(long long)w * HD * Nn + (long long)d * Nn + n] = vv[r];
    }
}

// ---------------- combine split-K x2 partials ----------------
__global__ __launch_bounds__(256) void combine_kernel(float* __restrict__ out)
{
    int idx = blockIdx.x * 256 + threadIdx.x;
    if (idx >= Nn * Cc / 4) return;
    const int n = idx >> 8, c4 = idx & 255;
    const int h = c4 >> 5, d4 = c4 & 31;
    const float4* p = reinterpret_cast<const float4*>(g_part);
    const size_t st = (size_t)Nn * 32;
    const size_t b = ((size_t)(h * 2) * Nn + n) * 32 + d4;
    float4 a0 = p[b], a1 = p[b + st];
    const float s = 1.f / g_rowsum[h * Nn + n];
    *reinterpret_cast<float4*>(out + (size_t)n * (2 * Cc) + h * 128 + d4 * 4) =
        make_float4((a0.x + a1.x) * s, (a0.y + a1.y) * s,
                    (a0.z + a1.z) * s, (a0.w + a1.w) * s);
}

// ---------------- simround2 pass1 ----------------
__global__ __launch_bounds__(256) void simr2_pass1()
{
    const int blk = blockIdx.x;
    const int tid = threadIdx.x;
    const int rl = tid >> 4, ct = tid & 15;
    const int i = blk * 16 + rl;
    const int rowBlk = i >> 7, il = i & 127;
    const int m = il >> 4, rg = il & 15, g = rg & 7, half = rg >> 3;
    const int ubase = m * 32 + g * 4;

    float irs[8];
    #pragma unroll
    for (int h = 0; h < 8; h++) irs[h] = 1.f / g_rowsum[h * Nn + i];

    float msum = 0.f;
    for (int kt = 0; kt < 8; kt++) {
        const int kb = ct + kt * 16;
        float acc[16];
        #pragma unroll
        for (int p = 0; p < 16; p++) acc[p] = 0.f;
        #pragma unroll
        for (int h = 0; h < 8; h++) {
            const uint4* blob = g_epk + ((size_t)((h * 16 + rowBlk) * 128 + kb)) * 768;
            const float w = irs[h];
            #pragma unroll
            for (int t = 0; t < 4; t++) {
                uint4 H = blob[ubase + t], L = blob[256 + ubase + t];
                uint32_t h0 = half ? H.y : H.x, l0 = half ? L.y : L.x;
                uint32_t h1 = half ? H.w : H.z, l1 = half ? L.w : L.z;
                acc[t*2+0]   += (blo(h0) + blo(l0)) * w;
                acc[t*2+1]   += (bhi(h0) + bhi(l0)) * w;
                acc[8+t*2+0] += (blo(h1) + blo(l1)) * w;
                acc[8+t*2+1] += (bhi(h1) + bhi(l1)) * w;
            }
        }
        const int j0 = kb * 16;
        uint4 mbv = *reinterpret_cast<const uint4*>(g_mask + (size_t)i * Nn + j0);
        const uint8_t* mb = reinterpret_cast<const uint8_t*>(&mbv);
        float* dst = g_es + (size_t)i * Nn + j0;
        #pragma unroll
        for (int kh = 0; kh < 2; kh++)
            #pragma unroll
            for (int t = 0; t < 4; t++) {
                float e0 = __expf(acc[kh*8 + t*2]     * 0.125f);
                float e1 = __expf(acc[kh*8 + t*2 + 1] * 0.125f);
                const int col = kh * 8 + t * 2;
                if (mb[col])     msum += e0;
                if (mb[col + 1]) msum += e1;
                *reinterpret_cast<float2*>(dst + col) = make_float2(e0, e1);
            }
    }
    #pragma unroll
    for (int o = 1; o < 16; o <<= 1) msum += __shfl_xor_sync(0xffffffffu, msum, o);
    if (ct == 0) g_srow[i] = msum;
}

// ---------------- simround2 pass2 ----------------
__global__ __launch_bounds__(256) void simr2_pass2(float* __restrict__ out)
{
    int idx = blockIdx.x * blockDim.x + threadIdx.x;
    if (idx >= Nn * Nn / 4) return;
    const int i = idx >> 9;
    const int j = (idx & 511) * 4;
    const float inv = 1.f / g_srow[i];
    uchar4 m = *reinterpret_cast<const uchar4*>(g_mask + (size_t)i * Nn + j);
    float4 e = *reinterpret_cast<const float4*>(g_es + (size_t)i * Nn + j);
    *reinterpret_cast<float4*>(out + (size_t)i * Nn + j) = make_float4(
        m.x ? e.x * inv : 0.f, m.y ? e.y * inv : 0.f,
        m.z ? e.z * inv : 0.f, m.w ? e.w * inv : 0.f);
}

// ---------------- copy raw v ----------------
__global__ __launch_bounds__(256) void copy_v_kernel(float* __restrict__ out)
{
    int idx = blockIdx.x * blockDim.x + threadIdx.x;
    if (idx >= Nn * Cc / 4) return;
    int n = idx / (Cc / 4);
    int c4 = idx % (Cc / 4);
    float4 v = *reinterpret_cast<const float4*>(&g_qkv[(size_t)n * (3 * Cc) + 2 * Cc + c4 * 4]);
    reinterpret_cast<float4*>(out)[(size_t)n * (2 * Cc / 4) + (Cc / 4) + c4] = v;
}

// ---------------- host launcher ----------------
extern "C" void kernel_launch(void* const* d_in, const int* in_sizes, int n_in,
                              void* d_out, int out_size)
{
    const float* x   = (const float*)d_in[0];
    const float* cls = (const float*)d_in[1];
    const float* W   = (const float*)d_in[3];
    float* out = (float*)d_out;

    float *p_qkv, *p_q, *p_k, *p_vn, *p_vT, *p_rs, *p_part;
    uint4 *p_xp, *p_Wp, *p_qp, *p_kp, *p_vnpA, *p_vnpB, *p_vTp, *p_epk;
    uint8_t* p_mask;
    cudaGetSymbolAddress((void**)&p_qkv, g_qkv);
    cudaGetSymbolAddress((void**)&p_q, g_q);
    cudaGetSymbolAddress((void**)&p_k, g_k);
    cudaGetSymbolAddress((void**)&p_vn, g_vn);
    cudaGetSymbolAddress((void**)&p_vT, g_vT);
    cudaGetSymbolAddress((void**)&p_rs, g_rowsum);
    cudaGetSymbolAddress((void**)&p_part, g_part);
    cudaGetSymbolAddress((void**)&p_xp, g_xp);
    cudaGetSymbolAddress((void**)&p_Wp, g_Wp);
    cudaGetSymbolAddress((void**)&p_qp, g_qp);
    cudaGetSymbolAddress((void**)&p_kp, g_kp);
    cudaGetSymbolAddress((void**)&p_vnpA, g_vnpA);
    cudaGetSymbolAddress((void**)&p_vnpB, g_vnpB);
    cudaGetSymbolAddress((void**)&p_vTp, g_vTp);
    cudaGetSymbolAddress((void**)&p_epk, g_epk);
    cudaGetSymbolAddress((void**)&p_mask, g_mask);

    // pack x, W
    pack_a2<<<dim3(64, 16, 1), 256>>>(x, Cc, 0, p_xp, 64);
    pack_b2<<<dim3(64, 24, 1), 256>>>(W, Cc, 0, p_Wp, 64);

    // 1. qkv = x @ W^T
    gemm_pk<0><<<dim3(24, 16, 1), 256>>>(p_xp, p_Wp, 64, 64, 64, 16, 24, 0,
                                         p_qkv, 3 * Cc, 0, nullptr, nullptr, nullptr, nullptr);

    // 2. normalize
    normalize_kernel<<<Nn, 256>>>();

    // 3. pack q, k, vn (A+B), vT
    pack_a2<<<dim3(8, 16, 8), 256>>>(p_q, HD, (long long)Nn * HD, p_qp, 8);
    pack_b2<<<dim3(8, 16, 8), 256>>>(p_k, HD, (long long)Nn * HD, p_kp, 8);
    pack_a2<<<dim3(64, 16, 1), 256>>>(p_vn, Cc, 0, p_vnpA, 64);
    pack_b2<<<dim3(64, 16, 1), 256>>>(p_vn, Cc, 0, p_vnpB, 64);
    pack_b2<<<dim3(128, 1, 8), 256>>>(p_vT, Nn, (long long)HD * Nn, p_vTp, 128);

    // 4. sim mask (symmetric upper-triangle tiles)
    gemm_pk<3><<<dim3(136, 1, 1), 256>>>(p_vnpA, p_vnpB, 64, 64, 64, 16, 16, 0,
                                         nullptr, 0, 0, nullptr, nullptr, nullptr, p_mask);

    // 5. logits + fused masked-exp -> packed e + rowsums
    cudaMemsetAsync(p_rs, 0, Hh * Nn * sizeof(float));
    gemm_pk<2><<<dim3(16, 16, 8), 256>>>(p_qp, p_kp, 8, 8, 8, 16, 16, 0,
                                         nullptr, 0, 0, cls, p_epk, p_rs, nullptr);

    // 6. attn@V split-K x2 -> partials
    gemm_pk<0><<<dim3(1, 16, 16), 256>>>(p_epk, p_vTp, 64, 128, 128, 16, 1, 1,
                                         p_part, HD, (long long)Nn * HD,
                                         nullptr, nullptr, nullptr, nullptr);

    // 7. combine partials / rowsum
    combine_kernel<<<(Nn * Cc / 4 + 255) / 256, 256>>>(out);

    // 8. x_ori
    copy_v_kernel<<<(Nn * Cc / 4 + 255) / 256, 256>>>(out);

    // 9. sim_round2
    simr2_pass1<<<128, 256>>>();
    simr2_pass2<<<(Nn * Nn / 4 + 255) / 256, 256>>>(out + (size_t)Nn * 2 * Cc);
}

// round 9
// speedup vs baseline: 1.1997x; 1.1997x over previous
#include <cuda_runtime.h>
#include <math.h>
#include <stdint.h>

#define Nn 2048
#define Cc 1024
#define Hh 8
#define HD 128
#define SCALE_F 25.0f

// ---------------- scratch ----------------
__device__ float g_qkv[Nn * 3 * Cc];
__device__ float g_q[Hh * Nn * HD];
__device__ float g_k[Hh * Nn * HD];
__device__ float g_vn[Nn * Cc];
__device__ float g_vT[Hh * HD * Nn];
__device__ float g_rowsum[Hh * Nn];
__device__ float g_part[(size_t)16 * Nn * HD];
__device__ float g_es[(size_t)Nn * Nn];
__device__ float g_srow[Nn];
__device__ uint8_t g_mask[(size_t)Nn * Nn];

// packed 2-term bf16 fragment images; tile = 128 rows x 16 k (stride 768 uint4)
__device__ uint4 g_xp [(size_t)16 * 64 * 768];
__device__ uint4 g_Wp [(size_t)24 * 64 * 768];
__device__ uint4 g_qp [(size_t)8 * 16 * 8 * 768];
__device__ uint4 g_kp [(size_t)8 * 16 * 8 * 768];
__device__ uint4 g_vnpA[(size_t)16 * 64 * 768];
__device__ uint4 g_vnpB[(size_t)16 * 64 * 768];
__device__ uint4 g_vTp[(size_t)8 * 128 * 768];
__device__ uint4 g_epk[(size_t)8 * 16 * 128 * 768];

// ---------------- helpers ----------------
__device__ __forceinline__ uint32_t packbf(float x, float y)
{
    uint32_t h;
    asm("cvt.rn.bf16x2.f32 %0, %1, %2;" : "=r"(h) : "f"(y), "f"(x));
    return h;
}
__device__ __forceinline__ float blo(uint32_t u) { return __uint_as_float(u << 16); }
__device__ __forceinline__ float bhi(uint32_t u) { return __uint_as_float(u & 0xFFFF0000u); }
__device__ __forceinline__ void split2(float x, float y, uint32_t& s0, uint32_t& s1)
{
    s0 = packbf(x, y);
    s1 = packbf(x - blo(s0), y - bhi(s0));
}

__device__ __forceinline__ void mma_bf16(float c[4], const uint32_t a[4],
                                         uint32_t b0, uint32_t b1)
{
    asm volatile(
        "mma.sync.aligned.m16n8k16.row.col.f32.bf16.bf16.f32 "
        "{%0,%1,%2,%3}, {%4,%5,%6,%7}, {%8,%9}, {%0,%1,%2,%3};"
        : "+f"(c[0]), "+f"(c[1]), "+f"(c[2]), "+f"(c[3])
        : "r"(a[0]), "r"(a[1]), "r"(a[2]), "r"(a[3]), "r"(b0), "r"(b1));
}

__device__ __forceinline__ void cpa16(void* smem, const void* gmem)
{
    uint32_t s = (uint32_t)__cvta_generic_to_shared(smem);
    asm volatile("cp.async.cg.shared.global [%0], [%1], 16;" :: "r"(s), "l"(gmem));
}
#define CP_COMMIT() asm volatile("cp.async.commit_group;")
#define CP_WAIT1()  asm volatile("cp.async.wait_group 1;")
#define CP_WAIT0()  asm volatile("cp.async.wait_group 0;")

// ---------------- pack kernels ----------------
__global__ __launch_bounds__(256) void pack_a2(
    const float* __restrict__ src, int lda, long long zstride, uint4* __restrict__ dst, int nKb)
{
    const int kb = blockIdx.x, rb = blockIdx.y, z = blockIdx.z;
    src += (long long)z * zstride;
    uint32_t* tb = (uint32_t*)(dst + ((size_t)(z * gridDim.y + rb) * nKb + kb) * 768);
    const int tid = threadIdx.x;
    #pragma unroll
    for (int t = 0; t < 2; t++) {
        int idx = tid + t * 256;
        int row = idx >> 2, k4 = (idx & 3) * 4;
        float4 v = *reinterpret_cast<const float4*>(
            &src[(long long)(rb * 128 + row) * lda + kb * 16 + k4]);
        int m = row >> 4, r16 = row & 15, g = r16 & 7, half = r16 >> 3;
        int tt = (k4 & 7) >> 1, reg = half + 2 * (k4 >> 3);
        int base = (m * 32 + g * 4 + tt) * 4 + reg;
        uint32_t s0, s1;
        split2(v.x, v.y, s0, s1);
        tb[base] = s0; tb[1024 + base] = s1;
        split2(v.z, v.w, s0, s1);
        tb[base + 4] = s0; tb[1024 + base + 4] = s1;
    }
}

__global__ __launch_bounds__(256) void pack_b2(
    const float* __restrict__ src, int ldb, long long zstride, uint4* __restrict__ dst, int nKb)
{
    const int kb = blockIdx.x, rb = blockIdx.y, z = blockIdx.z;
    src += (long long)z * zstride;
    uint32_t* tb = (uint32_t*)(dst + ((size_t)(z * gridDim.y + rb) * nKb + kb) * 768);
    const int tid = threadIdx.x;
    #pragma unroll
    for (int t = 0; t < 2; t++) {
        int idx = tid + t * 256;
        int row = idx >> 2, k4 = (idx & 3) * 4;
        float4 v = *reinterpret_cast<const float4*>(
            &src[(long long)(rb * 128 + row) * ldb + kb * 16 + k4]);
        int nb = row >> 3, g = row & 7;
        int tt = (k4 & 7) >> 1, reg = k4 >> 3;
        int base = (nb * 32 + g * 4 + tt) * 2 + reg;
        uint32_t s0, s1;
        split2(v.x, v.y, s0, s1);
        tb[base] = s0; tb[1024 + base] = s1;
        split2(v.z, v.w, s0, s1);
        tb[base + 2] = s0; tb[1024 + base + 2] = s1;
    }
}

// ---------------- packed bf16 GEMM, cp.async 3-stage ----------------
// MODE 0: plain fp32 store. MODE 2: logits->masked exp + packed e + rowsums.
// MODE 3: symmetric sim mask (1-product: hi*hi only — feeds a >6 threshold).
template<int MODE>
__global__ __launch_bounds__(256, 2) void gemm_pk(
    const uint4* __restrict__ At, const uint4* __restrict__ Bt,
    int nK, int nKtotA, int nKtotB, int nRbA, int nRbB, int kzBits,
    float* __restrict__ C, int ldc, long long cZ,
    const float* __restrict__ cls, uint4* __restrict__ epk,
    float* __restrict__ rsOut, uint8_t* __restrict__ maskOut)
{
    int bx, by;
    if (MODE == 3) {
        int r = blockIdx.x, row = 0;
        while (r >= 16 - row) { r -= 16 - row; row++; }
        by = row; bx = row + r;
    } else { bx = blockIdx.x; by = blockIdx.y; }

    const int hz = blockIdx.z >> kzBits;
    const int kz = blockIdx.z & ((1 << kzBits) - 1);
    const uint4* Ab = At + ((size_t)(hz * nRbA + by) * nKtotA + (size_t)kz * nK) * 768;
    const uint4* Bb = Bt + ((size_t)(hz * nRbB + bx) * nKtotB + (size_t)kz * nK) * 768;

    __shared__ uint4 smA[3][512], smB[3][512];

    const int tid = threadIdx.x, lane = tid & 31, wid = tid >> 5;
    const int wm = wid >> 1, wn = wid & 1;

    float acc[2][8][4];
    #pragma unroll
    for (int mt = 0; mt < 2; mt++)
        #pragma unroll
        for (int nt = 0; nt < 8; nt++)
            #pragma unroll
            for (int r = 0; r < 4; r++) acc[mt][nt][r] = 0.f;

    {
        cpa16(&smA[0][tid], Ab + tid);             cpa16(&smA[0][256 + tid], Ab + 256 + tid);
        cpa16(&smB[0][tid], Bb + tid);             cpa16(&smB[0][256 + tid], Bb + 256 + tid);
        CP_COMMIT();
        const uint4* A1 = Ab + 768;                const uint4* B1 = Bb + 768;
        cpa16(&smA[1][tid], A1 + tid);             cpa16(&smA[1][256 + tid], A1 + 256 + tid);
        cpa16(&smB[1][tid], B1 + tid);             cpa16(&smB[1][256 + tid], B1 + 256 + tid);
        CP_COMMIT();
    }

    int cur = 0;
    for (int kb = 0; kb < nK; kb++) {
        if (kb + 2 <= nK) CP_WAIT1(); else CP_WAIT0();
        __syncthreads();

        uint32_t af[2][2][4];
        #pragma unroll
        for (int mt = 0; mt < 2; mt++)
            *reinterpret_cast<uint4*>(af[0][mt]) =
                smA[cur][(wm * 2 + mt) * 32 + lane];
        if (MODE != 3) {
            #pragma unroll
            for (int mt = 0; mt < 2; mt++)
                *reinterpret_cast<uint4*>(af[1][mt]) =
                    smA[cur][256 + (wm * 2 + mt) * 32 + lane];
        }

        const uint2* B2 = reinterpret_cast<const uint2*>(smB[cur]);
        uint2 b0[8];
        #pragma unroll
        for (int nt = 0; nt < 8; nt++) b0[nt] = B2[(wn * 8 + nt) * 32 + lane];
        #pragma unroll
        for (int nt = 0; nt < 8; nt++)
            #pragma unroll
            for (int mt = 0; mt < 2; mt++)
                mma_bf16(acc[mt][nt], af[0][mt], b0[nt].x, b0[nt].y);   // hi*hi
        if (MODE != 3) {
            #pragma unroll
            for (int nt = 0; nt < 8; nt++)
                #pragma unroll
                for (int mt = 0; mt < 2; mt++)
                    mma_bf16(acc[mt][nt], af[1][mt], b0[nt].x, b0[nt].y);  // lo*hi
            uint2 b1[8];
            #pragma unroll
            for (int nt = 0; nt < 8; nt++) b1[nt] = B2[512 + (wn * 8 + nt) * 32 + lane];
            #pragma unroll
            for (int nt = 0; nt < 8; nt++)
                #pragma unroll
                for (int mt = 0; mt < 2; mt++)
                    mma_bf16(acc[mt][nt], af[0][mt], b1[nt].x, b1[nt].y);  // hi*lo
        }

        if (kb + 2 < nK) {
            const int st = (kb + 2) % 3;
            const uint4* An = Ab + (size_t)(kb + 2) * 768;
            const uint4* Bn = Bb + (size_t)(kb + 2) * 768;
            cpa16(&smA[st][tid], An + tid);        cpa16(&smA[st][256 + tid], An + 256 + tid);
            cpa16(&smB[st][tid], Bn + tid);        cpa16(&smB[st][256 + tid], Bn + 256 + tid);
        }
        CP_COMMIT();
        cur = (cur + 1 == 3) ? 0 : cur + 1;
    }

    const int g = lane >> 2, tq = lane & 3;

    if (MODE == 2) {
        #pragma unroll
        for (int mt = 0; mt < 2; mt++) {
            const int m = wm * 2 + mt;
            const int i0 = by * 128 + m * 16 + g;
            const int i1 = i0 + 8;
            const float tha = cls[i0] - 0.1f;
            const float thb = cls[i1] - 0.1f;
            float rs0 = 0.f, rs1 = 0.f;
            const int baseW = (m * 32 + g * 4 + tq) * 4;
            #pragma unroll
            for (int ntp = 0; ntp < 4; ntp++) {
                uint32_t hw[4], lw[4];
                #pragma unroll
                for (int sub = 0; sub < 2; sub++) {
                    const int nt = ntp * 2 + sub;
                    const int j = bx * 128 + wn * 64 + nt * 8 + tq * 2;
                    const float cj0 = cls[j], cj1 = cls[j + 1];
                    float e00 = (cj0 > tha) ? __expf(acc[mt][nt][0] * cj0) : 1.f;
                    float e01 = (cj1 > tha) ? __expf(acc[mt][nt][1] * cj1) : 1.f;
                    float e10 = (cj0 > thb) ? __expf(acc[mt][nt][2] * cj0) : 1.f;
                    float e11 = (cj1 > thb) ? __expf(acc[mt][nt][3] * cj1) : 1.f;
                    rs0 += e00 + e01;
                    rs1 += e10 + e11;
                    split2(e00, e01, hw[sub * 2], lw[sub * 2]);
                    split2(e10, e11, hw[sub * 2 + 1], lw[sub * 2 + 1]);
                }
                const size_t tIdx = (size_t)(hz * 16 + by) * 128 + bx * 8 + wn * 4 + ntp;
                uint32_t* tb = (uint32_t*)(epk + tIdx * 768);
                *reinterpret_cast<uint4*>(&tb[baseW]) =
                    make_uint4(hw[0], hw[1], hw[2], hw[3]);
                *reinterpret_cast<uint4*>(&tb[1024 + baseW]) =
                    make_uint4(lw[0], lw[1], lw[2], lw[3]);
            }
            rs0 += __shfl_xor_sync(0xffffffffu, rs0, 1);
            rs0 += __shfl_xor_sync(0xffffffffu, rs0, 2);
            rs1 += __shfl_xor_sync(0xffffffffu, rs1, 1);
            rs1 += __shfl_xor_sync(0xffffffffu, rs1, 2);
            if (tq == 0) {
                atomicAdd(&rsOut[hz * Nn + i0], rs0);
                atomicAdd(&rsOut[hz * Nn + i1], rs1);
            }
        }
    } else if (MODE == 3) {
        __syncthreads();
        uint8_t* sb = reinterpret_cast<uint8_t*>(smA);
        #pragma unroll
        for (int mt = 0; mt < 2; mt++)
            #pragma unroll
            for (int nt = 0; nt < 8; nt++) {
                const int r0 = wm * 32 + mt * 16 + g;
                const int c0 = wn * 64 + nt * 8 + tq * 2;
                sb[r0 * 144 + c0]           = acc[mt][nt][0] > 6.f;
                sb[r0 * 144 + c0 + 1]       = acc[mt][nt][1] > 6.f;
                sb[(r0 + 8) * 144 + c0]     = acc[mt][nt][2] > 6.f;
                sb[(r0 + 8) * 144 + c0 + 1] = acc[mt][nt][3] > 6.f;
            }
        __syncthreads();
        const int r = tid >> 1, hf = tid & 1;
        {
            const uint8_t* srcp = sb + r * 144 + hf * 64;
            uint4 v0 = *reinterpret_cast<const uint4*>(srcp);
            uint4 v1 = *reinterpret_cast<const uint4*>(srcp + 16);
            uint4 v2 = *reinterpret_cast<const uint4*>(srcp + 32);
            uint4 v3 = *reinterpret_cast<const uint4*>(srcp + 48);
            uint8_t* dst = maskOut + (size_t)(by * 128 + r) * Nn + bx * 128 + hf * 64;
            *reinterpret_cast<uint4*>(dst)      = v0;
            *reinterpret_cast<uint4*>(dst + 16) = v1;
            *reinterpret_cast<uint4*>(dst + 32) = v2;
            *reinterpret_cast<uint4*>(dst + 48) = v3;
        }
        {
            uint32_t wv[16];
            #pragma unroll
            for (int q = 0; q < 16; q++) {
                uint32_t b0 = sb[(hf * 64 + q * 4 + 0) * 144 + r];
                uint32_t b1 = sb[(hf * 64 + q * 4 + 1) * 144 + r];
                uint32_t b2 = sb[(hf * 64 + q * 4 + 2) * 144 + r];
                uint32_t b3 = sb[(hf * 64 + q * 4 + 3) * 144 + r];
                wv[q] = b0 | (b1 << 8) | (b2 << 16) | (b3 << 24);
            }
            uint8_t* dst = maskOut + (size_t)(bx * 128 + r) * Nn + by * 128 + hf * 64;
            #pragma unroll
            for (int q = 0; q < 4; q++)
                *reinterpret_cast<uint4*>(dst + q * 16) =
                    make_uint4(wv[q*4], wv[q*4+1], wv[q*4+2], wv[q*4+3]);
        }
    } else {
        float* Cz = C + (long long)blockIdx.z * cZ;
        #pragma unroll
        for (int mt = 0; mt < 2; mt++) {
            const int row0 = by * 128 + wm * 32 + mt * 16 + g;
            #pragma unroll
            for (int nt = 0; nt < 8; nt++) {
                const int col = bx * 128 + wn * 64 + nt * 8 + tq * 2;
                *reinterpret_cast<float2*>(&Cz[(long long)row0 * ldc + col]) =
                    make_float2(acc[mt][nt][0], acc[mt][nt][1]);
                *reinterpret_cast<float2*>(&Cz[(long long)(row0 + 8) * ldc + col]) =
                    make_float2(acc[mt][nt][2], acc[mt][nt][3]);
            }
        }
    }
}

// ---------------- normalize ----------------
__global__ __launch_bounds__(256) void normalize_kernel()
{
    const int n = blockIdx.x;
    const int w = threadIdx.x >> 5;
    const int lane = threadIdx.x & 31;
    const float* base = g_qkv + (long long)n * (3 * Cc);

    float qv[4], kv[4], vv[4];
    #pragma unroll
    for (int r = 0; r < 4; r++) {
        int d = lane + 32 * r;
        qv[r] = base[0 * Cc + w * HD + d];
        kv[r] = base[1 * Cc + w * HD + d];
        vv[r] = base[2 * Cc + w * HD + d];
    }
    float sq = 0.f, sk = 0.f, sv = 0.f;
    #pragma unroll
    for (int r = 0; r < 4; r++) { sq += qv[r]*qv[r]; sk += kv[r]*kv[r]; sv += vv[r]*vv[r]; }
    #pragma unroll
    for (int o = 16; o > 0; o >>= 1) {
        sq += __shfl_xor_sync(0xffffffffu, sq, o);
        sk += __shfl_xor_sync(0xffffffffu, sk, o);
        sv += __shfl_xor_sync(0xffffffffu, sv, o);
    }
    const float iq = SCALE_F / sqrtf(sq);
    const float ik = 1.0f / sqrtf(sk);
    const float iv = 1.0f / sqrtf(sv);
    #pragma unroll
    for (int r = 0; r < 4; r++) {
        int d = lane + 32 * r;
        g_q[(long long)w * Nn * HD + (long long)n * HD + d] = qv[r] * iq;
        g_k[(long long)w * Nn * HD + (long long)n * HD + d] = kv[r] * ik;
        g_vn[(long long)n * Cc + w * HD + d] = vv[r] * iv;
        g_vT[(long long)w * HD * Nn + (long long)d * Nn + n] = vv[r];
    }
}

// ---------------- combine split-K partials + copy x_ori (fused) ----------------
__global__ __launch_bounds__(256) void combine_kernel(float* __restrict__ out)
{
    int idx = blockIdx.x * 256 + threadIdx.x;
    if (idx >= Nn * Cc / 4) return;
    const int n = idx >> 8, c4 = idx & 255;
    const int h = c4 >> 5, d4 = c4 & 31;
    const float4* p = reinterpret_cast<const float4*>(g_part);
    const size_t st = (size_t)Nn * 32;
    const size_t b = ((size_t)(h * 2) * Nn + n) * 32 + d4;
    float4 a0 = p[b], a1 = p[b + st];
    const float s = 1.f / g_rowsum[h * Nn + n];
    *reinterpret_cast<float4*>(out + (size_t)n * (2 * Cc) + h * 128 + d4 * 4) =
        make_float4((a0.x + a1.x) * s, (a0.y + a1.y) * s,
                    (a0.z + a1.z) * s, (a0.w + a1.w) * s);
    // x_ori: raw v into second-half columns
    float4 v = *reinterpret_cast<const float4*>(
        &g_qkv[(size_t)n * (3 * Cc) + 2 * Cc + h * 128 + d4 * 4]);
    *reinterpret_cast<float4*>(out + (size_t)n * (2 * Cc) + Cc + h * 128 + d4 * 4) = v;
}

// ---------------- simround2 pass1: row-pair threads, full uint4 use ----------------
// grid 128 (16-row groups), 256 threads: warp w = row pair (i, i+8), lane = kb strip
__global__ __launch_bounds__(256) void simr2_pass1()
{
    const int blk = blockIdx.x;                 // 16-row group 0..127
    const int rowBlk = blk >> 3, m = blk & 7;   // 128-row block, group within it
    const int tid = threadIdx.x;
    const int gg = tid >> 5;                    // warp = g 0..7
    const int lane = tid & 31;
    const int i0 = blk * 16 + gg;               // row (half 0)
    const int i1 = i0 + 8;                      // row (half 1)
    const int ubase = m * 32 + gg * 4;

    float irs0[8], irs1[8];
    #pragma unroll
    for (int h = 0; h < 8; h++) {
        irs0[h] = 1.f / g_rowsum[h * Nn + i0];
        irs1[h] = 1.f / g_rowsum[h * Nn + i1];
    }

    float msum0 = 0.f, msum1 = 0.f;
    #pragma unroll 1
    for (int kt = 0; kt < 4; kt++) {
        const int kb = lane + kt * 32;
        float a0[16], a1[16];                   // cols 0..15 for rows i0, i1
        #pragma unroll
        for (int p = 0; p < 16; p++) { a0[p] = 0.f; a1[p] = 0.f; }
        #pragma unroll
        for (int h = 0; h < 8; h++) {
            const uint4* blob = g_epk + ((size_t)((h * 16 + rowBlk) * 128 + kb)) * 768;
            const float w0 = irs0[h], w1 = irs1[h];
            #pragma unroll
            for (int t = 0; t < 4; t++) {
                uint4 H = blob[ubase + t], L = blob[256 + ubase + t];
                // reg0 (H.x): row i0, cols 2t..2t+1 ; reg1 (H.y): row i1 same cols
                // reg2 (H.z): row i0, cols 8+2t..  ; reg3 (H.w): row i1 same
                a0[t*2+0]   += (blo(H.x) + blo(L.x)) * w0;
                a0[t*2+1]   += (bhi(H.x) + bhi(L.x)) * w0;
                a1[t*2+0]   += (blo(H.y) + blo(L.y)) * w1;
                a1[t*2+1]   += (bhi(H.y) + bhi(L.y)) * w1;
                a0[8+t*2+0] += (blo(H.z) + blo(L.z)) * w0;
                a0[8+t*2+1] += (bhi(H.z) + bhi(L.z)) * w0;
                a1[8+t*2+0] += (blo(H.w) + blo(L.w)) * w1;
                a1[8+t*2+1] += (bhi(H.w) + bhi(L.w)) * w1;
            }
        }
        const int j0 = kb * 16;
        uint4 mv0 = *reinterpret_cast<const uint4*>(g_mask + (size_t)i0 * Nn + j0);
        uint4 mv1 = *reinterpret_cast<const uint4*>(g_mask + (size_t)i1 * Nn + j0);
        const uint8_t* mb0 = reinterpret_cast<const uint8_t*>(&mv0);
        const uint8_t* mb1 = reinterpret_cast<const uint8_t*>(&mv1);
        float e0[16], e1[16];
        #pragma unroll
        for (int p = 0; p < 16; p++) {
            e0[p] = __expf(a0[p] * 0.125f);
            e1[p] = __expf(a1[p] * 0.125f);
            if (mb0[p]) msum0 += e0[p];
            if (mb1[p]) msum1 += e1[p];
        }
        float* d0 = g_es + (size_t)i0 * Nn + j0;
        float* d1 = g_es + (size_t)i1 * Nn + j0;
        #pragma unroll
        for (int q = 0; q < 4; q++) {
            *reinterpret_cast<float4*>(d0 + q * 4) =
                make_float4(e0[q*4], e0[q*4+1], e0[q*4+2], e0[q*4+3]);
            *reinterpret_cast<float4*>(d1 + q * 4) =
                make_float4(e1[q*4], e1[q*4+1], e1[q*4+2], e1[q*4+3]);
        }
    }
    #pragma unroll
    for (int o = 16; o > 0; o >>= 1) {
        msum0 += __shfl_xor_sync(0xffffffffu, msum0, o);
        msum1 += __shfl_xor_sync(0xffffffffu, msum1, o);
    }
    if (lane == 0) { g_srow[i0] = msum0; g_srow[i1] = msum1; }
}

// ---------------- simround2 pass2 ----------------
__global__ __launch_bounds__(256) void simr2_pass2(float* __restrict__ out)
{
    int idx = blockIdx.x * blockDim.x + threadIdx.x;
    if (idx >= Nn * Nn / 4) return;
    const int i = idx >> 9;
    const int j = (idx & 511) * 4;
    const float inv = 1.f / g_srow[i];
    uchar4 m = *reinterpret_cast<const uchar4*>(g_mask + (size_t)i * Nn + j);
    float4 e = *reinterpret_cast<const float4*>(g_es + (size_t)i * Nn + j);
    *reinterpret_cast<float4*>(out + (size_t)i * Nn + j) = make_float4(
        m.x ? e.x * inv : 0.f, m.y ? e.y * inv : 0.f,
        m.z ? e.z * inv : 0.f, m.w ? e.w * inv : 0.f);
}

// ---------------- host launcher ----------------
extern "C" void kernel_launch(void* const* d_in, const int* in_sizes, int n_in,
                              void* d_out, int out_size)
{
    const float* x   = (const float*)d_in[0];
    const float* cls = (const float*)d_in[1];
    const float* W   = (const float*)d_in[3];
    float* out = (float*)d_out;

    float *p_qkv, *p_q, *p_k, *p_vn, *p_vT, *p_rs, *p_part;
    uint4 *p_xp, *p_Wp, *p_qp, *p_kp, *p_vnpA, *p_vnpB, *p_vTp, *p_epk;
    uint8_t* p_mask;
    cudaGetSymbolAddress((void**)&p_qkv, g_qkv);
    cudaGetSymbolAddress((void**)&p_q, g_q);
    cudaGetSymbolAddress((void**)&p_k, g_k);
    cudaGetSymbolAddress((void**)&p_vn, g_vn);
    cudaGetSymbolAddress((void**)&p_vT, g_vT);
    cudaGetSymbolAddress((void**)&p_rs, g_rowsum);
    cudaGetSymbolAddress((void**)&p_part, g_part);
    cudaGetSymbolAddress((void**)&p_xp, g_xp);
    cudaGetSymbolAddress((void**)&p_Wp, g_Wp);
    cudaGetSymbolAddress((void**)&p_qp, g_qp);
    cudaGetSymbolAddress((void**)&p_kp, g_kp);
    cudaGetSymbolAddress((void**)&p_vnpA, g_vnpA);
    cudaGetSymbolAddress((void**)&p_vnpB, g_vnpB);
    cudaGetSymbolAddress((void**)&p_vTp, g_vTp);
    cudaGetSymbolAddress((void**)&p_epk, g_epk);
    cudaGetSymbolAddress((void**)&p_mask, g_mask);

    // pack x, W
    pack_a2<<<dim3(64, 16, 1), 256>>>(x, Cc, 0, p_xp, 64);
    pack_b2<<<dim3(64, 24, 1), 256>>>(W, Cc, 0, p_Wp, 64);

    // 1. qkv = x @ W^T
    gemm_pk<0><<<dim3(24, 16, 1), 256>>>(p_xp, p_Wp, 64, 64, 64, 16, 24, 0,
                                         p_qkv, 3 * Cc, 0, nullptr, nullptr, nullptr, nullptr);

    // 2. normalize
    normalize_kernel<<<Nn, 256>>>();

    // 3. pack q, k, vn (A+B), vT
    pack_a2<<<dim3(8, 16, 8), 256>>>(p_q, HD, (long long)Nn * HD, p_qp, 8);
    pack_b2<<<dim3(8, 16, 8), 256>>>(p_k, HD, (long long)Nn * HD, p_kp, 8);
    pack_a2<<<dim3(64, 16, 1), 256>>>(p_vn, Cc, 0, p_vnpA, 64);
    pack_b2<<<dim3(64, 16, 1), 256>>>(p_vn, Cc, 0, p_vnpB, 64);
    pack_b2<<<dim3(128, 1, 8), 256>>>(p_vT, Nn, (long long)HD * Nn, p_vTp, 128);

    // 4. sim mask (symmetric upper-triangle, 1-product)
    gemm_pk<3><<<dim3(136, 1, 1), 256>>>(p_vnpA, p_vnpB, 64, 64, 64, 16, 16, 0,
                                         nullptr, 0, 0, nullptr, nullptr, nullptr, p_mask);

    // 5. logits + fused masked-exp -> packed e + rowsums (coalesced epk writes)
    cudaMemsetAsync(p_rs, 0, Hh * Nn * sizeof(float));
    gemm_pk<2><<<dim3(16, 16, 8), 256>>>(p_qp, p_kp, 8, 8, 8, 16, 16, 0,
                                         nullptr, 0, 0, cls, p_epk, p_rs, nullptr);

    // 6. attn@V split-K x2 -> partials
    gemm_pk<0><<<dim3(1, 16, 16), 256>>>(p_epk, p_vTp, 64, 128, 128, 16, 1, 1,
                                         p_part, HD, (long long)Nn * HD,
                                         nullptr, nullptr, nullptr, nullptr);

    // 7. combine partials / rowsum + x_ori copy (fused)
    combine_kernel<<<(Nn * Cc / 4 + 255) / 256, 256>>>(out);

    // 8. sim_round2
    simr2_pass1<<<128, 256>>>();
    simr2_pass2<<<(Nn * Nn / 4 + 255) / 256, 256>>>(out + (size_t)Nn * 2 * Cc);
}

// round 10
// speedup vs baseline: 1.3276x; 1.1066x over previous
#include <cuda_runtime.h>
#include <math.h>
#include <stdint.h>

#define Nn 2048
#define Cc 1024
#define Hh 8
#define HD 128
#define SCALE_F 25.0f

// ---------------- scratch ----------------
__device__ float g_qkv[Nn * 3 * Cc];
__device__ float g_q[Hh * Nn * HD];
__device__ float g_k[Hh * Nn * HD];
__device__ float g_vn[Nn * Cc];
__device__ float g_vT[Hh * HD * Nn];
__device__ float g_rowsum[Hh * Nn];
__device__ float g_part[(size_t)16 * Nn * HD];
__device__ float g_es[(size_t)Nn * Nn];
__device__ float g_srow[Nn];
__device__ uint8_t g_mask[(size_t)Nn * Nn];

// packed 2-term bf16 fragment images; tile = 128 rows x 16 k (stride 768 uint4)
__device__ uint4 g_xp [(size_t)16 * 64 * 768];
__device__ uint4 g_Wp [(size_t)24 * 64 * 768];
__device__ uint4 g_qp [(size_t)8 * 16 * 8 * 768];
__device__ uint4 g_kp [(size_t)8 * 16 * 8 * 768];
__device__ uint4 g_vnpA[(size_t)16 * 64 * 768];
__device__ uint4 g_vnpB[(size_t)16 * 64 * 768];
__device__ uint4 g_vTp[(size_t)8 * 128 * 768];
__device__ uint4 g_epk[(size_t)8 * 16 * 128 * 768];

// ---------------- helpers ----------------
__device__ __forceinline__ uint32_t packbf(float x, float y)
{
    uint32_t h;
    asm("cvt.rn.bf16x2.f32 %0, %1, %2;" : "=r"(h) : "f"(y), "f"(x));
    return h;
}
__device__ __forceinline__ float blo(uint32_t u) { return __uint_as_float(u << 16); }
__device__ __forceinline__ float bhi(uint32_t u) { return __uint_as_float(u & 0xFFFF0000u); }
__device__ __forceinline__ void split2(float x, float y, uint32_t& s0, uint32_t& s1)
{
    s0 = packbf(x, y);
    s1 = packbf(x - blo(s0), y - bhi(s0));
}

__device__ __forceinline__ void mma_bf16(float c[4], const uint32_t a[4],
                                         uint32_t b0, uint32_t b1)
{
    asm volatile(
        "mma.sync.aligned.m16n8k16.row.col.f32.bf16.bf16.f32 "
        "{%0,%1,%2,%3}, {%4,%5,%6,%7}, {%8,%9}, {%0,%1,%2,%3};"
        : "+f"(c[0]), "+f"(c[1]), "+f"(c[2]), "+f"(c[3])
        : "r"(a[0]), "r"(a[1]), "r"(a[2]), "r"(a[3]), "r"(b0), "r"(b1));
}

__device__ __forceinline__ void cpa16(void* smem, const void* gmem)
{
    uint32_t s = (uint32_t)__cvta_generic_to_shared(smem);
    asm volatile("cp.async.cg.shared.global [%0], [%1], 16;" :: "r"(s), "l"(gmem));
}
#define CP_COMMIT() asm volatile("cp.async.commit_group;")
#define CP_WAIT1()  asm volatile("cp.async.wait_group 1;")
#define CP_WAIT0()  asm volatile("cp.async.wait_group 0;")

// ---------------- pack kernels ----------------
__global__ __launch_bounds__(256) void pack_a2(
    const float* __restrict__ src, int lda, long long zstride, uint4* __restrict__ dst, int nKb)
{
    const int kb = blockIdx.x, rb = blockIdx.y, z = blockIdx.z;
    src += (long long)z * zstride;
    uint32_t* tb = (uint32_t*)(dst + ((size_t)(z * gridDim.y + rb) * nKb + kb) * 768);
    const int tid = threadIdx.x;
    #pragma unroll
    for (int t = 0; t < 2; t++) {
        int idx = tid + t * 256;
        int row = idx >> 2, k4 = (idx & 3) * 4;
        float4 v = *reinterpret_cast<const float4*>(
            &src[(long long)(rb * 128 + row) * lda + kb * 16 + k4]);
        int m = row >> 4, r16 = row & 15, g = r16 & 7, half = r16 >> 3;
        int tt = (k4 & 7) >> 1, reg = half + 2 * (k4 >> 3);
        int base = (m * 32 + g * 4 + tt) * 4 + reg;
        uint32_t s0, s1;
        split2(v.x, v.y, s0, s1);
        tb[base] = s0; tb[1024 + base] = s1;
        split2(v.z, v.w, s0, s1);
        tb[base + 4] = s0; tb[1024 + base + 4] = s1;
    }
}

__global__ __launch_bounds__(256) void pack_b2(
    const float* __restrict__ src, int ldb, long long zstride, uint4* __restrict__ dst, int nKb)
{
    const int kb = blockIdx.x, rb = blockIdx.y, z = blockIdx.z;
    src += (long long)z * zstride;
    uint32_t* tb = (uint32_t*)(dst + ((size_t)(z * gridDim.y + rb) * nKb + kb) * 768);
    const int tid = threadIdx.x;
    #pragma unroll
    for (int t = 0; t < 2; t++) {
        int idx = tid + t * 256;
        int row = idx >> 2, k4 = (idx & 3) * 4;
        float4 v = *reinterpret_cast<const float4*>(
            &src[(long long)(rb * 128 + row) * ldb + kb * 16 + k4]);
        int nb = row >> 3, g = row & 7;
        int tt = (k4 & 7) >> 1, reg = k4 >> 3;
        int base = (nb * 32 + g * 4 + tt) * 2 + reg;
        uint32_t s0, s1;
        split2(v.x, v.y, s0, s1);
        tb[base] = s0; tb[1024 + base] = s1;
        split2(v.z, v.w, s0, s1);
        tb[base + 2] = s0; tb[1024 + base + 2] = s1;
    }
}

// ---------------- packed bf16 GEMM, cp.async 3-stage ----------------
// MODE 0: plain fp32 store. MODE 2: logits->masked exp + packed e + rowsums.
// MODE 3: symmetric sim mask. PROD = number of bf16 term-products (1..3).
template<int MODE, int PROD>
__global__ __launch_bounds__(256, 2) void gemm_pk(
    const uint4* __restrict__ At, const uint4* __restrict__ Bt,
    int nK, int nKtotA, int nKtotB, int nRbA, int nRbB, int kzBits,
    float* __restrict__ C, int ldc, long long cZ,
    const float* __restrict__ cls, uint4* __restrict__ epk,
    float* __restrict__ rsOut, uint8_t* __restrict__ maskOut)
{
    int bx, by;
    if (MODE == 3) {
        int r = blockIdx.x, row = 0;
        while (r >= 16 - row) { r -= 16 - row; row++; }
        by = row; bx = row + r;
    } else { bx = blockIdx.x; by = blockIdx.y; }

    const int hz = blockIdx.z >> kzBits;
    const int kz = blockIdx.z & ((1 << kzBits) - 1);
    const uint4* Ab = At + ((size_t)(hz * nRbA + by) * nKtotA + (size_t)kz * nK) * 768;
    const uint4* Bb = Bt + ((size_t)(hz * nRbB + bx) * nKtotB + (size_t)kz * nK) * 768;

    __shared__ uint4 smA[3][512], smB[3][512];

    const int tid = threadIdx.x, lane = tid & 31, wid = tid >> 5;
    const int wm = wid >> 1, wn = wid & 1;

    float acc[2][8][4];
    #pragma unroll
    for (int mt = 0; mt < 2; mt++)
        #pragma unroll
        for (int nt = 0; nt < 8; nt++)
            #pragma unroll
            for (int r = 0; r < 4; r++) acc[mt][nt][r] = 0.f;

    {
        cpa16(&smA[0][tid], Ab + tid);             cpa16(&smA[0][256 + tid], Ab + 256 + tid);
        cpa16(&smB[0][tid], Bb + tid);             cpa16(&smB[0][256 + tid], Bb + 256 + tid);
        CP_COMMIT();
        const uint4* A1 = Ab + 768;                const uint4* B1 = Bb + 768;
        cpa16(&smA[1][tid], A1 + tid);             cpa16(&smA[1][256 + tid], A1 + 256 + tid);
        cpa16(&smB[1][tid], B1 + tid);             cpa16(&smB[1][256 + tid], B1 + 256 + tid);
        CP_COMMIT();
    }

    int cur = 0;
    for (int kb = 0; kb < nK; kb++) {
        if (kb + 2 <= nK) CP_WAIT1(); else CP_WAIT0();
        __syncthreads();

        uint32_t af[2][2][4];
        #pragma unroll
        for (int mt = 0; mt < 2; mt++)
            *reinterpret_cast<uint4*>(af[0][mt]) =
                smA[cur][(wm * 2 + mt) * 32 + lane];
        if (PROD >= 2) {
            #pragma unroll
            for (int mt = 0; mt < 2; mt++)
                *reinterpret_cast<uint4*>(af[1][mt]) =
                    smA[cur][256 + (wm * 2 + mt) * 32 + lane];
        }

        const uint2* B2 = reinterpret_cast<const uint2*>(smB[cur]);
        uint2 b0[8];
        #pragma unroll
        for (int nt = 0; nt < 8; nt++) b0[nt] = B2[(wn * 8 + nt) * 32 + lane];
        #pragma unroll
        for (int nt = 0; nt < 8; nt++)
            #pragma unroll
            for (int mt = 0; mt < 2; mt++)
                mma_bf16(acc[mt][nt], af[0][mt], b0[nt].x, b0[nt].y);   // hi*hi
        if (PROD >= 2) {
            #pragma unroll
            for (int nt = 0; nt < 8; nt++)
                #pragma unroll
                for (int mt = 0; mt < 2; mt++)
                    mma_bf16(acc[mt][nt], af[1][mt], b0[nt].x, b0[nt].y);  // lo*hi
        }
        if (PROD >= 3) {
            uint2 b1[8];
            #pragma unroll
            for (int nt = 0; nt < 8; nt++) b1[nt] = B2[512 + (wn * 8 + nt) * 32 + lane];
            #pragma unroll
            for (int nt = 0; nt < 8; nt++)
                #pragma unroll
                for (int mt = 0; mt < 2; mt++)
                    mma_bf16(acc[mt][nt], af[0][mt], b1[nt].x, b1[nt].y);  // hi*lo
        }

        if (kb + 2 < nK) {
            const int st = (kb + 2) % 3;
            const uint4* An = Ab + (size_t)(kb + 2) * 768;
            const uint4* Bn = Bb + (size_t)(kb + 2) * 768;
            cpa16(&smA[st][tid], An + tid);        cpa16(&smA[st][256 + tid], An + 256 + tid);
            cpa16(&smB[st][tid], Bn + tid);        cpa16(&smB[st][256 + tid], Bn + 256 + tid);
        }
        CP_COMMIT();
        cur = (cur + 1 == 3) ? 0 : cur + 1;
    }

    const int g = lane >> 2, tq = lane & 3;

    if (MODE == 2) {
        #pragma unroll
        for (int mt = 0; mt < 2; mt++) {
            const int m = wm * 2 + mt;
            const int i0 = by * 128 + m * 16 + g;
            const int i1 = i0 + 8;
            const float tha = cls[i0] - 0.1f;
            const float thb = cls[i1] - 0.1f;
            float rs0 = 0.f, rs1 = 0.f;
            const int baseW = (m * 32 + g * 4 + tq) * 4;
            #pragma unroll
            for (int ntp = 0; ntp < 4; ntp++) {
                uint32_t hw[4], lw[4];
                #pragma unroll
                for (int sub = 0; sub < 2; sub++) {
                    const int nt = ntp * 2 + sub;
                    const int j = bx * 128 + wn * 64 + nt * 8 + tq * 2;
                    const float cj0 = cls[j], cj1 = cls[j + 1];
                    float e00 = (cj0 > tha) ? __expf(acc[mt][nt][0] * cj0) : 1.f;
                    float e01 = (cj1 > tha) ? __expf(acc[mt][nt][1] * cj1) : 1.f;
                    float e10 = (cj0 > thb) ? __expf(acc[mt][nt][2] * cj0) : 1.f;
                    float e11 = (cj1 > thb) ? __expf(acc[mt][nt][3] * cj1) : 1.f;
                    rs0 += e00 + e01;
                    rs1 += e10 + e11;
                    split2(e00, e01, hw[sub * 2], lw[sub * 2]);
                    split2(e10, e11, hw[sub * 2 + 1], lw[sub * 2 + 1]);
                }
                const size_t tIdx = (size_t)(hz * 16 + by) * 128 + bx * 8 + wn * 4 + ntp;
                uint32_t* tb = (uint32_t*)(epk + tIdx * 768);
                *reinterpret_cast<uint4*>(&tb[baseW]) =
                    make_uint4(hw[0], hw[1], hw[2], hw[3]);
                *reinterpret_cast<uint4*>(&tb[1024 + baseW]) =
                    make_uint4(lw[0], lw[1], lw[2], lw[3]);
            }
            rs0 += __shfl_xor_sync(0xffffffffu, rs0, 1);
            rs0 += __shfl_xor_sync(0xffffffffu, rs0, 2);
            rs1 += __shfl_xor_sync(0xffffffffu, rs1, 1);
            rs1 += __shfl_xor_sync(0xffffffffu, rs1, 2);
            if (tq == 0) {
                atomicAdd(&rsOut[hz * Nn + i0], rs0);
                atomicAdd(&rsOut[hz * Nn + i1], rs1);
            }
        }
    } else if (MODE == 3) {
        __syncthreads();
        uint8_t* sb = reinterpret_cast<uint8_t*>(smA);
        #pragma unroll
        for (int mt = 0; mt < 2; mt++)
            #pragma unroll
            for (int nt = 0; nt < 8; nt++) {
                const int r0 = wm * 32 + mt * 16 + g;
                const int c0 = wn * 64 + nt * 8 + tq * 2;
                sb[r0 * 144 + c0]           = acc[mt][nt][0] > 6.f;
                sb[r0 * 144 + c0 + 1]       = acc[mt][nt][1] > 6.f;
                sb[(r0 + 8) * 144 + c0]     = acc[mt][nt][2] > 6.f;
                sb[(r0 + 8) * 144 + c0 + 1] = acc[mt][nt][3] > 6.f;
            }
        __syncthreads();
        const int r = tid >> 1, hf = tid & 1;
        {
            const uint8_t* srcp = sb + r * 144 + hf * 64;
            uint4 v0 = *reinterpret_cast<const uint4*>(srcp);
            uint4 v1 = *reinterpret_cast<const uint4*>(srcp + 16);
            uint4 v2 = *reinterpret_cast<const uint4*>(srcp + 32);
            uint4 v3 = *reinterpret_cast<const uint4*>(srcp + 48);
            uint8_t* dst = maskOut + (size_t)(by * 128 + r) * Nn + bx * 128 + hf * 64;
            *reinterpret_cast<uint4*>(dst)      = v0;
            *reinterpret_cast<uint4*>(dst + 16) = v1;
            *reinterpret_cast<uint4*>(dst + 32) = v2;
            *reinterpret_cast<uint4*>(dst + 48) = v3;
        }
        {
            uint32_t wv[16];
            #pragma unroll
            for (int q = 0; q < 16; q++) {
                uint32_t b0 = sb[(hf * 64 + q * 4 + 0) * 144 + r];
                uint32_t b1 = sb[(hf * 64 + q * 4 + 1) * 144 + r];
                uint32_t b2 = sb[(hf * 64 + q * 4 + 2) * 144 + r];
                uint32_t b3 = sb[(hf * 64 + q * 4 + 3) * 144 + r];
                wv[q] = b0 | (b1 << 8) | (b2 << 16) | (b3 << 24);
            }
            uint8_t* dst = maskOut + (size_t)(bx * 128 + r) * Nn + by * 128 + hf * 64;
            #pragma unroll
            for (int q = 0; q < 4; q++)
                *reinterpret_cast<uint4*>(dst + q * 16) =
                    make_uint4(wv[q*4], wv[q*4+1], wv[q*4+2], wv[q*4+3]);
        }
    } else {
        float* Cz = C + (long long)blockIdx.z * cZ;
        #pragma unroll
        for (int mt = 0; mt < 2; mt++) {
            const int row0 = by * 128 + wm * 32 + mt * 16 + g;
            #pragma unroll
            for (int nt = 0; nt < 8; nt++) {
                const int col = bx * 128 + wn * 64 + nt * 8 + tq * 2;
                *reinterpret_cast<float2*>(&Cz[(long long)row0 * ldc + col]) =
                    make_float2(acc[mt][nt][0], acc[mt][nt][1]);
                *reinterpret_cast<float2*>(&Cz[(long long)(row0 + 8) * ldc + col]) =
                    make_float2(acc[mt][nt][2], acc[mt][nt][3]);
            }
        }
    }
}

// ---------------- normalize: block = (32 tokens, 1 head), smem transpose for vT ----------------
__global__ __launch_bounds__(256) void normalize_kernel()
{
    const int nb = blockIdx.x;       // token block 0..63 (32 tokens)
    const int h  = blockIdx.y;       // head
    const int tid = threadIdx.x;
    const int nl = tid >> 3;         // local token 0..31
    const int dg = tid & 7;          // d-group 0..7
    const int n = nb * 32 + nl;

    __shared__ float sv[32 * 132];   // raw v tile [n_local][d], pad 132

    const float* base = g_qkv + (size_t)n * (3 * Cc) + h * HD;

    float4 qv[4], kv[4], vv[4];
    #pragma unroll
    for (int r = 0; r < 4; r++) {
        const int d = (dg + 8 * r) * 4;
        qv[r] = *reinterpret_cast<const float4*>(base + d);
        kv[r] = *reinterpret_cast<const float4*>(base + Cc + d);
        vv[r] = *reinterpret_cast<const float4*>(base + 2 * Cc + d);
    }
    float sq = 0.f, sk = 0.f, sv2 = 0.f;
    #pragma unroll
    for (int r = 0; r < 4; r++) {
        sq  += qv[r].x*qv[r].x + qv[r].y*qv[r].y + qv[r].z*qv[r].z + qv[r].w*qv[r].w;
        sk  += kv[r].x*kv[r].x + kv[r].y*kv[r].y + kv[r].z*kv[r].z + kv[r].w*kv[r].w;
        sv2 += vv[r].x*vv[r].x + vv[r].y*vv[r].y + vv[r].z*vv[r].z + vv[r].w*vv[r].w;
    }
    #pragma unroll
    for (int o = 1; o < 8; o <<= 1) {
        sq  += __shfl_xor_sync(0xffffffffu, sq, o);
        sk  += __shfl_xor_sync(0xffffffffu, sk, o);
        sv2 += __shfl_xor_sync(0xffffffffu, sv2, o);
    }
    const float iq = SCALE_F / sqrtf(sq);
    const float ik = 1.0f / sqrtf(sk);
    const float iv = 1.0f / sqrtf(sv2);

    float* gq = g_q + (size_t)h * Nn * HD + (size_t)n * HD;
    float* gk = g_k + (size_t)h * Nn * HD + (size_t)n * HD;
    float* gv = g_vn + (size_t)n * Cc + h * HD;
    #pragma unroll
    for (int r = 0; r < 4; r++) {
        const int d = (dg + 8 * r) * 4;
        *reinterpret_cast<float4*>(gq + d) =
            make_float4(qv[r].x*iq, qv[r].y*iq, qv[r].z*iq, qv[r].w*iq);
        *reinterpret_cast<float4*>(gk + d) =
            make_float4(kv[r].x*ik, kv[r].y*ik, kv[r].z*ik, kv[r].w*ik);
        *reinterpret_cast<float4*>(gv + d) =
            make_float4(vv[r].x*iv, vv[r].y*iv, vv[r].z*iv, vv[r].w*iv);
        float* s = sv + nl * 132 + d;
        s[0] = vv[r].x; s[1] = vv[r].y; s[2] = vv[r].z; s[3] = vv[r].w;
    }
    __syncthreads();

    // vT write: warp w covers d rows [w*16, w*16+16); per iter 4 rows x 8 lane-quads
    const int w = tid >> 5, lane = tid & 31;
    #pragma unroll
    for (int it = 0; it < 4; it++) {
        const int d = w * 16 + it * 4 + (lane >> 3);
        const int n4 = (lane & 7) * 4;
        float4 o;
        o.x = sv[(n4 + 0) * 132 + d];
        o.y = sv[(n4 + 1) * 132 + d];
        o.z = sv[(n4 + 2) * 132 + d];
        o.w = sv[(n4 + 3) * 132 + d];
        *reinterpret_cast<float4*>(
            g_vT + (size_t)(h * HD + d) * Nn + nb * 32 + n4) = o;
    }
}

// ---------------- combine split-K partials + copy x_ori (fused) ----------------
__global__ __launch_bounds__(256) void combine_kernel(float* __restrict__ out)
{
    int idx = blockIdx.x * 256 + threadIdx.x;
    if (idx >= Nn * Cc / 4) return;
    const int n = idx >> 8, c4 = idx & 255;
    const int h = c4 >> 5, d4 = c4 & 31;
    const float4* p = reinterpret_cast<const float4*>(g_part);
    const size_t st = (size_t)Nn * 32;
    const size_t b = ((size_t)(h * 2) * Nn + n) * 32 + d4;
    float4 a0 = p[b], a1 = p[b + st];
    const float s = 1.f / g_rowsum[h * Nn + n];
    *reinterpret_cast<float4*>(out + (size_t)n * (2 * Cc) + h * 128 + d4 * 4) =
        make_float4((a0.x + a1.x) * s, (a0.y + a1.y) * s,
                    (a0.z + a1.z) * s, (a0.w + a1.w) * s);
    float4 v = *reinterpret_cast<const float4*>(
        &g_qkv[(size_t)n * (3 * Cc) + 2 * Cc + h * 128 + d4 * 4]);
    *reinterpret_cast<float4*>(out + (size_t)n * (2 * Cc) + Cc + h * 128 + d4 * 4) = v;
}

// ---------------- simround2 pass1: hi-plane only ----------------
__global__ __launch_bounds__(256) void simr2_pass1()
{
    const int blk = blockIdx.x;
    const int rowBlk = blk >> 3, m = blk & 7;
    const int tid = threadIdx.x;
    const int gg = tid >> 5;
    const int lane = tid & 31;
    const int i0 = blk * 16 + gg;
    const int i1 = i0 + 8;
    const int ubase = m * 32 + gg * 4;

    float irs0[8], irs1[8];
    #pragma unroll
    for (int h = 0; h < 8; h++) {
        irs0[h] = 1.f / g_rowsum[h * Nn + i0];
        irs1[h] = 1.f / g_rowsum[h * Nn + i1];
    }

    float msum0 = 0.f, msum1 = 0.f;
    #pragma unroll 1
    for (int kt = 0; kt < 4; kt++) {
        const int kb = lane + kt * 32;
        float a0[16], a1[16];
        #pragma unroll
        for (int p = 0; p < 16; p++) { a0[p] = 0.f; a1[p] = 0.f; }
        #pragma unroll
        for (int h = 0; h < 8; h++) {
            const uint4* blob = g_epk + ((size_t)((h * 16 + rowBlk) * 128 + kb)) * 768;
            const float w0 = irs0[h], w1 = irs1[h];
            #pragma unroll
            for (int t = 0; t < 4; t++) {
                uint4 H = blob[ubase + t];
                a0[t*2+0]   += blo(H.x) * w0;
                a0[t*2+1]   += bhi(H.x) * w0;
                a1[t*2+0]   += blo(H.y) * w1;
                a1[t*2+1]   += bhi(H.y) * w1;
                a0[8+t*2+0] += blo(H.z) * w0;
                a0[8+t*2+1] += bhi(H.z) * w0;
                a1[8+t*2+0] += blo(H.w) * w1;
                a1[8+t*2+1] += bhi(H.w) * w1;
            }
        }
        const int j0 = kb * 16;
        uint4 mv0 = *reinterpret_cast<const uint4*>(g_mask + (size_t)i0 * Nn + j0);
        uint4 mv1 = *reinterpret_cast<const uint4*>(g_mask + (size_t)i1 * Nn + j0);
        const uint8_t* mb0 = reinterpret_cast<const uint8_t*>(&mv0);
        const uint8_t* mb1 = reinterpret_cast<const uint8_t*>(&mv1);
        float e0[16], e1[16];
        #pragma unroll
        for (int p = 0; p < 16; p++) {
            e0[p] = __expf(a0[p] * 0.125f);
            e1[p] = __expf(a1[p] * 0.125f);
            if (mb0[p]) msum0 += e0[p];
            if (mb1[p]) msum1 += e1[p];
        }
        float* d0 = g_es + (size_t)i0 * Nn + j0;
        float* d1 = g_es + (size_t)i1 * Nn + j0;
        #pragma unroll
        for (int q = 0; q < 4; q++) {
            *reinterpret_cast<float4*>(d0 + q * 4) =
                make_float4(e0[q*4], e0[q*4+1], e0[q*4+2], e0[q*4+3]);
            *reinterpret_cast<float4*>(d1 + q * 4) =
                make_float4(e1[q*4], e1[q*4+1], e1[q*4+2], e1[q*4+3]);
        }
    }
    #pragma unroll
    for (int o = 16; o > 0; o >>= 1) {
        msum0 += __shfl_xor_sync(0xffffffffu, msum0, o);
        msum1 += __shfl_xor_sync(0xffffffffu, msum1, o);
    }
    if (lane == 0) { g_srow[i0] = msum0; g_srow[i1] = msum1; }
}

// ---------------- simround2 pass2 ----------------
__global__ __launch_bounds__(256) void simr2_pass2(float* __restrict__ out)
{
    int idx = blockIdx.x * blockDim.x + threadIdx.x;
    if (idx >= Nn * Nn / 4) return;
    const int i = idx >> 9;
    const int j = (idx & 511) * 4;
    const float inv = 1.f / g_srow[i];
    uchar4 m = *reinterpret_cast<const uchar4*>(g_mask + (size_t)i * Nn + j);
    float4 e = *reinterpret_cast<const float4*>(g_es + (size_t)i * Nn + j);
    *reinterpret_cast<float4*>(out + (size_t)i * Nn + j) = make_float4(
        m.x ? e.x * inv : 0.f, m.y ? e.y * inv : 0.f,
        m.z ? e.z * inv : 0.f, m.w ? e.w * inv : 0.f);
}

// ---------------- host launcher ----------------
extern "C" void kernel_launch(void* const* d_in, const int* in_sizes, int n_in,
                              void* d_out, int out_size)
{
    const float* x   = (const float*)d_in[0];
    const float* cls = (const float*)d_in[1];
    const float* W   = (const float*)d_in[3];
    float* out = (float*)d_out;

    float *p_qkv, *p_q, *p_k, *p_vn, *p_vT, *p_rs, *p_part;
    uint4 *p_xp, *p_Wp, *p_qp, *p_kp, *p_vnpA, *p_vnpB, *p_vTp, *p_epk;
    uint8_t* p_mask;
    cudaGetSymbolAddress((void**)&p_qkv, g_qkv);
    cudaGetSymbolAddress((void**)&p_q, g_q);
    cudaGetSymbolAddress((void**)&p_k, g_k);
    cudaGetSymbolAddress((void**)&p_vn, g_vn);
    cudaGetSymbolAddress((void**)&p_vT, g_vT);
    cudaGetSymbolAddress((void**)&p_rs, g_rowsum);
    cudaGetSymbolAddress((void**)&p_part, g_part);
    cudaGetSymbolAddress((void**)&p_xp, g_xp);
    cudaGetSymbolAddress((void**)&p_Wp, g_Wp);
    cudaGetSymbolAddress((void**)&p_qp, g_qp);
    cudaGetSymbolAddress((void**)&p_kp, g_kp);
    cudaGetSymbolAddress((void**)&p_vnpA, g_vnpA);
    cudaGetSymbolAddress((void**)&p_vnpB, g_vnpB);
    cudaGetSymbolAddress((void**)&p_vTp, g_vTp);
    cudaGetSymbolAddress((void**)&p_epk, g_epk);
    cudaGetSymbolAddress((void**)&p_mask, g_mask);

    // pack x, W
    pack_a2<<<dim3(64, 16, 1), 256>>>(x, Cc, 0, p_xp, 64);
    pack_b2<<<dim3(64, 24, 1), 256>>>(W, Cc, 0, p_Wp, 64);

    // 1. qkv = x @ W^T (3 products)
    gemm_pk<0, 3><<<dim3(24, 16, 1), 256>>>(p_xp, p_Wp, 64, 64, 64, 16, 24, 0,
                                            p_qkv, 3 * Cc, 0, nullptr, nullptr, nullptr, nullptr);

    // 2. normalize (smem-transposed vT writes)
    normalize_kernel<<<dim3(64, 8), 256>>>();

    // 3. pack q, k, vn (A+B), vT
    pack_a2<<<dim3(8, 16, 8), 256>>>(p_q, HD, (long long)Nn * HD, p_qp, 8);
    pack_b2<<<dim3(8, 16, 8), 256>>>(p_k, HD, (long long)Nn * HD, p_kp, 8);
    pack_a2<<<dim3(64, 16, 1), 256>>>(p_vn, Cc, 0, p_vnpA, 64);
    pack_b2<<<dim3(64, 16, 1), 256>>>(p_vn, Cc, 0, p_vnpB, 64);
    pack_b2<<<dim3(128, 1, 8), 256>>>(p_vT, Nn, (long long)HD * Nn, p_vTp, 128);

    // 4. sim mask (symmetric upper-triangle, 1 product)
    gemm_pk<3, 1><<<dim3(136, 1, 1), 256>>>(p_vnpA, p_vnpB, 64, 64, 64, 16, 16, 0,
                                            nullptr, 0, 0, nullptr, nullptr, nullptr, p_mask);

    // 5. logits + fused masked-exp -> packed e + rowsums (3 products)
    cudaMemsetAsync(p_rs, 0, Hh * Nn * sizeof(float));
    gemm_pk<2, 3><<<dim3(16, 16, 8), 256>>>(p_qp, p_kp, 8, 8, 8, 16, 16, 0,
                                            nullptr, 0, 0, cls, p_epk, p_rs, nullptr);

    // 6. attn@V split-K x2 (2 products: e 2-term x v hi)
    gemm_pk<0, 2><<<dim3(1, 16, 16), 256>>>(p_epk, p_vTp, 64, 128, 128, 16, 1, 1,
                                            p_part, HD, (long long)Nn * HD,
                                            nullptr, nullptr, nullptr, nullptr);

    // 7. combine partials / rowsum + x_ori copy (fused)
    combine_kernel<<<(Nn * Cc / 4 + 255) / 256, 256>>>(out);

    // 8. sim_round2
    simr2_pass1<<<128, 256>>>();
    simr2_pass2<<<(Nn * Nn / 4 + 255) / 256, 256>>>(out + (size_t)Nn * 2 * Cc);
}

// round 11
// speedup vs baseline: 1.3716x; 1.0331x over previous
#include <cuda_runtime.h>
#include <math.h>
#include <stdint.h>

#define Nn 2048
#define Cc 1024
#define Hh 8
#define HD 128
#define SCALE_F 25.0f

// ---------------- scratch ----------------
__device__ float g_qkv[Nn * 3 * Cc];
__device__ float g_q[Hh * Nn * HD];
__device__ float g_k[Hh * Nn * HD];
__device__ float g_vn[Nn * Cc];
__device__ float g_vT[Hh * HD * Nn];
__device__ float g_rowsum[Hh * Nn];
__device__ float g_part[(size_t)16 * Nn * HD];
__device__ float g_srow[Nn];
__device__ uint8_t g_mask[(size_t)Nn * Nn];

// packed bf16 fragment images; tile = 128 rows x 16 k (stride 768 uint4)
__device__ uint4 g_xp [(size_t)16 * 64 * 768];
__device__ uint4 g_Wp [(size_t)24 * 64 * 768];
__device__ uint4 g_qp [(size_t)8 * 16 * 8 * 768];
__device__ uint4 g_kp [(size_t)8 * 16 * 8 * 768];
__device__ uint4 g_vnpA[(size_t)16 * 64 * 768];
__device__ uint4 g_vnpB[(size_t)16 * 64 * 768];
__device__ uint4 g_vTp[(size_t)8 * 128 * 768];
__device__ uint4 g_epk[(size_t)8 * 16 * 128 * 768];

// ---------------- helpers ----------------
__device__ __forceinline__ uint32_t packbf(float x, float y)
{
    uint32_t h;
    asm("cvt.rn.bf16x2.f32 %0, %1, %2;" : "=r"(h) : "f"(y), "f"(x));
    return h;
}
__device__ __forceinline__ float blo(uint32_t u) { return __uint_as_float(u << 16); }
__device__ __forceinline__ float bhi(uint32_t u) { return __uint_as_float(u & 0xFFFF0000u); }
__device__ __forceinline__ void split2(float x, float y, uint32_t& s0, uint32_t& s1)
{
    s0 = packbf(x, y);
    s1 = packbf(x - blo(s0), y - bhi(s0));
}

__device__ __forceinline__ void mma_bf16(float c[4], const uint32_t a[4],
                                         uint32_t b0, uint32_t b1)
{
    asm volatile(
        "mma.sync.aligned.m16n8k16.row.col.f32.bf16.bf16.f32 "
        "{%0,%1,%2,%3}, {%4,%5,%6,%7}, {%8,%9}, {%0,%1,%2,%3};"
        : "+f"(c[0]), "+f"(c[1]), "+f"(c[2]), "+f"(c[3])
        : "r"(a[0]), "r"(a[1]), "r"(a[2]), "r"(a[3]), "r"(b0), "r"(b1));
}

__device__ __forceinline__ void cpa16(void* smem, const void* gmem)
{
    uint32_t s = (uint32_t)__cvta_generic_to_shared(smem);
    asm volatile("cp.async.cg.shared.global [%0], [%1], 16;" :: "r"(s), "l"(gmem));
}
#define CP_COMMIT() asm volatile("cp.async.commit_group;")
#define CP_WAIT1()  asm volatile("cp.async.wait_group 1;")
#define CP_WAIT0()  asm volatile("cp.async.wait_group 0;")

// ---------------- pack kernels (TERMS = planes written) ----------------
template<int TERMS>
__global__ __launch_bounds__(256) void pack_a(
    const float* __restrict__ src, int lda, long long zstride, uint4* __restrict__ dst, int nKb)
{
    const int kb = blockIdx.x, rb = blockIdx.y, z = blockIdx.z;
    src += (long long)z * zstride;
    uint32_t* tb = (uint32_t*)(dst + ((size_t)(z * gridDim.y + rb) * nKb + kb) * 768);
    const int tid = threadIdx.x;
    #pragma unroll
    for (int t = 0; t < 2; t++) {
        int idx = tid + t * 256;
        int row = idx >> 2, k4 = (idx & 3) * 4;
        float4 v = *reinterpret_cast<const float4*>(
            &src[(long long)(rb * 128 + row) * lda + kb * 16 + k4]);
        int m = row >> 4, r16 = row & 15, g = r16 & 7, half = r16 >> 3;
        int tt = (k4 & 7) >> 1, reg = half + 2 * (k4 >> 3);
        int base = (m * 32 + g * 4 + tt) * 4 + reg;
        uint32_t s0, s1;
        split2(v.x, v.y, s0, s1);
        tb[base] = s0;
        if (TERMS >= 2) tb[1024 + base] = s1;
        split2(v.z, v.w, s0, s1);
        tb[base + 4] = s0;
        if (TERMS >= 2) tb[1024 + base + 4] = s1;
    }
}

template<int TERMS>
__global__ __launch_bounds__(256) void pack_b(
    const float* __restrict__ src, int ldb, long long zstride, uint4* __restrict__ dst, int nKb)
{
    const int kb = blockIdx.x, rb = blockIdx.y, z = blockIdx.z;
    src += (long long)z * zstride;
    uint32_t* tb = (uint32_t*)(dst + ((size_t)(z * gridDim.y + rb) * nKb + kb) * 768);
    const int tid = threadIdx.x;
    #pragma unroll
    for (int t = 0; t < 2; t++) {
        int idx = tid + t * 256;
        int row = idx >> 2, k4 = (idx & 3) * 4;
        float4 v = *reinterpret_cast<const float4*>(
            &src[(long long)(rb * 128 + row) * ldb + kb * 16 + k4]);
        int nb = row >> 3, g = row & 7;
        int tt = (k4 & 7) >> 1, reg = k4 >> 3;
        int base = (nb * 32 + g * 4 + tt) * 2 + reg;
        uint32_t s0, s1;
        split2(v.x, v.y, s0, s1);
        tb[base] = s0;
        if (TERMS >= 2) tb[1024 + base] = s1;
        split2(v.z, v.w, s0, s1);
        tb[base + 2] = s0;
        if (TERMS >= 2) tb[1024 + base + 2] = s1;
    }
}

// ---------------- packed bf16 GEMM, cp.async 3-stage, PROD-gated plane loads ----------------
// MODE 0: plain fp32 store. MODE 2: logits->masked exp + packed e + rowsums.
// MODE 3: symmetric sim mask. PROD = products (1: hh, 2: +lh, 3: +hl).
template<int MODE, int PROD>
__global__ __launch_bounds__(256, 2) void gemm_pk(
    const uint4* __restrict__ At, const uint4* __restrict__ Bt,
    int nK, int nKtotA, int nKtotB, int nRbA, int nRbB, int kzBits,
    float* __restrict__ C, int ldc, long long cZ,
    const float* __restrict__ cls, uint4* __restrict__ epk,
    float* __restrict__ rsOut, uint8_t* __restrict__ maskOut)
{
    int bx, by;
    if (MODE == 3) {
        int r = blockIdx.x, row = 0;
        while (r >= 16 - row) { r -= 16 - row; row++; }
        by = row; bx = row + r;
    } else { bx = blockIdx.x; by = blockIdx.y; }

    const int hz = blockIdx.z >> kzBits;
    const int kz = blockIdx.z & ((1 << kzBits) - 1);
    const uint4* Ab = At + ((size_t)(hz * nRbA + by) * nKtotA + (size_t)kz * nK) * 768;
    const uint4* Bb = Bt + ((size_t)(hz * nRbB + bx) * nKtotB + (size_t)kz * nK) * 768;

    __shared__ uint4 smA[3][512], smB[3][512];

    const int tid = threadIdx.x, lane = tid & 31, wid = tid >> 5;
    const int wm = wid >> 1, wn = wid & 1;

    float acc[2][8][4];
    #pragma unroll
    for (int mt = 0; mt < 2; mt++)
        #pragma unroll
        for (int nt = 0; nt < 8; nt++)
            #pragma unroll
            for (int r = 0; r < 4; r++) acc[mt][nt][r] = 0.f;

    auto stage_load = [&](int kb, int st) {
        const uint4* An = Ab + (size_t)kb * 768;
        const uint4* Bn = Bb + (size_t)kb * 768;
        cpa16(&smA[st][tid], An + tid);
        if (PROD >= 2) cpa16(&smA[st][256 + tid], An + 256 + tid);
        cpa16(&smB[st][tid], Bn + tid);
        if (PROD >= 3) cpa16(&smB[st][256 + tid], Bn + 256 + tid);
        CP_COMMIT();
    };

    stage_load(0, 0);
    if (nK > 1) stage_load(1, 1);

    int cur = 0;
    for (int kb = 0; kb < nK; kb++) {
        if (kb + 2 <= nK) CP_WAIT1(); else CP_WAIT0();
        __syncthreads();

        uint32_t af[2][2][4];
        #pragma unroll
        for (int mt = 0; mt < 2; mt++)
            *reinterpret_cast<uint4*>(af[0][mt]) =
                smA[cur][(wm * 2 + mt) * 32 + lane];
        if (PROD >= 2) {
            #pragma unroll
            for (int mt = 0; mt < 2; mt++)
                *reinterpret_cast<uint4*>(af[1][mt]) =
                    smA[cur][256 + (wm * 2 + mt) * 32 + lane];
        }

        const uint2* B2 = reinterpret_cast<const uint2*>(smB[cur]);
        uint2 b0[8];
        #pragma unroll
        for (int nt = 0; nt < 8; nt++) b0[nt] = B2[(wn * 8 + nt) * 32 + lane];
        #pragma unroll
        for (int nt = 0; nt < 8; nt++)
            #pragma unroll
            for (int mt = 0; mt < 2; mt++)
                mma_bf16(acc[mt][nt], af[0][mt], b0[nt].x, b0[nt].y);   // hi*hi
        if (PROD >= 2) {
            #pragma unroll
            for (int nt = 0; nt < 8; nt++)
                #pragma unroll
                for (int mt = 0; mt < 2; mt++)
                    mma_bf16(acc[mt][nt], af[1][mt], b0[nt].x, b0[nt].y);  // lo*hi
        }
        if (PROD >= 3) {
            uint2 b1[8];
            #pragma unroll
            for (int nt = 0; nt < 8; nt++) b1[nt] = B2[512 + (wn * 8 + nt) * 32 + lane];
            #pragma unroll
            for (int nt = 0; nt < 8; nt++)
                #pragma unroll
                for (int mt = 0; mt < 2; mt++)
                    mma_bf16(acc[mt][nt], af[0][mt], b1[nt].x, b1[nt].y);  // hi*lo
        }

        if (kb + 2 < nK) stage_load(kb + 2, (kb + 2) % 3);
        else CP_COMMIT();
        cur = (cur + 1 == 3) ? 0 : cur + 1;
    }

    const int g = lane >> 2, tq = lane & 3;

    if (MODE == 2) {
        #pragma unroll
        for (int mt = 0; mt < 2; mt++) {
            const int m = wm * 2 + mt;
            const int i0 = by * 128 + m * 16 + g;
            const int i1 = i0 + 8;
            const float tha = cls[i0] - 0.1f;
            const float thb = cls[i1] - 0.1f;
            float rs0 = 0.f, rs1 = 0.f;
            const int baseW = (m * 32 + g * 4 + tq) * 4;
            #pragma unroll
            for (int ntp = 0; ntp < 4; ntp++) {
                uint32_t hw[4], lw[4];
                #pragma unroll
                for (int sub = 0; sub < 2; sub++) {
                    const int nt = ntp * 2 + sub;
                    const int j = bx * 128 + wn * 64 + nt * 8 + tq * 2;
                    const float cj0 = cls[j], cj1 = cls[j + 1];
                    float e00 = (cj0 > tha) ? __expf(acc[mt][nt][0] * cj0) : 1.f;
                    float e01 = (cj1 > tha) ? __expf(acc[mt][nt][1] * cj1) : 1.f;
                    float e10 = (cj0 > thb) ? __expf(acc[mt][nt][2] * cj0) : 1.f;
                    float e11 = (cj1 > thb) ? __expf(acc[mt][nt][3] * cj1) : 1.f;
                    rs0 += e00 + e01;
                    rs1 += e10 + e11;
                    split2(e00, e01, hw[sub * 2], lw[sub * 2]);
                    split2(e10, e11, hw[sub * 2 + 1], lw[sub * 2 + 1]);
                }
                const size_t tIdx = (size_t)(hz * 16 + by) * 128 + bx * 8 + wn * 4 + ntp;
                uint32_t* tb = (uint32_t*)(epk + tIdx * 768);
                *reinterpret_cast<uint4*>(&tb[baseW]) =
                    make_uint4(hw[0], hw[1], hw[2], hw[3]);
                *reinterpret_cast<uint4*>(&tb[1024 + baseW]) =
                    make_uint4(lw[0], lw[1], lw[2], lw[3]);
            }
            rs0 += __shfl_xor_sync(0xffffffffu, rs0, 1);
            rs0 += __shfl_xor_sync(0xffffffffu, rs0, 2);
            rs1 += __shfl_xor_sync(0xffffffffu, rs1, 1);
            rs1 += __shfl_xor_sync(0xffffffffu, rs1, 2);
            if (tq == 0) {
                atomicAdd(&rsOut[hz * Nn + i0], rs0);
                atomicAdd(&rsOut[hz * Nn + i1], rs1);
            }
        }
    } else if (MODE == 3) {
        __syncthreads();
        uint8_t* sb = reinterpret_cast<uint8_t*>(smA);
        #pragma unroll
        for (int mt = 0; mt < 2; mt++)
            #pragma unroll
            for (int nt = 0; nt < 8; nt++) {
                const int r0 = wm * 32 + mt * 16 + g;
                const int c0 = wn * 64 + nt * 8 + tq * 2;
                sb[r0 * 144 + c0]           = acc[mt][nt][0] > 6.f;
                sb[r0 * 144 + c0 + 1]       = acc[mt][nt][1] > 6.f;
                sb[(r0 + 8) * 144 + c0]     = acc[mt][nt][2] > 6.f;
                sb[(r0 + 8) * 144 + c0 + 1] = acc[mt][nt][3] > 6.f;
            }
        __syncthreads();
        const int r = tid >> 1, hf = tid & 1;
        {
            const uint8_t* srcp = sb + r * 144 + hf * 64;
            uint4 v0 = *reinterpret_cast<const uint4*>(srcp);
            uint4 v1 = *reinterpret_cast<const uint4*>(srcp + 16);
            uint4 v2 = *reinterpret_cast<const uint4*>(srcp + 32);
            uint4 v3 = *reinterpret_cast<const uint4*>(srcp + 48);
            uint8_t* dst = maskOut + (size_t)(by * 128 + r) * Nn + bx * 128 + hf * 64;
            *reinterpret_cast<uint4*>(dst)      = v0;
            *reinterpret_cast<uint4*>(dst + 16) = v1;
            *reinterpret_cast<uint4*>(dst + 32) = v2;
            *reinterpret_cast<uint4*>(dst + 48) = v3;
        }
        {
            uint32_t wv[16];
            #pragma unroll
            for (int q = 0; q < 16; q++) {
                uint32_t b0 = sb[(hf * 64 + q * 4 + 0) * 144 + r];
                uint32_t b1 = sb[(hf * 64 + q * 4 + 1) * 144 + r];
                uint32_t b2 = sb[(hf * 64 + q * 4 + 2) * 144 + r];
                uint32_t b3 = sb[(hf * 64 + q * 4 + 3) * 144 + r];
                wv[q] = b0 | (b1 << 8) | (b2 << 16) | (b3 << 24);
            }
            uint8_t* dst = maskOut + (size_t)(bx * 128 + r) * Nn + by * 128 + hf * 64;
            #pragma unroll
            for (int q = 0; q < 4; q++)
                *reinterpret_cast<uint4*>(dst + q * 16) =
                    make_uint4(wv[q*4], wv[q*4+1], wv[q*4+2], wv[q*4+3]);
        }
    } else {
        float* Cz = C + (long long)blockIdx.z * cZ;
        #pragma unroll
        for (int mt = 0; mt < 2; mt++) {
            const int row0 = by * 128 + wm * 32 + mt * 16 + g;
            #pragma unroll
            for (int nt = 0; nt < 8; nt++) {
                const int col = bx * 128 + wn * 64 + nt * 8 + tq * 2;
                *reinterpret_cast<float2*>(&Cz[(long long)row0 * ldc + col]) =
                    make_float2(acc[mt][nt][0], acc[mt][nt][1]);
                *reinterpret_cast<float2*>(&Cz[(long long)(row0 + 8) * ldc + col]) =
                    make_float2(acc[mt][nt][2], acc[mt][nt][3]);
            }
        }
    }
}

// ---------------- normalize: block = (32 tokens, 1 head), smem transpose for vT ----------------
__global__ __launch_bounds__(256) void normalize_kernel()
{
    const int nb = blockIdx.x;
    const int h  = blockIdx.y;
    const int tid = threadIdx.x;
    const int nl = tid >> 3;
    const int dg = tid & 7;
    const int n = nb * 32 + nl;

    __shared__ float sv[32 * 132];

    const float* base = g_qkv + (size_t)n * (3 * Cc) + h * HD;

    float4 qv[4], kv[4], vv[4];
    #pragma unroll
    for (int r = 0; r < 4; r++) {
        const int d = (dg + 8 * r) * 4;
        qv[r] = *reinterpret_cast<const float4*>(base + d);
        kv[r] = *reinterpret_cast<const float4*>(base + Cc + d);
        vv[r] = *reinterpret_cast<const float4*>(base + 2 * Cc + d);
    }
    float sq = 0.f, sk = 0.f, sv2 = 0.f;
    #pragma unroll
    for (int r = 0; r < 4; r++) {
        sq  += qv[r].x*qv[r].x + qv[r].y*qv[r].y + qv[r].z*qv[r].z + qv[r].w*qv[r].w;
        sk  += kv[r].x*kv[r].x + kv[r].y*kv[r].y + kv[r].z*kv[r].z + kv[r].w*kv[r].w;
        sv2 += vv[r].x*vv[r].x + vv[r].y*vv[r].y + vv[r].z*vv[r].z + vv[r].w*vv[r].w;
    }
    #pragma unroll
    for (int o = 1; o < 8; o <<= 1) {
        sq  += __shfl_xor_sync(0xffffffffu, sq, o);
        sk  += __shfl_xor_sync(0xffffffffu, sk, o);
        sv2 += __shfl_xor_sync(0xffffffffu, sv2, o);
    }
    const float iq = SCALE_F / sqrtf(sq);
    const float ik = 1.0f / sqrtf(sk);
    const float iv = 1.0f / sqrtf(sv2);

    float* gq = g_q + (size_t)h * Nn * HD + (size_t)n * HD;
    float* gk = g_k + (size_t)h * Nn * HD + (size_t)n * HD;
    float* gv = g_vn + (size_t)n * Cc + h * HD;
    #pragma unroll
    for (int r = 0; r < 4; r++) {
        const int d = (dg + 8 * r) * 4;
        *reinterpret_cast<float4*>(gq + d) =
            make_float4(qv[r].x*iq, qv[r].y*iq, qv[r].z*iq, qv[r].w*iq);
        *reinterpret_cast<float4*>(gk + d) =
            make_float4(kv[r].x*ik, kv[r].y*ik, kv[r].z*ik, kv[r].w*ik);
        *reinterpret_cast<float4*>(gv + d) =
            make_float4(vv[r].x*iv, vv[r].y*iv, vv[r].z*iv, vv[r].w*iv);
        float* s = sv + nl * 132 + d;
        s[0] = vv[r].x; s[1] = vv[r].y; s[2] = vv[r].z; s[3] = vv[r].w;
    }
    __syncthreads();

    const int w = tid >> 5, lane = tid & 31;
    #pragma unroll
    for (int it = 0; it < 4; it++) {
        const int d = w * 16 + it * 4 + (lane >> 3);
        const int n4 = (lane & 7) * 4;
        float4 o;
        o.x = sv[(n4 + 0) * 132 + d];
        o.y = sv[(n4 + 1) * 132 + d];
        o.z = sv[(n4 + 2) * 132 + d];
        o.w = sv[(n4 + 3) * 132 + d];
        *reinterpret_cast<float4*>(
            g_vT + (size_t)(h * HD + d) * Nn + nb * 32 + n4) = o;
    }
}

// ---------------- combine split-K partials + copy x_ori (fused) ----------------
__global__ __launch_bounds__(256) void combine_kernel(float* __restrict__ out)
{
    int idx = blockIdx.x * 256 + threadIdx.x;
    if (idx >= Nn * Cc / 4) return;
    const int n = idx >> 8, c4 = idx & 255;
    const int h = c4 >> 5, d4 = c4 & 31;
    const float4* p = reinterpret_cast<const float4*>(g_part);
    const size_t st = (size_t)Nn * 32;
    const size_t b = ((size_t)(h * 2) * Nn + n) * 32 + d4;
    float4 a0 = p[b], a1 = p[b + st];
    const float s = 1.f / g_rowsum[h * Nn + n];
    *reinterpret_cast<float4*>(out + (size_t)n * (2 * Cc) + h * 128 + d4 * 4) =
        make_float4((a0.x + a1.x) * s, (a0.y + a1.y) * s,
                    (a0.z + a1.z) * s, (a0.w + a1.w) * s);
    float4 v = *reinterpret_cast<const float4*>(
        &g_qkv[(size_t)n * (3 * Cc) + 2 * Cc + h * 128 + d4 * 4]);
    *reinterpret_cast<float4*>(out + (size_t)n * (2 * Cc) + Cc + h * 128 + d4 * 4) = v;
}

// ---------------- simround2 merged: e in registers, single epk read ----------------
__global__ __launch_bounds__(256) void simr2_merged(float* __restrict__ out)
{
    const int blk = blockIdx.x;
    const int rowBlk = blk >> 3, m = blk & 7;
    const int tid = threadIdx.x;
    const int gg = tid >> 5;
    const int lane = tid & 31;
    const int i0 = blk * 16 + gg;
    const int i1 = i0 + 8;
    const int ubase = m * 32 + gg * 4;
    __shared__ float sinv[16];

    float irs0[8], irs1[8];
    #pragma unroll
    for (int h = 0; h < 8; h++) {
        irs0[h] = 1.f / g_rowsum[h * Nn + i0];
        irs1[h] = 1.f / g_rowsum[h * Nn + i1];
    }

    float e0r[64], e1r[64];
    float msum0 = 0.f, msum1 = 0.f;
    #pragma unroll
    for (int kt = 0; kt < 4; kt++) {
        const int kb = lane + kt * 32;
        float a0[16], a1[16];
        #pragma unroll
        for (int p = 0; p < 16; p++) { a0[p] = 0.f; a1[p] = 0.f; }
        #pragma unroll
        for (int h = 0; h < 8; h++) {
            const uint4* blob = g_epk + ((size_t)((h * 16 + rowBlk) * 128 + kb)) * 768;
            const float w0 = irs0[h], w1 = irs1[h];
            #pragma unroll
            for (int t = 0; t < 4; t++) {
                uint4 H = blob[ubase + t];
                a0[t*2+0]   += blo(H.x) * w0;
                a0[t*2+1]   += bhi(H.x) * w0;
                a1[t*2+0]   += blo(H.y) * w1;
                a1[t*2+1]   += bhi(H.y) * w1;
                a0[8+t*2+0] += blo(H.z) * w0;
                a0[8+t*2+1] += bhi(H.z) * w0;
                a1[8+t*2+0] += blo(H.w) * w1;
                a1[8+t*2+1] += bhi(H.w) * w1;
            }
        }
        const int j0 = kb * 16;
        uint4 mv0 = *reinterpret_cast<const uint4*>(g_mask + (size_t)i0 * Nn + j0);
        uint4 mv1 = *reinterpret_cast<const uint4*>(g_mask + (size_t)i1 * Nn + j0);
        const uint8_t* mb0 = reinterpret_cast<const uint8_t*>(&mv0);
        const uint8_t* mb1 = reinterpret_cast<const uint8_t*>(&mv1);
        #pragma unroll
        for (int p = 0; p < 16; p++) {
            float e0 = __expf(a0[p] * 0.125f);
            float e1 = __expf(a1[p] * 0.125f);
            e0r[kt * 16 + p] = e0;
            e1r[kt * 16 + p] = e1;
            if (mb0[p]) msum0 += e0;
            if (mb1[p]) msum1 += e1;
        }
    }
    #pragma unroll
    for (int o = 16; o > 0; o >>= 1) {
        msum0 += __shfl_xor_sync(0xffffffffu, msum0, o);
        msum1 += __shfl_xor_sync(0xffffffffu, msum1, o);
    }
    if (lane == 0) { sinv[gg] = 1.f / msum0; sinv[8 + gg] = 1.f / msum1; }
    __syncthreads();
    const float inv0 = sinv[gg], inv1 = sinv[8 + gg];

    #pragma unroll
    for (int kt = 0; kt < 4; kt++) {
        const int j0 = (lane + kt * 32) * 16;
        uint4 mv0 = *reinterpret_cast<const uint4*>(g_mask + (size_t)i0 * Nn + j0);
        uint4 mv1 = *reinterpret_cast<const uint4*>(g_mask + (size_t)i1 * Nn + j0);
        const uint8_t* mb0 = reinterpret_cast<const uint8_t*>(&mv0);
        const uint8_t* mb1 = reinterpret_cast<const uint8_t*>(&mv1);
        float* d0 = out + (size_t)i0 * Nn + j0;
        float* d1 = out + (size_t)i1 * Nn + j0;
        #pragma unroll
        for (int q = 0; q < 4; q++) {
            float4 o0, o1;
            o0.x = mb0[q*4+0] ? e0r[kt*16 + q*4+0] * inv0 : 0.f;
            o0.y = mb0[q*4+1] ? e0r[kt*16 + q*4+1] * inv0 : 0.f;
            o0.z = mb0[q*4+2] ? e0r[kt*16 + q*4+2] * inv0 : 0.f;
            o0.w = mb0[q*4+3] ? e0r[kt*16 + q*4+3] * inv0 : 0.f;
            o1.x = mb1[q*4+0] ? e1r[kt*16 + q*4+0] * inv1 : 0.f;
            o1.y = mb1[q*4+1] ? e1r[kt*16 + q*4+1] * inv1 : 0.f;
            o1.z = mb1[q*4+2] ? e1r[kt*16 + q*4+2] * inv1 : 0.f;
            o1.w = mb1[q*4+3] ? e1r[kt*16 + q*4+3] * inv1 : 0.f;
            *reinterpret_cast<float4*>(d0 + q * 4) = o0;
            *reinterpret_cast<float4*>(d1 + q * 4) = o1;
        }
    }
}

// ---------------- host launcher ----------------
extern "C" void kernel_launch(void* const* d_in, const int* in_sizes, int n_in,
                              void* d_out, int out_size)
{
    const float* x   = (const float*)d_in[0];
    const float* cls = (const float*)d_in[1];
    const float* W   = (const float*)d_in[3];
    float* out = (float*)d_out;

    float *p_qkv, *p_q, *p_k, *p_vn, *p_vT, *p_rs, *p_part;
    uint4 *p_xp, *p_Wp, *p_qp, *p_kp, *p_vnpA, *p_vnpB, *p_vTp, *p_epk;
    uint8_t* p_mask;
    cudaGetSymbolAddress((void**)&p_qkv, g_qkv);
    cudaGetSymbolAddress((void**)&p_q, g_q);
    cudaGetSymbolAddress((void**)&p_k, g_k);
    cudaGetSymbolAddress((void**)&p_vn, g_vn);
    cudaGetSymbolAddress((void**)&p_vT, g_vT);
    cudaGetSymbolAddress((void**)&p_rs, g_rowsum);
    cudaGetSymbolAddress((void**)&p_part, g_part);
    cudaGetSymbolAddress((void**)&p_xp, g_xp);
    cudaGetSymbolAddress((void**)&p_Wp, g_Wp);
    cudaGetSymbolAddress((void**)&p_qp, g_qp);
    cudaGetSymbolAddress((void**)&p_kp, g_kp);
    cudaGetSymbolAddress((void**)&p_vnpA, g_vnpA);
    cudaGetSymbolAddress((void**)&p_vnpB, g_vnpB);
    cudaGetSymbolAddress((void**)&p_vTp, g_vTp);
    cudaGetSymbolAddress((void**)&p_epk, g_epk);
    cudaGetSymbolAddress((void**)&p_mask, g_mask);

    // pack x, W (2-term)
    pack_a<2><<<dim3(64, 16, 1), 256>>>(x, Cc, 0, p_xp, 64);
    pack_b<2><<<dim3(64, 24, 1), 256>>>(W, Cc, 0, p_Wp, 64);

    // 1. qkv = x @ W^T (3 products)
    gemm_pk<0, 3><<<dim3(24, 16, 1), 256>>>(p_xp, p_Wp, 64, 64, 64, 16, 24, 0,
                                            p_qkv, 3 * Cc, 0, nullptr, nullptr, nullptr, nullptr);

    // 2. normalize
    normalize_kernel<<<dim3(64, 8), 256>>>();

    // 3. pack q, k (2-term), vn A/B + vT (hi only)
    pack_a<2><<<dim3(8, 16, 8), 256>>>(p_q, HD, (long long)Nn * HD, p_qp, 8);
    pack_b<2><<<dim3(8, 16, 8), 256>>>(p_k, HD, (long long)Nn * HD, p_kp, 8);
    pack_a<1><<<dim3(64, 16, 1), 256>>>(p_vn, Cc, 0, p_vnpA, 64);
    pack_b<1><<<dim3(64, 16, 1), 256>>>(p_vn, Cc, 0, p_vnpB, 64);
    pack_b<1><<<dim3(128, 1, 8), 256>>>(p_vT, Nn, (long long)HD * Nn, p_vTp, 128);

    // 4. sim mask (symmetric upper-triangle, 1 product)
    gemm_pk<3, 1><<<dim3(136, 1, 1), 256>>>(p_vnpA, p_vnpB, 64, 64, 64, 16, 16, 0,
                                            nullptr, 0, 0, nullptr, nullptr, nullptr, p_mask);

    // 5. logits + fused masked-exp -> packed e + rowsums (3 products)
    cudaMemsetAsync(p_rs, 0, Hh * Nn * sizeof(float));
    gemm_pk<2, 3><<<dim3(16, 16, 8), 256>>>(p_qp, p_kp, 8, 8, 8, 16, 16, 0,
                                            nullptr, 0, 0, cls, p_epk, p_rs, nullptr);

    // 6. attn@V split-K x2 (2 products; B lo plane never staged)
    gemm_pk<0, 2><<<dim3(1, 16, 16), 256>>>(p_epk, p_vTp, 64, 128, 128, 16, 1, 1,
                                            p_part, HD, (long long)Nn * HD,
                                            nullptr, nullptr, nullptr, nullptr);

    // 7. combine partials / rowsum + x_ori copy (fused)
    combine_kernel<<<(Nn * Cc / 4 + 255) / 256, 256>>>(out);

    // 8. sim_round2 (single merged kernel, e register-resident)
    simr2_merged<<<128, 256>>>(out + (size_t)Nn * 2 * Cc);
}

// round 12
// speedup vs baseline: 1.4647x; 1.0678x over previous
#include <cuda_runtime.h>
#include <math.h>
#include <stdint.h>

#define Nn 2048
#define Cc 1024
#define Hh 8
#define HD 128
#define SCALE_F 25.0f

// ---------------- scratch ----------------
__device__ float g_qkv[Nn * 3 * Cc];
__device__ float g_q[Hh * Nn * HD];
__device__ float g_k[Hh * Nn * HD];
__device__ float g_vn[Nn * Cc];
__device__ float g_vT[Hh * HD * Nn];
__device__ float g_rowsum[Hh * Nn];
__device__ float g_part[(size_t)16 * Nn * HD];
__device__ uint8_t g_mask[(size_t)Nn * Nn];

// packed bf16 fragment images; tile = 128 rows x 16 k (stride 768 uint4)
__device__ uint4 g_xp [(size_t)16 * 64 * 768];
__device__ uint4 g_Wp [(size_t)24 * 64 * 768];
__device__ uint4 g_qp [(size_t)8 * 16 * 8 * 768];
__device__ uint4 g_kp [(size_t)8 * 16 * 8 * 768];
__device__ uint4 g_vnpA[(size_t)16 * 64 * 768];
__device__ uint4 g_vnpB[(size_t)16 * 64 * 768];
__device__ uint4 g_vTp[(size_t)8 * 128 * 768];
__device__ uint4 g_epk[(size_t)8 * 16 * 128 * 768];   // hi plane only used

// ---------------- helpers ----------------
__device__ __forceinline__ uint32_t packbf(float x, float y)
{
    uint32_t h;
    asm("cvt.rn.bf16x2.f32 %0, %1, %2;" : "=r"(h) : "f"(y), "f"(x));
    return h;
}
__device__ __forceinline__ float blo(uint32_t u) { return __uint_as_float(u << 16); }
__device__ __forceinline__ float bhi(uint32_t u) { return __uint_as_float(u & 0xFFFF0000u); }
__device__ __forceinline__ void split2(float x, float y, uint32_t& s0, uint32_t& s1)
{
    s0 = packbf(x, y);
    s1 = packbf(x - blo(s0), y - bhi(s0));
}

__device__ __forceinline__ void mma_bf16(float c[4], const uint32_t a[4],
                                         uint32_t b0, uint32_t b1)
{
    asm volatile(
        "mma.sync.aligned.m16n8k16.row.col.f32.bf16.bf16.f32 "
        "{%0,%1,%2,%3}, {%4,%5,%6,%7}, {%8,%9}, {%0,%1,%2,%3};"
        : "+f"(c[0]), "+f"(c[1]), "+f"(c[2]), "+f"(c[3])
        : "r"(a[0]), "r"(a[1]), "r"(a[2]), "r"(a[3]), "r"(b0), "r"(b1));
}

__device__ __forceinline__ void cpa16(void* smem, const void* gmem)
{
    uint32_t s = (uint32_t)__cvta_generic_to_shared(smem);
    asm volatile("cp.async.cg.shared.global [%0], [%1], 16;" :: "r"(s), "l"(gmem));
}
#define CP_COMMIT() asm volatile("cp.async.commit_group;")
#define CP_WAIT1()  asm volatile("cp.async.wait_group 1;")
#define CP_WAIT0()  asm volatile("cp.async.wait_group 0;")

// ---------------- pack kernels (TERMS = planes written) ----------------
template<int TERMS>
__global__ __launch_bounds__(256) void pack_a(
    const float* __restrict__ src, int lda, long long zstride, uint4* __restrict__ dst, int nKb)
{
    const int kb = blockIdx.x, rb = blockIdx.y, z = blockIdx.z;
    src += (long long)z * zstride;
    uint32_t* tb = (uint32_t*)(dst + ((size_t)(z * gridDim.y + rb) * nKb + kb) * 768);
    const int tid = threadIdx.x;
    #pragma unroll
    for (int t = 0; t < 2; t++) {
        int idx = tid + t * 256;
        int row = idx >> 2, k4 = (idx & 3) * 4;
        float4 v = *reinterpret_cast<const float4*>(
            &src[(long long)(rb * 128 + row) * lda + kb * 16 + k4]);
        int m = row >> 4, r16 = row & 15, g = r16 & 7, half = r16 >> 3;
        int tt = (k4 & 7) >> 1, reg = half + 2 * (k4 >> 3);
        int base = (m * 32 + g * 4 + tt) * 4 + reg;
        uint32_t s0, s1;
        split2(v.x, v.y, s0, s1);
        tb[base] = s0;
        if (TERMS >= 2) tb[1024 + base] = s1;
        split2(v.z, v.w, s0, s1);
        tb[base + 4] = s0;
        if (TERMS >= 2) tb[1024 + base + 4] = s1;
    }
}

template<int TERMS>
__global__ __launch_bounds__(256) void pack_b(
    const float* __restrict__ src, int ldb, long long zstride, uint4* __restrict__ dst, int nKb)
{
    const int kb = blockIdx.x, rb = blockIdx.y, z = blockIdx.z;
    src += (long long)z * zstride;
    uint32_t* tb = (uint32_t*)(dst + ((size_t)(z * gridDim.y + rb) * nKb + kb) * 768);
    const int tid = threadIdx.x;
    #pragma unroll
    for (int t = 0; t < 2; t++) {
        int idx = tid + t * 256;
        int row = idx >> 2, k4 = (idx & 3) * 4;
        float4 v = *reinterpret_cast<const float4*>(
            &src[(long long)(rb * 128 + row) * ldb + kb * 16 + k4]);
        int nb = row >> 3, g = row & 7;
        int tt = (k4 & 7) >> 1, reg = k4 >> 3;
        int base = (nb * 32 + g * 4 + tt) * 2 + reg;
        uint32_t s0, s1;
        split2(v.x, v.y, s0, s1);
        tb[base] = s0;
        if (TERMS >= 2) tb[1024 + base] = s1;
        split2(v.z, v.w, s0, s1);
        tb[base + 2] = s0;
        if (TERMS >= 2) tb[1024 + base + 2] = s1;
    }
}

// ---------------- packed bf16 GEMM, cp.async 3-stage, PROD-gated plane loads ----------------
// MODE 0: plain fp32 store. MODE 2: logits->masked exp + packed e (hi only) + rowsums.
// MODE 3: symmetric sim mask. PROD = products (1: hh, 2: +lh, 3: +hl).
template<int MODE, int PROD>
__global__ __launch_bounds__(256, 2) void gemm_pk(
    const uint4* __restrict__ At, const uint4* __restrict__ Bt,
    int nK, int nKtotA, int nKtotB, int nRbA, int nRbB, int kzBits,
    float* __restrict__ C, int ldc, long long cZ,
    const float* __restrict__ cls, uint4* __restrict__ epk,
    float* __restrict__ rsOut, uint8_t* __restrict__ maskOut)
{
    int bx, by;
    if (MODE == 3) {
        int r = blockIdx.x, row = 0;
        while (r >= 16 - row) { r -= 16 - row; row++; }
        by = row; bx = row + r;
    } else { bx = blockIdx.x; by = blockIdx.y; }

    const int hz = blockIdx.z >> kzBits;
    const int kz = blockIdx.z & ((1 << kzBits) - 1);
    const uint4* Ab = At + ((size_t)(hz * nRbA + by) * nKtotA + (size_t)kz * nK) * 768;
    const uint4* Bb = Bt + ((size_t)(hz * nRbB + bx) * nKtotB + (size_t)kz * nK) * 768;

    __shared__ uint4 smA[3][512], smB[3][512];

    const int tid = threadIdx.x, lane = tid & 31, wid = tid >> 5;
    const int wm = wid >> 1, wn = wid & 1;

    float acc[2][8][4];
    #pragma unroll
    for (int mt = 0; mt < 2; mt++)
        #pragma unroll
        for (int nt = 0; nt < 8; nt++)
            #pragma unroll
            for (int r = 0; r < 4; r++) acc[mt][nt][r] = 0.f;

    auto stage_load = [&](int kb, int st) {
        const uint4* An = Ab + (size_t)kb * 768;
        const uint4* Bn = Bb + (size_t)kb * 768;
        cpa16(&smA[st][tid], An + tid);
        if (PROD >= 2) cpa16(&smA[st][256 + tid], An + 256 + tid);
        cpa16(&smB[st][tid], Bn + tid);
        if (PROD >= 3) cpa16(&smB[st][256 + tid], Bn + 256 + tid);
        CP_COMMIT();
    };

    stage_load(0, 0);
    if (nK > 1) stage_load(1, 1);

    int cur = 0;
    for (int kb = 0; kb < nK; kb++) {
        if (kb + 2 <= nK) CP_WAIT1(); else CP_WAIT0();
        __syncthreads();

        uint32_t af[2][2][4];
        #pragma unroll
        for (int mt = 0; mt < 2; mt++)
            *reinterpret_cast<uint4*>(af[0][mt]) =
                smA[cur][(wm * 2 + mt) * 32 + lane];
        if (PROD >= 2) {
            #pragma unroll
            for (int mt = 0; mt < 2; mt++)
                *reinterpret_cast<uint4*>(af[1][mt]) =
                    smA[cur][256 + (wm * 2 + mt) * 32 + lane];
        }

        const uint2* B2 = reinterpret_cast<const uint2*>(smB[cur]);
        uint2 b0[8];
        #pragma unroll
        for (int nt = 0; nt < 8; nt++) b0[nt] = B2[(wn * 8 + nt) * 32 + lane];
        #pragma unroll
        for (int nt = 0; nt < 8; nt++)
            #pragma unroll
            for (int mt = 0; mt < 2; mt++)
                mma_bf16(acc[mt][nt], af[0][mt], b0[nt].x, b0[nt].y);   // hi*hi
        if (PROD >= 2) {
            #pragma unroll
            for (int nt = 0; nt < 8; nt++)
                #pragma unroll
                for (int mt = 0; mt < 2; mt++)
                    mma_bf16(acc[mt][nt], af[1][mt], b0[nt].x, b0[nt].y);  // lo*hi
        }
        if (PROD >= 3) {
            uint2 b1[8];
            #pragma unroll
            for (int nt = 0; nt < 8; nt++) b1[nt] = B2[512 + (wn * 8 + nt) * 32 + lane];
            #pragma unroll
            for (int nt = 0; nt < 8; nt++)
                #pragma unroll
                for (int mt = 0; mt < 2; mt++)
                    mma_bf16(acc[mt][nt], af[0][mt], b1[nt].x, b1[nt].y);  // hi*lo
        }

        if (kb + 2 < nK) stage_load(kb + 2, (kb + 2) % 3);
        else CP_COMMIT();
        cur = (cur + 1 == 3) ? 0 : cur + 1;
    }

    const int g = lane >> 2, tq = lane & 3;

    if (MODE == 2) {
        #pragma unroll
        for (int mt = 0; mt < 2; mt++) {
            const int m = wm * 2 + mt;
            const int i0 = by * 128 + m * 16 + g;
            const int i1 = i0 + 8;
            const float tha = cls[i0] - 0.1f;
            const float thb = cls[i1] - 0.1f;
            float rs0 = 0.f, rs1 = 0.f;
            const int baseW = (m * 32 + g * 4 + tq) * 4;
            #pragma unroll
            for (int ntp = 0; ntp < 4; ntp++) {
                uint32_t hw[4];
                #pragma unroll
                for (int sub = 0; sub < 2; sub++) {
                    const int nt = ntp * 2 + sub;
                    const int j = bx * 128 + wn * 64 + nt * 8 + tq * 2;
                    const float cj0 = cls[j], cj1 = cls[j + 1];
                    float e00 = (cj0 > tha) ? __expf(acc[mt][nt][0] * cj0) : 1.f;
                    float e01 = (cj1 > tha) ? __expf(acc[mt][nt][1] * cj1) : 1.f;
                    float e10 = (cj0 > thb) ? __expf(acc[mt][nt][2] * cj0) : 1.f;
                    float e11 = (cj1 > thb) ? __expf(acc[mt][nt][3] * cj1) : 1.f;
                    rs0 += e00 + e01;
                    rs1 += e10 + e11;
                    hw[sub * 2]     = packbf(e00, e01);
                    hw[sub * 2 + 1] = packbf(e10, e11);
                }
                const size_t tIdx = (size_t)(hz * 16 + by) * 128 + bx * 8 + wn * 4 + ntp;
                uint32_t* tb = (uint32_t*)(epk + tIdx * 768);
                *reinterpret_cast<uint4*>(&tb[baseW]) =
                    make_uint4(hw[0], hw[1], hw[2], hw[3]);
            }
            rs0 += __shfl_xor_sync(0xffffffffu, rs0, 1);
            rs0 += __shfl_xor_sync(0xffffffffu, rs0, 2);
            rs1 += __shfl_xor_sync(0xffffffffu, rs1, 1);
            rs1 += __shfl_xor_sync(0xffffffffu, rs1, 2);
            if (tq == 0) {
                atomicAdd(&rsOut[hz * Nn + i0], rs0);
                atomicAdd(&rsOut[hz * Nn + i1], rs1);
            }
        }
    } else if (MODE == 3) {
        __syncthreads();
        uint8_t* sb = reinterpret_cast<uint8_t*>(smA);
        #pragma unroll
        for (int mt = 0; mt < 2; mt++)
            #pragma unroll
            for (int nt = 0; nt < 8; nt++) {
                const int r0 = wm * 32 + mt * 16 + g;
                const int c0 = wn * 64 + nt * 8 + tq * 2;
                sb[r0 * 144 + c0]           = acc[mt][nt][0] > 6.f;
                sb[r0 * 144 + c0 + 1]       = acc[mt][nt][1] > 6.f;
                sb[(r0 + 8) * 144 + c0]     = acc[mt][nt][2] > 6.f;
                sb[(r0 + 8) * 144 + c0 + 1] = acc[mt][nt][3] > 6.f;
            }
        __syncthreads();
        const int r = tid >> 1, hf = tid & 1;
        {
            const uint8_t* srcp = sb + r * 144 + hf * 64;
            uint4 v0 = *reinterpret_cast<const uint4*>(srcp);
            uint4 v1 = *reinterpret_cast<const uint4*>(srcp + 16);
            uint4 v2 = *reinterpret_cast<const uint4*>(srcp + 32);
            uint4 v3 = *reinterpret_cast<const uint4*>(srcp + 48);
            uint8_t* dst = maskOut + (size_t)(by * 128 + r) * Nn + bx * 128 + hf * 64;
            *reinterpret_cast<uint4*>(dst)      = v0;
            *reinterpret_cast<uint4*>(dst + 16) = v1;
            *reinterpret_cast<uint4*>(dst + 32) = v2;
            *reinterpret_cast<uint4*>(dst + 48) = v3;
        }
        {
            uint32_t wv[16];
            #pragma unroll
            for (int q = 0; q < 16; q++) {
                uint32_t b0 = sb[(hf * 64 + q * 4 + 0) * 144 + r];
                uint32_t b1 = sb[(hf * 64 + q * 4 + 1) * 144 + r];
                uint32_t b2 = sb[(hf * 64 + q * 4 + 2) * 144 + r];
                uint32_t b3 = sb[(hf * 64 + q * 4 + 3) * 144 + r];
                wv[q] = b0 | (b1 << 8) | (b2 << 16) | (b3 << 24);
            }
            uint8_t* dst = maskOut + (size_t)(bx * 128 + r) * Nn + by * 128 + hf * 64;
            #pragma unroll
            for (int q = 0; q < 4; q++)
                *reinterpret_cast<uint4*>(dst + q * 16) =
                    make_uint4(wv[q*4], wv[q*4+1], wv[q*4+2], wv[q*4+3]);
        }
    } else {
        float* Cz = C + (long long)blockIdx.z * cZ;
        #pragma unroll
        for (int mt = 0; mt < 2; mt++) {
            const int row0 = by * 128 + wm * 32 + mt * 16 + g;
            #pragma unroll
            for (int nt = 0; nt < 8; nt++) {
                const int col = bx * 128 + wn * 64 + nt * 8 + tq * 2;
                *reinterpret_cast<float2*>(&Cz[(long long)row0 * ldc + col]) =
                    make_float2(acc[mt][nt][0], acc[mt][nt][1]);
                *reinterpret_cast<float2*>(&Cz[(long long)(row0 + 8) * ldc + col]) =
                    make_float2(acc[mt][nt][2], acc[mt][nt][3]);
            }
        }
    }
}

// ---------------- normalize: block = (32 tokens, 1 head), smem transpose for vT ----------------
__global__ __launch_bounds__(256) void normalize_kernel()
{
    const int nb = blockIdx.x;
    const int h  = blockIdx.y;
    const int tid = threadIdx.x;
    const int nl = tid >> 3;
    const int dg = tid & 7;
    const int n = nb * 32 + nl;

    __shared__ float sv[32 * 132];

    const float* base = g_qkv + (size_t)n * (3 * Cc) + h * HD;

    float4 qv[4], kv[4], vv[4];
    #pragma unroll
    for (int r = 0; r < 4; r++) {
        const int d = (dg + 8 * r) * 4;
        qv[r] = *reinterpret_cast<const float4*>(base + d);
        kv[r] = *reinterpret_cast<const float4*>(base + Cc + d);
        vv[r] = *reinterpret_cast<const float4*>(base + 2 * Cc + d);
    }
    float sq = 0.f, sk = 0.f, sv2 = 0.f;
    #pragma unroll
    for (int r = 0; r < 4; r++) {
        sq  += qv[r].x*qv[r].x + qv[r].y*qv[r].y + qv[r].z*qv[r].z + qv[r].w*qv[r].w;
        sk  += kv[r].x*kv[r].x + kv[r].y*kv[r].y + kv[r].z*kv[r].z + kv[r].w*kv[r].w;
        sv2 += vv[r].x*vv[r].x + vv[r].y*vv[r].y + vv[r].z*vv[r].z + vv[r].w*vv[r].w;
    }
    #pragma unroll
    for (int o = 1; o < 8; o <<= 1) {
        sq  += __shfl_xor_sync(0xffffffffu, sq, o);
        sk  += __shfl_xor_sync(0xffffffffu, sk, o);
        sv2 += __shfl_xor_sync(0xffffffffu, sv2, o);
    }
    const float iq = SCALE_F / sqrtf(sq);
    const float ik = 1.0f / sqrtf(sk);
    const float iv = 1.0f / sqrtf(sv2);

    float* gq = g_q + (size_t)h * Nn * HD + (size_t)n * HD;
    float* gk = g_k + (size_t)h * Nn * HD + (size_t)n * HD;
    float* gv = g_vn + (size_t)n * Cc + h * HD;
    #pragma unroll
    for (int r = 0; r < 4; r++) {
        const int d = (dg + 8 * r) * 4;
        *reinterpret_cast<float4*>(gq + d) =
            make_float4(qv[r].x*iq, qv[r].y*iq, qv[r].z*iq, qv[r].w*iq);
        *reinterpret_cast<float4*>(gk + d) =
            make_float4(kv[r].x*ik, kv[r].y*ik, kv[r].z*ik, kv[r].w*ik);
        *reinterpret_cast<float4*>(gv + d) =
            make_float4(vv[r].x*iv, vv[r].y*iv, vv[r].z*iv, vv[r].w*iv);
        float* s = sv + nl * 132 + d;
        s[0] = vv[r].x; s[1] = vv[r].y; s[2] = vv[r].z; s[3] = vv[r].w;
    }
    __syncthreads();

    const int w = tid >> 5, lane = tid & 31;
    #pragma unroll
    for (int it = 0; it < 4; it++) {
        const int d = w * 16 + it * 4 + (lane >> 3);
        const int n4 = (lane & 7) * 4;
        float4 o;
        o.x = sv[(n4 + 0) * 132 + d];
        o.y = sv[(n4 + 1) * 132 + d];
        o.z = sv[(n4 + 2) * 132 + d];
        o.w = sv[(n4 + 3) * 132 + d];
        *reinterpret_cast<float4*>(
            g_vT + (size_t)(h * HD + d) * Nn + nb * 32 + n4) = o;
    }
}

// ---------------- combine split-K partials + copy x_ori (fused) ----------------
__global__ __launch_bounds__(256) void combine_kernel(float* __restrict__ out)
{
    int idx = blockIdx.x * 256 + threadIdx.x;
    if (idx >= Nn * Cc / 4) return;
    const int n = idx >> 8, c4 = idx & 255;
    const int h = c4 >> 5, d4 = c4 & 31;
    const float4* p = reinterpret_cast<const float4*>(g_part);
    const size_t st = (size_t)Nn * 32;
    const size_t b = ((size_t)(h * 2) * Nn + n) * 32 + d4;
    float4 a0 = p[b], a1 = p[b + st];
    const float s = 1.f / g_rowsum[h * Nn + n];
    *reinterpret_cast<float4*>(out + (size_t)n * (2 * Cc) + h * 128 + d4 * 4) =
        make_float4((a0.x + a1.x) * s, (a0.y + a1.y) * s,
                    (a0.z + a1.z) * s, (a0.w + a1.w) * s);
    float4 v = *reinterpret_cast<const float4*>(
        &g_qkv[(size_t)n * (3 * Cc) + 2 * Cc + h * 128 + d4 * 4]);
    *reinterpret_cast<float4*>(out + (size_t)n * (2 * Cc) + Cc + h * 128 + d4 * 4) = v;
}

// ---------------- simround2 merged: e in registers, single epk read ----------------
__global__ __launch_bounds__(256) void simr2_merged(float* __restrict__ out)
{
    const int blk = blockIdx.x;
    const int rowBlk = blk >> 3, m = blk & 7;
    const int tid = threadIdx.x;
    const int gg = tid >> 5;
    const int lane = tid & 31;
    const int i0 = blk * 16 + gg;
    const int i1 = i0 + 8;
    const int ubase = m * 32 + gg * 4;
    __shared__ float sinv[16];

    float irs0[8], irs1[8];
    #pragma unroll
    for (int h = 0; h < 8; h++) {
        irs0[h] = 1.f / g_rowsum[h * Nn + i0];
        irs1[h] = 1.f / g_rowsum[h * Nn + i1];
    }

    float e0r[64], e1r[64];
    float msum0 = 0.f, msum1 = 0.f;
    #pragma unroll
    for (int kt = 0; kt < 4; kt++) {
        const int kb = lane + kt * 32;
        float a0[16], a1[16];
        #pragma unroll
        for (int p = 0; p < 16; p++) { a0[p] = 0.f; a1[p] = 0.f; }
        #pragma unroll
        for (int h = 0; h < 8; h++) {
            const uint4* blob = g_epk + ((size_t)((h * 16 + rowBlk) * 128 + kb)) * 768;
            const float w0 = irs0[h], w1 = irs1[h];
            #pragma unroll
            for (int t = 0; t < 4; t++) {
                uint4 H = blob[ubase + t];
                a0[t*2+0]   += blo(H.x) * w0;
                a0[t*2+1]   += bhi(H.x) * w0;
                a1[t*2+0]   += blo(H.y) * w1;
                a1[t*2+1]   += bhi(H.y) * w1;
                a0[8+t*2+0] += blo(H.z) * w0;
                a0[8+t*2+1] += bhi(H.z) * w0;
                a1[8+t*2+0] += blo(H.w) * w1;
                a1[8+t*2+1] += bhi(H.w) * w1;
            }
        }
        const int j0 = kb * 16;
        uint4 mv0 = *reinterpret_cast<const uint4*>(g_mask + (size_t)i0 * Nn + j0);
        uint4 mv1 = *reinterpret_cast<const uint4*>(g_mask + (size_t)i1 * Nn + j0);
        const uint8_t* mb0 = reinterpret_cast<const uint8_t*>(&mv0);
        const uint8_t* mb1 = reinterpret_cast<const uint8_t*>(&mv1);
        #pragma unroll
        for (int p = 0; p < 16; p++) {
            float e0 = __expf(a0[p] * 0.125f);
            float e1 = __expf(a1[p] * 0.125f);
            e0r[kt * 16 + p] = e0;
            e1r[kt * 16 + p] = e1;
            if (mb0[p]) msum0 += e0;
            if (mb1[p]) msum1 += e1;
        }
    }
    #pragma unroll
    for (int o = 16; o > 0; o >>= 1) {
        msum0 += __shfl_xor_sync(0xffffffffu, msum0, o);
        msum1 += __shfl_xor_sync(0xffffffffu, msum1, o);
    }
    if (lane == 0) { sinv[gg] = 1.f / msum0; sinv[8 + gg] = 1.f / msum1; }
    __syncthreads();
    const float inv0 = sinv[gg], inv1 = sinv[8 + gg];

    #pragma unroll
    for (int kt = 0; kt < 4; kt++) {
        const int j0 = (lane + kt * 32) * 16;
        uint4 mv0 = *reinterpret_cast<const uint4*>(g_mask + (size_t)i0 * Nn + j0);
        uint4 mv1 = *reinterpret_cast<const uint4*>(g_mask + (size_t)i1 * Nn + j0);
        const uint8_t* mb0 = reinterpret_cast<const uint8_t*>(&mv0);
        const uint8_t* mb1 = reinterpret_cast<const uint8_t*>(&mv1);
        float* d0 = out + (size_t)i0 * Nn + j0;
        float* d1 = out + (size_t)i1 * Nn + j0;
        #pragma unroll
        for (int q = 0; q < 4; q++) {
            float4 o0, o1;
            o0.x = mb0[q*4+0] ? e0r[kt*16 + q*4+0] * inv0 : 0.f;
            o0.y = mb0[q*4+1] ? e0r[kt*16 + q*4+1] * inv0 : 0.f;
            o0.z = mb0[q*4+2] ? e0r[kt*16 + q*4+2] * inv0 : 0.f;
            o0.w = mb0[q*4+3] ? e0r[kt*16 + q*4+3] * inv0 : 0.f;
            o1.x = mb1[q*4+0] ? e1r[kt*16 + q*4+0] * inv1 : 0.f;
            o1.y = mb1[q*4+1] ? e1r[kt*16 + q*4+1] * inv1 : 0.f;
            o1.z = mb1[q*4+2] ? e1r[kt*16 + q*4+2] * inv1 : 0.f;
            o1.w = mb1[q*4+3] ? e1r[kt*16 + q*4+3] * inv1 : 0.f;
            *reinterpret_cast<float4*>(d0 + q * 4) = o0;
            *reinterpret_cast<float4*>(d1 + q * 4) = o1;
        }
    }
}

// ---------------- host launcher ----------------
extern "C" void kernel_launch(void* const* d_in, const int* in_sizes, int n_in,
                              void* d_out, int out_size)
{
    const float* x   = (const float*)d_in[0];
    const float* cls = (const float*)d_in[1];
    const float* W   = (const float*)d_in[3];
    float* out = (float*)d_out;

    float *p_qkv, *p_q, *p_k, *p_vn, *p_vT, *p_rs, *p_part;
    uint4 *p_xp, *p_Wp, *p_qp, *p_kp, *p_vnpA, *p_vnpB, *p_vTp, *p_epk;
    uint8_t* p_mask;
    cudaGetSymbolAddress((void**)&p_qkv, g_qkv);
    cudaGetSymbolAddress((void**)&p_q, g_q);
    cudaGetSymbolAddress((void**)&p_k, g_k);
    cudaGetSymbolAddress((void**)&p_vn, g_vn);
    cudaGetSymbolAddress((void**)&p_vT, g_vT);
    cudaGetSymbolAddress((void**)&p_rs, g_rowsum);
    cudaGetSymbolAddress((void**)&p_part, g_part);
    cudaGetSymbolAddress((void**)&p_xp, g_xp);
    cudaGetSymbolAddress((void**)&p_Wp, g_Wp);
    cudaGetSymbolAddress((void**)&p_qp, g_qp);
    cudaGetSymbolAddress((void**)&p_kp, g_kp);
    cudaGetSymbolAddress((void**)&p_vnpA, g_vnpA);
    cudaGetSymbolAddress((void**)&p_vnpB, g_vnpB);
    cudaGetSymbolAddress((void**)&p_vTp, g_vTp);
    cudaGetSymbolAddress((void**)&p_epk, g_epk);
    cudaGetSymbolAddress((void**)&p_mask, g_mask);

    // pack x, W (2-term)
    pack_a<2><<<dim3(64, 16, 1), 256>>>(x, Cc, 0, p_xp, 64);
    pack_b<2><<<dim3(64, 24, 1), 256>>>(W, Cc, 0, p_Wp, 64);

    // 1. qkv = x @ W^T (3 products)
    gemm_pk<0, 3><<<dim3(24, 16, 1), 256>>>(p_xp, p_Wp, 64, 64, 64, 16, 24, 0,
                                            p_qkv, 3 * Cc, 0, nullptr, nullptr, nullptr, nullptr);

    // 2. normalize
    normalize_kernel<<<dim3(64, 8), 256>>>();

    // 3. pack q, k (2-term), vn A/B + vT (hi only)
    pack_a<2><<<dim3(8, 16, 8), 256>>>(p_q, HD, (long long)Nn * HD, p_qp, 8);
    pack_b<2><<<dim3(8, 16, 8), 256>>>(p_k, HD, (long long)Nn * HD, p_kp, 8);
    pack_a<1><<<dim3(64, 16, 1), 256>>>(p_vn, Cc, 0, p_vnpA, 64);
    pack_b<1><<<dim3(64, 16, 1), 256>>>(p_vn, Cc, 0, p_vnpB, 64);
    pack_b<1><<<dim3(128, 1, 8), 256>>>(p_vT, Nn, (long long)HD * Nn, p_vTp, 128);

    // 4. sim mask (symmetric upper-triangle, 1 product)
    gemm_pk<3, 1><<<dim3(136, 1, 1), 256>>>(p_vnpA, p_vnpB, 64, 64, 64, 16, 16, 0,
                                            nullptr, 0, 0, nullptr, nullptr, nullptr, p_mask);

    // 5. logits + fused masked-exp -> packed e (hi only) + rowsums (3 products)
    cudaMemsetAsync(p_rs, 0, Hh * Nn * sizeof(float));
    gemm_pk<2, 3><<<dim3(16, 16, 8), 256>>>(p_qp, p_kp, 8, 8, 8, 16, 16, 0,
                                            nullptr, 0, 0, cls, p_epk, p_rs, nullptr);

    // 6. attn@V split-K x2 (1 product: e_hi * v_hi)
    gemm_pk<0, 1><<<dim3(1, 16, 16), 256>>>(p_epk, p_vTp, 64, 128, 128, 16, 1, 1,
                                            p_part, HD, (long long)Nn * HD,
                                            nullptr, nullptr, nullptr, nullptr);

    // 7. combine partials / rowsum + x_ori copy (fused)
    combine_kernel<<<(Nn * Cc / 4 + 255) / 256, 256>>>(out);

    // 8. sim_round2 (single merged kernel, e register-resident)
    simr2_merged<<<128, 256>>>(out + (size_t)Nn * 2 * Cc);
}

// round 13
// speedup vs baseline: 1.5630x; 1.0671x over previous
#include <cuda_runtime.h>
#include <math.h>
#include <stdint.h>

#define Nn 2048
#define Cc 1024
#define Hh 8
#define HD 128
#define SCALE_F 25.0f

// ---------------- scratch ----------------
__device__ float g_qkv[Nn * 3 * Cc];
__device__ float g_q[Hh * Nn * HD];
__device__ float g_k[Hh * Nn * HD];
__device__ float g_vn[Nn * Cc];
__device__ float g_vT[Hh * HD * Nn];
__device__ float g_rowsum[Hh * Nn];
__device__ float g_part[(size_t)16 * Nn * HD];
__device__ uint8_t g_mask[(size_t)Nn * Nn];

// packed bf16 fragment images; tile = 128 rows x 16 k (stride 768 uint4)
__device__ uint4 g_xp [(size_t)16 * 64 * 768];
__device__ uint4 g_Wp [(size_t)24 * 64 * 768];
__device__ uint4 g_qp [(size_t)8 * 16 * 8 * 768];
__device__ uint4 g_kp [(size_t)8 * 16 * 8 * 768];
__device__ uint4 g_vnpA[(size_t)16 * 64 * 768];
__device__ uint4 g_vnpB[(size_t)16 * 64 * 768];
__device__ uint4 g_vTp[(size_t)8 * 128 * 768];
__device__ uint4 g_epk[(size_t)8 * 16 * 128 * 768];   // hi plane only used

// ---------------- helpers ----------------
__device__ __forceinline__ uint32_t packbf(float x, float y)
{
    uint32_t h;
    asm("cvt.rn.bf16x2.f32 %0, %1, %2;" : "=r"(h) : "f"(y), "f"(x));
    return h;
}
__device__ __forceinline__ float blo(uint32_t u) { return __uint_as_float(u << 16); }
__device__ __forceinline__ float bhi(uint32_t u) { return __uint_as_float(u & 0xFFFF0000u); }
__device__ __forceinline__ void split2(float x, float y, uint32_t& s0, uint32_t& s1)
{
    s0 = packbf(x, y);
    s1 = packbf(x - blo(s0), y - bhi(s0));
}

__device__ __forceinline__ void mma_bf16(float c[4], const uint32_t a[4],
                                         uint32_t b0, uint32_t b1)
{
    asm volatile(
        "mma.sync.aligned.m16n8k16.row.col.f32.bf16.bf16.f32 "
        "{%0,%1,%2,%3}, {%4,%5,%6,%7}, {%8,%9}, {%0,%1,%2,%3};"
        : "+f"(c[0]), "+f"(c[1]), "+f"(c[2]), "+f"(c[3])
        : "r"(a[0]), "r"(a[1]), "r"(a[2]), "r"(a[3]), "r"(b0), "r"(b1));
}

__device__ __forceinline__ void cpa16(void* smem, const void* gmem)
{
    uint32_t s = (uint32_t)__cvta_generic_to_shared(smem);
    asm volatile("cp.async.cg.shared.global [%0], [%1], 16;" :: "r"(s), "l"(gmem));
}
#define CP_COMMIT() asm volatile("cp.async.commit_group;")
#define CP_WAIT1()  asm volatile("cp.async.wait_group 1;")
#define CP_WAIT0()  asm volatile("cp.async.wait_group 0;")

// ---------------- pack kernels (TERMS = planes written) ----------------
template<int TERMS>
__global__ __launch_bounds__(256) void pack_a(
    const float* __restrict__ src, int lda, long long zstride, uint4* __restrict__ dst, int nKb)
{
    const int kb = blockIdx.x, rb = blockIdx.y, z = blockIdx.z;
    src += (long long)z * zstride;
    uint32_t* tb = (uint32_t*)(dst + ((size_t)(z * gridDim.y + rb) * nKb + kb) * 768);
    const int tid = threadIdx.x;
    #pragma unroll
    for (int t = 0; t < 2; t++) {
        int idx = tid + t * 256;
        int row = idx >> 2, k4 = (idx & 3) * 4;
        float4 v = *reinterpret_cast<const float4*>(
            &src[(long long)(rb * 128 + row) * lda + kb * 16 + k4]);
        int m = row >> 4, r16 = row & 15, g = r16 & 7, half = r16 >> 3;
        int tt = (k4 & 7) >> 1, reg = half + 2 * (k4 >> 3);
        int base = (m * 32 + g * 4 + tt) * 4 + reg;
        uint32_t s0, s1;
        split2(v.x, v.y, s0, s1);
        tb[base] = s0;
        if (TERMS >= 2) tb[1024 + base] = s1;
        split2(v.z, v.w, s0, s1);
        tb[base + 4] = s0;
        if (TERMS >= 2) tb[1024 + base + 4] = s1;
    }
}

template<int TERMS>
__global__ __launch_bounds__(256) void pack_b(
    const float* __restrict__ src, int ldb, long long zstride, uint4* __restrict__ dst, int nKb)
{
    const int kb = blockIdx.x, rb = blockIdx.y, z = blockIdx.z;
    src += (long long)z * zstride;
    uint32_t* tb = (uint32_t*)(dst + ((size_t)(z * gridDim.y + rb) * nKb + kb) * 768);
    const int tid = threadIdx.x;
    #pragma unroll
    for (int t = 0; t < 2; t++) {
        int idx = tid + t * 256;
        int row = idx >> 2, k4 = (idx & 3) * 4;
        float4 v = *reinterpret_cast<const float4*>(
            &src[(long long)(rb * 128 + row) * ldb + kb * 16 + k4]);
        int nb = row >> 3, g = row & 7;
        int tt = (k4 & 7) >> 1, reg = k4 >> 3;
        int base = (nb * 32 + g * 4 + tt) * 2 + reg;
        uint32_t s0, s1;
        split2(v.x, v.y, s0, s1);
        tb[base] = s0;
        if (TERMS >= 2) tb[1024 + base] = s1;
        split2(v.z, v.w, s0, s1);
        tb[base + 2] = s0;
        if (TERMS >= 2) tb[1024 + base + 2] = s1;
    }
}

// ---------------- packed bf16 GEMM, cp.async 3-stage, PROD-gated plane loads ----------------
template<int MODE, int PROD>
__global__ __launch_bounds__(256, 2) void gemm_pk(
    const uint4* __restrict__ At, const uint4* __restrict__ Bt,
    int nK, int nKtotA, int nKtotB, int nRbA, int nRbB, int kzBits,
    float* __restrict__ C, int ldc, long long cZ,
    const float* __restrict__ cls, uint4* __restrict__ epk,
    float* __restrict__ rsOut, uint8_t* __restrict__ maskOut)
{
    int bx, by;
    if (MODE == 3) {
        int r = blockIdx.x, row = 0;
        while (r >= 16 - row) { r -= 16 - row; row++; }
        by = row; bx = row + r;
    } else { bx = blockIdx.x; by = blockIdx.y; }

    const int hz = blockIdx.z >> kzBits;
    const int kz = blockIdx.z & ((1 << kzBits) - 1);
    const uint4* Ab = At + ((size_t)(hz * nRbA + by) * nKtotA + (size_t)kz * nK) * 768;
    const uint4* Bb = Bt + ((size_t)(hz * nRbB + bx) * nKtotB + (size_t)kz * nK) * 768;

    __shared__ uint4 smA[3][512], smB[3][512];

    const int tid = threadIdx.x, lane = tid & 31, wid = tid >> 5;
    const int wm = wid >> 1, wn = wid & 1;

    float acc[2][8][4];
    #pragma unroll
    for (int mt = 0; mt < 2; mt++)
        #pragma unroll
        for (int nt = 0; nt < 8; nt++)
            #pragma unroll
            for (int r = 0; r < 4; r++) acc[mt][nt][r] = 0.f;

    auto stage_load = [&](int kb, int st) {
        const uint4* An = Ab + (size_t)kb * 768;
        const uint4* Bn = Bb + (size_t)kb * 768;
        cpa16(&smA[st][tid], An + tid);
        if (PROD >= 2) cpa16(&smA[st][256 + tid], An + 256 + tid);
        cpa16(&smB[st][tid], Bn + tid);
        if (PROD >= 3) cpa16(&smB[st][256 + tid], Bn + 256 + tid);
        CP_COMMIT();
    };

    stage_load(0, 0);
    if (nK > 1) stage_load(1, 1);

    int cur = 0;
    for (int kb = 0; kb < nK; kb++) {
        if (kb + 2 <= nK) CP_WAIT1(); else CP_WAIT0();
        __syncthreads();

        uint32_t af[2][2][4];
        #pragma unroll
        for (int mt = 0; mt < 2; mt++)
            *reinterpret_cast<uint4*>(af[0][mt]) =
                smA[cur][(wm * 2 + mt) * 32 + lane];
        if (PROD >= 2) {
            #pragma unroll
            for (int mt = 0; mt < 2; mt++)
                *reinterpret_cast<uint4*>(af[1][mt]) =
                    smA[cur][256 + (wm * 2 + mt) * 32 + lane];
        }

        const uint2* B2 = reinterpret_cast<const uint2*>(smB[cur]);
        uint2 b0[8];
        #pragma unroll
        for (int nt = 0; nt < 8; nt++) b0[nt] = B2[(wn * 8 + nt) * 32 + lane];
        #pragma unroll
        for (int nt = 0; nt < 8; nt++)
            #pragma unroll
            for (int mt = 0; mt < 2; mt++)
                mma_bf16(acc[mt][nt], af[0][mt], b0[nt].x, b0[nt].y);   // hi*hi
        if (PROD >= 2) {
            #pragma unroll
            for (int nt = 0; nt < 8; nt++)
                #pragma unroll
                for (int mt = 0; mt < 2; mt++)
                    mma_bf16(acc[mt][nt], af[1][mt], b0[nt].x, b0[nt].y);  // lo*hi
        }
        if (PROD >= 3) {
            uint2 b1[8];
            #pragma unroll
            for (int nt = 0; nt < 8; nt++) b1[nt] = B2[512 + (wn * 8 + nt) * 32 + lane];
            #pragma unroll
            for (int nt = 0; nt < 8; nt++)
                #pragma unroll
                for (int mt = 0; mt < 2; mt++)
                    mma_bf16(acc[mt][nt], af[0][mt], b1[nt].x, b1[nt].y);  // hi*lo
        }

        if (kb + 2 < nK) stage_load(kb + 2, (kb + 2) % 3);
        else CP_COMMIT();
        cur = (cur + 1 == 3) ? 0 : cur + 1;
    }

    const int g = lane >> 2, tq = lane & 3;

    if (MODE == 2) {
        #pragma unroll
        for (int mt = 0; mt < 2; mt++) {
            const int m = wm * 2 + mt;
            const int i0 = by * 128 + m * 16 + g;
            const int i1 = i0 + 8;
            const float tha = cls[i0] - 0.1f;
            const float thb = cls[i1] - 0.1f;
            float rs0 = 0.f, rs1 = 0.f;
            const int baseW = (m * 32 + g * 4 + tq) * 4;
            #pragma unroll
            for (int ntp = 0; ntp < 4; ntp++) {
                uint32_t hw[4];
                #pragma unroll
                for (int sub = 0; sub < 2; sub++) {
                    const int nt = ntp * 2 + sub;
                    const int j = bx * 128 + wn * 64 + nt * 8 + tq * 2;
                    const float cj0 = cls[j], cj1 = cls[j + 1];
                    float e00 = (cj0 > tha) ? __expf(acc[mt][nt][0] * cj0) : 1.f;
                    float e01 = (cj1 > tha) ? __expf(acc[mt][nt][1] * cj1) : 1.f;
                    float e10 = (cj0 > thb) ? __expf(acc[mt][nt][2] * cj0) : 1.f;
                    float e11 = (cj1 > thb) ? __expf(acc[mt][nt][3] * cj1) : 1.f;
                    rs0 += e00 + e01;
                    rs1 += e10 + e11;
                    hw[sub * 2]     = packbf(e00, e01);
                    hw[sub * 2 + 1] = packbf(e10, e11);
                }
                const size_t tIdx = (size_t)(hz * 16 + by) * 128 + bx * 8 + wn * 4 + ntp;
                uint32_t* tb = (uint32_t*)(epk + tIdx * 768);
                *reinterpret_cast<uint4*>(&tb[baseW]) =
                    make_uint4(hw[0], hw[1], hw[2], hw[3]);
            }
            rs0 += __shfl_xor_sync(0xffffffffu, rs0, 1);
            rs0 += __shfl_xor_sync(0xffffffffu, rs0, 2);
            rs1 += __shfl_xor_sync(0xffffffffu, rs1, 1);
            rs1 += __shfl_xor_sync(0xffffffffu, rs1, 2);
            if (tq == 0) {
                atomicAdd(&rsOut[hz * Nn + i0], rs0);
                atomicAdd(&rsOut[hz * Nn + i1], rs1);
            }
        }
    } else if (MODE == 3) {
        __syncthreads();
        uint8_t* sb = reinterpret_cast<uint8_t*>(smA);
        #pragma unroll
        for (int mt = 0; mt < 2; mt++)
            #pragma unroll
            for (int nt = 0; nt < 8; nt++) {
                const int r0 = wm * 32 + mt * 16 + g;
                const int c0 = wn * 64 + nt * 8 + tq * 2;
                sb[r0 * 144 + c0]           = acc[mt][nt][0] > 6.f;
                sb[r0 * 144 + c0 + 1]       = acc[mt][nt][1] > 6.f;
                sb[(r0 + 8) * 144 + c0]     = acc[mt][nt][2] > 6.f;
                sb[(r0 + 8) * 144 + c0 + 1] = acc[mt][nt][3] > 6.f;
            }
        __syncthreads();
        const int r = tid >> 1, hf = tid & 1;
        {
            const uint8_t* srcp = sb + r * 144 + hf * 64;
            uint4 v0 = *reinterpret_cast<const uint4*>(srcp);
            uint4 v1 = *reinterpret_cast<const uint4*>(srcp + 16);
            uint4 v2 = *reinterpret_cast<const uint4*>(srcp + 32);
            uint4 v3 = *reinterpret_cast<const uint4*>(srcp + 48);
            uint8_t* dst = maskOut + (size_t)(by * 128 + r) * Nn + bx * 128 + hf * 64;
            *reinterpret_cast<uint4*>(dst)      = v0;
            *reinterpret_cast<uint4*>(dst + 16) = v1;
            *reinterpret_cast<uint4*>(dst + 32) = v2;
            *reinterpret_cast<uint4*>(dst + 48) = v3;
        }
        {
            uint32_t wv[16];
            #pragma unroll
            for (int q = 0; q < 16; q++) {
                uint32_t b0 = sb[(hf * 64 + q * 4 + 0) * 144 + r];
                uint32_t b1 = sb[(hf * 64 + q * 4 + 1) * 144 + r];
                uint32_t b2 = sb[(hf * 64 + q * 4 + 2) * 144 + r];
                uint32_t b3 = sb[(hf * 64 + q * 4 + 3) * 144 + r];
                wv[q] = b0 | (b1 << 8) | (b2 << 16) | (b3 << 24);
            }
            uint8_t* dst = maskOut + (size_t)(bx * 128 + r) * Nn + by * 128 + hf * 64;
            #pragma unroll
            for (int q = 0; q < 4; q++)
                *reinterpret_cast<uint4*>(dst + q * 16) =
                    make_uint4(wv[q*4], wv[q*4+1], wv[q*4+2], wv[q*4+3]);
        }
    } else {
        float* Cz = C + (long long)blockIdx.z * cZ;
        #pragma unroll
        for (int mt = 0; mt < 2; mt++) {
            const int row0 = by * 128 + wm * 32 + mt * 16 + g;
            #pragma unroll
            for (int nt = 0; nt < 8; nt++) {
                const int col = bx * 128 + wn * 64 + nt * 8 + tq * 2;
                *reinterpret_cast<float2*>(&Cz[(long long)row0 * ldc + col]) =
                    make_float2(acc[mt][nt][0], acc[mt][nt][1]);
                *reinterpret_cast<float2*>(&Cz[(long long)(row0 + 8) * ldc + col]) =
                    make_float2(acc[mt][nt][2], acc[mt][nt][3]);
            }
        }
    }
}

// ---------------- normalize: block = (32 tokens, 1 head), smem transpose for vT ----------------
__global__ __launch_bounds__(256) void normalize_kernel()
{
    const int nb = blockIdx.x;
    const int h  = blockIdx.y;
    const int tid = threadIdx.x;
    const int nl = tid >> 3;
    const int dg = tid & 7;
    const int n = nb * 32 + nl;

    __shared__ float sv[32 * 132];

    const float* base = g_qkv + (size_t)n * (3 * Cc) + h * HD;

    float4 qv[4], kv[4], vv[4];
    #pragma unroll
    for (int r = 0; r < 4; r++) {
        const int d = (dg + 8 * r) * 4;
        qv[r] = *reinterpret_cast<const float4*>(base + d);
        kv[r] = *reinterpret_cast<const float4*>(base + Cc + d);
        vv[r] = *reinterpret_cast<const float4*>(base + 2 * Cc + d);
    }
    float sq = 0.f, sk = 0.f, sv2 = 0.f;
    #pragma unroll
    for (int r = 0; r < 4; r++) {
        sq  += qv[r].x*qv[r].x + qv[r].y*qv[r].y + qv[r].z*qv[r].z + qv[r].w*qv[r].w;
        sk  += kv[r].x*kv[r].x + kv[r].y*kv[r].y + kv[r].z*kv[r].z + kv[r].w*kv[r].w;
        sv2 += vv[r].x*vv[r].x + vv[r].y*vv[r].y + vv[r].z*vv[r].z + vv[r].w*vv[r].w;
    }
    #pragma unroll
    for (int o = 1; o < 8; o <<= 1) {
        sq  += __shfl_xor_sync(0xffffffffu, sq, o);
        sk  += __shfl_xor_sync(0xffffffffu, sk, o);
        sv2 += __shfl_xor_sync(0xffffffffu, sv2, o);
    }
    const float iq = SCALE_F / sqrtf(sq);
    const float ik = 1.0f / sqrtf(sk);
    const float iv = 1.0f / sqrtf(sv2);

    float* gq = g_q + (size_t)h * Nn * HD + (size_t)n * HD;
    float* gk = g_k + (size_t)h * Nn * HD + (size_t)n * HD;
    float* gv = g_vn + (size_t)n * Cc + h * HD;
    #pragma unroll
    for (int r = 0; r < 4; r++) {
        const int d = (dg + 8 * r) * 4;
        *reinterpret_cast<float4*>(gq + d) =
            make_float4(qv[r].x*iq, qv[r].y*iq, qv[r].z*iq, qv[r].w*iq);
        *reinterpret_cast<float4*>(gk + d) =
            make_float4(kv[r].x*ik, kv[r].y*ik, kv[r].z*ik, kv[r].w*ik);
        *reinterpret_cast<float4*>(gv + d) =
            make_float4(vv[r].x*iv, vv[r].y*iv, vv[r].z*iv, vv[r].w*iv);
        float* s = sv + nl * 132 + d;
        s[0] = vv[r].x; s[1] = vv[r].y; s[2] = vv[r].z; s[3] = vv[r].w;
    }
    __syncthreads();

    const int w = tid >> 5, lane = tid & 31;
    #pragma unroll
    for (int it = 0; it < 4; it++) {
        const int d = w * 16 + it * 4 + (lane >> 3);
        const int n4 = (lane & 7) * 4;
        float4 o;
        o.x = sv[(n4 + 0) * 132 + d];
        o.y = sv[(n4 + 1) * 132 + d];
        o.z = sv[(n4 + 2) * 132 + d];
        o.w = sv[(n4 + 3) * 132 + d];
        *reinterpret_cast<float4*>(
            g_vT + (size_t)(h * HD + d) * Nn + nb * 32 + n4) = o;
    }
}

// ---------------- combine split-K partials + copy x_ori (fused) ----------------
__global__ __launch_bounds__(256) void combine_kernel(float* __restrict__ out)
{
    int idx = blockIdx.x * 256 + threadIdx.x;
    if (idx >= Nn * Cc / 4) return;
    const int n = idx >> 8, c4 = idx & 255;
    const int h = c4 >> 5, d4 = c4 & 31;
    const float4* p = reinterpret_cast<const float4*>(g_part);
    const size_t st = (size_t)Nn * 32;
    const size_t b = ((size_t)(h * 2) * Nn + n) * 32 + d4;
    float4 a0 = p[b], a1 = p[b + st];
    const float s = 1.f / g_rowsum[h * Nn + n];
    *reinterpret_cast<float4*>(out + (size_t)n * (2 * Cc) + h * 128 + d4 * 4) =
        make_float4((a0.x + a1.x) * s, (a0.y + a1.y) * s,
                    (a0.z + a1.z) * s, (a0.w + a1.w) * s);
    float4 v = *reinterpret_cast<const float4*>(
        &g_qkv[(size_t)n * (3 * Cc) + 2 * Cc + h * 128 + d4 * 4]);
    *reinterpret_cast<float4*>(out + (size_t)n * (2 * Cc) + Cc + h * 128 + d4 * 4) = v;
}

// ---------------- simround2 merged: e in registers, single epk read ----------------
__global__ __launch_bounds__(256) void simr2_merged(float* __restrict__ out)
{
    const int blk = blockIdx.x;
    const int rowBlk = blk >> 3, m = blk & 7;
    const int tid = threadIdx.x;
    const int gg = tid >> 5;
    const int lane = tid & 31;
    const int i0 = blk * 16 + gg;
    const int i1 = i0 + 8;
    const int ubase = m * 32 + gg * 4;
    __shared__ float sinv[16];

    float irs0[8], irs1[8];
    #pragma unroll
    for (int h = 0; h < 8; h++) {
        irs0[h] = 1.f / g_rowsum[h * Nn + i0];
        irs1[h] = 1.f / g_rowsum[h * Nn + i1];
    }

    float e0r[64], e1r[64];
    float msum0 = 0.f, msum1 = 0.f;
    #pragma unroll
    for (int kt = 0; kt < 4; kt++) {
        const int kb = lane + kt * 32;
        float a0[16], a1[16];
        #pragma unroll
        for (int p = 0; p < 16; p++) { a0[p] = 0.f; a1[p] = 0.f; }
        #pragma unroll
        for (int h = 0; h < 8; h++) {
            const uint4* blob = g_epk + ((size_t)((h * 16 + rowBlk) * 128 + kb)) * 768;
            const float w0 = irs0[h], w1 = irs1[h];
            #pragma unroll
            for (int t = 0; t < 4; t++) {
                uint4 H = blob[ubase + t];
                a0[t*2+0]   += blo(H.x) * w0;
                a0[t*2+1]   += bhi(H.x) * w0;
                a1[t*2+0]   += blo(H.y) * w1;
                a1[t*2+1]   += bhi(H.y) * w1;
                a0[8+t*2+0] += blo(H.z) * w0;
                a0[8+t*2+1] += bhi(H.z) * w0;
                a1[8+t*2+0] += blo(H.w) * w1;
                a1[8+t*2+1] += bhi(H.w) * w1;
            }
        }
        const int j0 = kb * 16;
        uint4 mv0 = *reinterpret_cast<const uint4*>(g_mask + (size_t)i0 * Nn + j0);
        uint4 mv1 = *reinterpret_cast<const uint4*>(g_mask + (size_t)i1 * Nn + j0);
        const uint8_t* mb0 = reinterpret_cast<const uint8_t*>(&mv0);
        const uint8_t* mb1 = reinterpret_cast<const uint8_t*>(&mv1);
        #pragma unroll
        for (int p = 0; p < 16; p++) {
            float e0 = __expf(a0[p] * 0.125f);
            float e1 = __expf(a1[p] * 0.125f);
            e0r[kt * 16 + p] = e0;
            e1r[kt * 16 + p] = e1;
            if (mb0[p]) msum0 += e0;
            if (mb1[p]) msum1 += e1;
        }
    }
    #pragma unroll
    for (int o = 16; o > 0; o >>= 1) {
        msum0 += __shfl_xor_sync(0xffffffffu, msum0, o);
        msum1 += __shfl_xor_sync(0xffffffffu, msum1, o);
    }
    if (lane == 0) { sinv[gg] = 1.f / msum0; sinv[8 + gg] = 1.f / msum1; }
    __syncthreads();
    const float inv0 = sinv[gg], inv1 = sinv[8 + gg];

    #pragma unroll
    for (int kt = 0; kt < 4; kt++) {
        const int j0 = (lane + kt * 32) * 16;
        uint4 mv0 = *reinterpret_cast<const uint4*>(g_mask + (size_t)i0 * Nn + j0);
        uint4 mv1 = *reinterpret_cast<const uint4*>(g_mask + (size_t)i1 * Nn + j0);
        const uint8_t* mb0 = reinterpret_cast<const uint8_t*>(&mv0);
        const uint8_t* mb1 = reinterpret_cast<const uint8_t*>(&mv1);
        float* d0 = out + (size_t)i0 * Nn + j0;
        float* d1 = out + (size_t)i1 * Nn + j0;
        #pragma unroll
        for (int q = 0; q < 4; q++) {
            float4 o0, o1;
            o0.x = mb0[q*4+0] ? e0r[kt*16 + q*4+0] * inv0 : 0.f;
            o0.y = mb0[q*4+1] ? e0r[kt*16 + q*4+1] * inv0 : 0.f;
            o0.z = mb0[q*4+2] ? e0r[kt*16 + q*4+2] * inv0 : 0.f;
            o0.w = mb0[q*4+3] ? e0r[kt*16 + q*4+3] * inv0 : 0.f;
            o1.x = mb1[q*4+0] ? e1r[kt*16 + q*4+0] * inv1 : 0.f;
            o1.y = mb1[q*4+1] ? e1r[kt*16 + q*4+1] * inv1 : 0.f;
            o1.z = mb1[q*4+2] ? e1r[kt*16 + q*4+2] * inv1 : 0.f;
            o1.w = mb1[q*4+3] ? e1r[kt*16 + q*4+3] * inv1 : 0.f;
            *reinterpret_cast<float4*>(d0 + q * 4) = o0;
            *reinterpret_cast<float4*>(d1 + q * 4) = o1;
        }
    }
}

// ---------------- host launcher (multi-stream fork/join for overlap) ----------------
extern "C" void kernel_launch(void* const* d_in, const int* in_sizes, int n_in,
                              void* d_out, int out_size)
{
    const float* x   = (const float*)d_in[0];
    const float* cls = (const float*)d_in[1];
    const float* W   = (const float*)d_in[3];
    float* out = (float*)d_out;

    float *p_qkv, *p_q, *p_k, *p_vn, *p_vT, *p_rs, *p_part;
    uint4 *p_xp, *p_Wp, *p_qp, *p_kp, *p_vnpA, *p_vnpB, *p_vTp, *p_epk;
    uint8_t* p_mask;
    cudaGetSymbolAddress((void**)&p_qkv, g_qkv);
    cudaGetSymbolAddress((void**)&p_q, g_q);
    cudaGetSymbolAddress((void**)&p_k, g_k);
    cudaGetSymbolAddress((void**)&p_vn, g_vn);
    cudaGetSymbolAddress((void**)&p_vT, g_vT);
    cudaGetSymbolAddress((void**)&p_rs, g_rowsum);
    cudaGetSymbolAddress((void**)&p_part, g_part);
    cudaGetSymbolAddress((void**)&p_xp, g_xp);
    cudaGetSymbolAddress((void**)&p_Wp, g_Wp);
    cudaGetSymbolAddress((void**)&p_qp, g_qp);
    cudaGetSymbolAddress((void**)&p_kp, g_kp);
    cudaGetSymbolAddress((void**)&p_vnpA, g_vnpA);
    cudaGetSymbolAddress((void**)&p_vnpB, g_vnpB);
    cudaGetSymbolAddress((void**)&p_vTp, g_vTp);
    cudaGetSymbolAddress((void**)&p_epk, g_epk);
    cudaGetSymbolAddress((void**)&p_mask, g_mask);

    // one-time side stream + events (created on the uncaptured correctness call)
    static cudaStream_t s1 = nullptr;
    static cudaEvent_t evFork = nullptr, evVtp = nullptr, evLog = nullptr, evEnd = nullptr;
    if (!s1) {
        cudaStreamCreateWithFlags(&s1, cudaStreamNonBlocking);
        cudaEventCreateWithFlags(&evFork, cudaEventDisableTiming);
        cudaEventCreateWithFlags(&evVtp, cudaEventDisableTiming);
        cudaEventCreateWithFlags(&evLog, cudaEventDisableTiming);
        cudaEventCreateWithFlags(&evEnd, cudaEventDisableTiming);
    }

    // ---- main stream (legacy default) ----
    pack_a<2><<<dim3(64, 16, 1), 256>>>(x, Cc, 0, p_xp, 64);
    pack_b<2><<<dim3(64, 24, 1), 256>>>(W, Cc, 0, p_Wp, 64);

    // 1. qkv = x @ W^T (3 products)
    gemm_pk<0, 3><<<dim3(24, 16, 1), 256>>>(p_xp, p_Wp, 64, 64, 64, 16, 24, 0,
                                            p_qkv, 3 * Cc, 0, nullptr, nullptr, nullptr, nullptr);

    // 2. normalize
    normalize_kernel<<<dim3(64, 8), 256>>>();
    cudaEventRecord(evFork, 0);

    // ---- side stream: v-branch (vn/vT packs, sim mask), later simr2 ----
    cudaStreamWaitEvent(s1, evFork, 0);
    pack_a<1><<<dim3(64, 16, 1), 256, 0, s1>>>(p_vn, Cc, 0, p_vnpA, 64);
    pack_b<1><<<dim3(64, 16, 1), 256, 0, s1>>>(p_vn, Cc, 0, p_vnpB, 64);
    pack_b<1><<<dim3(128, 1, 8), 256, 0, s1>>>(p_vT, Nn, (long long)HD * Nn, p_vTp, 128);
    cudaEventRecord(evVtp, s1);
    gemm_pk<3, 1><<<dim3(136, 1, 1), 256, 0, s1>>>(p_vnpA, p_vnpB, 64, 64, 64, 16, 16, 0,
                                                   nullptr, 0, 0, nullptr, nullptr, nullptr, p_mask);

    // ---- main stream: q/k branch ----
    pack_a<2><<<dim3(8, 16, 8), 256>>>(p_q, HD, (long long)Nn * HD, p_qp, 8);
    pack_b<2><<<dim3(8, 16, 8), 256>>>(p_k, HD, (long long)Nn * HD, p_kp, 8);
    cudaMemsetAsync(p_rs, 0, Hh * Nn * sizeof(float));
    gemm_pk<2, 3><<<dim3(16, 16, 8), 256>>>(p_qp, p_kp, 8, 8, 8, 16, 16, 0,
                                            nullptr, 0, 0, cls, p_epk, p_rs, nullptr);
    cudaEventRecord(evLog, 0);

    // side stream: simr2 (needs epk+rowsum from logits; mask from its own order)
    cudaStreamWaitEvent(s1, evLog, 0);
    simr2_merged<<<128, 256, 0, s1>>>(out + (size_t)Nn * 2 * Cc);
    cudaEventRecord(evEnd, s1);

    // main stream: attn@V (needs epk + vTp)
    cudaStreamWaitEvent(0, evVtp, 0);
    gemm_pk<0, 1><<<dim3(1, 16, 16), 256>>>(p_epk, p_vTp, 64, 128, 128, 16, 1, 1,
                                            p_part, HD, (long long)Nn * HD,
                                            nullptr, nullptr, nullptr, nullptr);
    combine_kernel<<<(Nn * Cc / 4 + 255) / 256, 256>>>(out);

    // join side stream back to main before returning
    cudaStreamWaitEvent(0, evEnd, 0);
}

// round 14
// speedup vs baseline: 1.6342x; 1.0455x over previous
#include <cuda_runtime.h>
#include <math.h>
#include <stdint.h>

#define Nn 2048
#define Cc 1024
#define Hh 8
#define HD 128
#define SCALE_F 25.0f

// ---------------- scratch ----------------
__device__ float g_rowsum[Hh * Nn];
__device__ float g_part[(size_t)16 * Nn * HD];
__device__ uint8_t g_mask[(size_t)Nn * Nn];

// packed bf16 fragment images; tile = 128 rows x 16 k (stride 768 uint4)
__device__ uint4 g_xp [(size_t)16 * 64 * 768];
__device__ uint4 g_Wp [(size_t)24 * 64 * 768];
__device__ uint4 g_qp [(size_t)8 * 16 * 8 * 768];
__device__ uint4 g_kp [(size_t)8 * 16 * 8 * 768];
__device__ uint4 g_vnpA[(size_t)16 * 64 * 768];
__device__ uint4 g_vnpB[(size_t)16 * 64 * 768];
__device__ uint4 g_vTp[(size_t)8 * 128 * 768];
__device__ uint4 g_epk[(size_t)8 * 16 * 128 * 768];   // hi plane only used

// ---------------- helpers ----------------
__device__ __forceinline__ uint32_t packbf(float x, float y)
{
    uint32_t h;
    asm("cvt.rn.bf16x2.f32 %0, %1, %2;" : "=r"(h) : "f"(y), "f"(x));
    return h;
}
__device__ __forceinline__ float blo(uint32_t u) { return __uint_as_float(u << 16); }
__device__ __forceinline__ float bhi(uint32_t u) { return __uint_as_float(u & 0xFFFF0000u); }
__device__ __forceinline__ void split2(float x, float y, uint32_t& s0, uint32_t& s1)
{
    s0 = packbf(x, y);
    s1 = packbf(x - blo(s0), y - bhi(s0));
}

__device__ __forceinline__ void mma_bf16(float c[4], const uint32_t a[4],
                                         uint32_t b0, uint32_t b1)
{
    asm volatile(
        "mma.sync.aligned.m16n8k16.row.col.f32.bf16.bf16.f32 "
        "{%0,%1,%2,%3}, {%4,%5,%6,%7}, {%8,%9}, {%0,%1,%2,%3};"
        : "+f"(c[0]), "+f"(c[1]), "+f"(c[2]), "+f"(c[3])
        : "r"(a[0]), "r"(a[1]), "r"(a[2]), "r"(a[3]), "r"(b0), "r"(b1));
}

__device__ __forceinline__ void cpa16(void* smem, const void* gmem)
{
    uint32_t s = (uint32_t)__cvta_generic_to_shared(smem);
    asm volatile("cp.async.cg.shared.global [%0], [%1], 16;" :: "r"(s), "l"(gmem));
}
#define CP_COMMIT() asm volatile("cp.async.commit_group;")
#define CP_WAIT1()  asm volatile("cp.async.wait_group 1;")
#define CP_WAIT0()  asm volatile("cp.async.wait_group 0;")

// ---------------- pack kernels (TERMS = planes written) ----------------
template<int TERMS>
__global__ __launch_bounds__(256) void pack_a(
    const float* __restrict__ src, int lda, long long zstride, uint4* __restrict__ dst, int nKb)
{
    const int kb = blockIdx.x, rb = blockIdx.y, z = blockIdx.z;
    src += (long long)z * zstride;
    uint32_t* tb = (uint32_t*)(dst + ((size_t)(z * gridDim.y + rb) * nKb + kb) * 768);
    const int tid = threadIdx.x;
    #pragma unroll
    for (int t = 0; t < 2; t++) {
        int idx = tid + t * 256;
        int row = idx >> 2, k4 = (idx & 3) * 4;
        float4 v = *reinterpret_cast<const float4*>(
            &src[(long long)(rb * 128 + row) * lda + kb * 16 + k4]);
        int m = row >> 4, r16 = row & 15, g = r16 & 7, half = r16 >> 3;
        int tt = (k4 & 7) >> 1, reg = half + 2 * (k4 >> 3);
        int base = (m * 32 + g * 4 + tt) * 4 + reg;
        uint32_t s0, s1;
        split2(v.x, v.y, s0, s1);
        tb[base] = s0;
        if (TERMS >= 2) tb[1024 + base] = s1;
        split2(v.z, v.w, s0, s1);
        tb[base + 4] = s0;
        if (TERMS >= 2) tb[1024 + base + 4] = s1;
    }
}

template<int TERMS>
__global__ __launch_bounds__(256) void pack_b(
    const float* __restrict__ src, int ldb, long long zstride, uint4* __restrict__ dst, int nKb)
{
    const int kb = blockIdx.x, rb = blockIdx.y, z = blockIdx.z;
    src += (long long)z * zstride;
    uint32_t* tb = (uint32_t*)(dst + ((size_t)(z * gridDim.y + rb) * nKb + kb) * 768);
    const int tid = threadIdx.x;
    #pragma unroll
    for (int t = 0; t < 2; t++) {
        int idx = tid + t * 256;
        int row = idx >> 2, k4 = (idx & 3) * 4;
        float4 v = *reinterpret_cast<const float4*>(
            &src[(long long)(rb * 128 + row) * ldb + kb * 16 + k4]);
        int nb = row >> 3, g = row & 7;
        int tt = (k4 & 7) >> 1, reg = k4 >> 3;
        int base = (nb * 32 + g * 4 + tt) * 2 + reg;
        uint32_t s0, s1;
        split2(v.x, v.y, s0, s1);
        tb[base] = s0;
        if (TERMS >= 2) tb[1024 + base] = s1;
        split2(v.z, v.w, s0, s1);
        tb[base + 2] = s0;
        if (TERMS >= 2) tb[1024 + base + 2] = s1;
    }
}

// ---------------- pack vT from x_ori region of out (transpose gather) ----------------
__global__ __launch_bounds__(256) void pack_vT(
    const float* __restrict__ xori, uint4* __restrict__ dst)
{
    const int kb = blockIdx.x;    // 16-token tile
    const int h  = blockIdx.y;
    const int tid = threadIdx.x;
    __shared__ float sv[16][132];
    {
        const int tok = tid >> 4;
        const int dq  = (tid & 15) * 8;
        const float* src = xori + (size_t)(kb * 16 + tok) * (2 * Cc) + Cc + h * HD + dq;
        float4 a = *reinterpret_cast<const float4*>(src);
        float4 b = *reinterpret_cast<const float4*>(src + 4);
        sv[tok][dq + 0] = a.x; sv[tok][dq + 1] = a.y;
        sv[tok][dq + 2] = a.z; sv[tok][dq + 3] = a.w;
        sv[tok][dq + 4] = b.x; sv[tok][dq + 5] = b.y;
        sv[tok][dq + 6] = b.z; sv[tok][dq + 7] = b.w;
    }
    __syncthreads();
    uint32_t* tb = (uint32_t*)(dst + ((size_t)h * 128 + kb) * 768);
    uint32_t wv[4];
    #pragma unroll
    for (int q = 0; q < 4; q++) {
        const int w = tid * 4 + q;
        const int reg = w & 1;
        const int t   = (w >> 1) & 3;
        const int gg  = (w >> 3) & 7;
        const int nb  = w >> 6;
        const int d = nb * 8 + gg;
        const int tok = reg * 8 + t * 2;
        wv[q] = packbf(sv[tok][d], sv[tok + 1][d]);
    }
    *reinterpret_cast<uint4*>(&tb[tid * 4]) = make_uint4(wv[0], wv[1], wv[2], wv[3]);
}

// ---------------- qkv GEMM with fused normalize + pack epilogue ----------------
// grid (24, 16): bx 0..7 = q heads, 8..15 = k heads, 16..23 = v heads; by = token block.
__global__ __launch_bounds__(256, 2) void gemm_qkv(
    const uint4* __restrict__ At, const uint4* __restrict__ Bt,
    uint4* __restrict__ qp, uint4* __restrict__ kp,
    uint4* __restrict__ vnA, uint4* __restrict__ vnB,
    float* __restrict__ xori)
{
    const int bx = blockIdx.x, by = blockIdx.y;
    const int nK = 64;
    const uint4* Ab = At + (size_t)by * nK * 768;
    const uint4* Bb = Bt + (size_t)bx * nK * 768;

    __shared__ uint4 smA[3][512], smB[3][512];

    const int tid = threadIdx.x, lane = tid & 31, wid = tid >> 5;
    const int wm = wid >> 1, wn = wid & 1;

    float acc[2][8][4];
    #pragma unroll
    for (int mt = 0; mt < 2; mt++)
        #pragma unroll
        for (int nt = 0; nt < 8; nt++)
            #pragma unroll
            for (int r = 0; r < 4; r++) acc[mt][nt][r] = 0.f;

    auto stage_load = [&](int kb, int st) {
        const uint4* An = Ab + (size_t)kb * 768;
        const uint4* Bn = Bb + (size_t)kb * 768;
        cpa16(&smA[st][tid], An + tid);
        cpa16(&smA[st][256 + tid], An + 256 + tid);
        cpa16(&smB[st][tid], Bn + tid);
        cpa16(&smB[st][256 + tid], Bn + 256 + tid);
        CP_COMMIT();
    };

    stage_load(0, 0);
    stage_load(1, 1);

    int cur = 0;
    for (int kb = 0; kb < nK; kb++) {
        if (kb + 2 <= nK) CP_WAIT1(); else CP_WAIT0();
        __syncthreads();

        uint32_t af[2][2][4];
        #pragma unroll
        for (int i = 0; i < 2; i++)
            #pragma unroll
            for (int mt = 0; mt < 2; mt++)
                *reinterpret_cast<uint4*>(af[i][mt]) =
                    smA[cur][i * 256 + (wm * 2 + mt) * 32 + lane];

        const uint2* B2 = reinterpret_cast<const uint2*>(smB[cur]);
        uint2 b0[8];
        #pragma unroll
        for (int nt = 0; nt < 8; nt++) b0[nt] = B2[(wn * 8 + nt) * 32 + lane];
        #pragma unroll
        for (int nt = 0; nt < 8; nt++)
            #pragma unroll
            for (int mt = 0; mt < 2; mt++)
                mma_bf16(acc[mt][nt], af[0][mt], b0[nt].x, b0[nt].y);   // hi*hi
        #pragma unroll
        for (int nt = 0; nt < 8; nt++)
            #pragma unroll
            for (int mt = 0; mt < 2; mt++)
                mma_bf16(acc[mt][nt], af[1][mt], b0[nt].x, b0[nt].y);   // lo*hi
        uint2 b1[8];
        #pragma unroll
        for (int nt = 0; nt < 8; nt++) b1[nt] = B2[512 + (wn * 8 + nt) * 32 + lane];
        #pragma unroll
        for (int nt = 0; nt < 8; nt++)
            #pragma unroll
            for (int mt = 0; mt < 2; mt++)
                mma_bf16(acc[mt][nt], af[0][mt], b1[nt].x, b1[nt].y);   // hi*lo

        if (kb + 2 < nK) stage_load(kb + 2, (kb + 2) % 3);
        else CP_COMMIT();
        cur = (cur + 1 == 3) ? 0 : cur + 1;
    }

    // ---- epilogue: per-row norms (cross-warp via smem), then pack/store ----
    const int g = lane >> 2, tq = lane & 3;
    __syncthreads();                               // smA reads done; reuse as float scratch
    float* snorm = reinterpret_cast<float*>(smA);  // [2 wn halves][128 rows]

    #pragma unroll
    for (int mt = 0; mt < 2; mt++) {
        float p0 = 0.f, p1 = 0.f;
        #pragma unroll
        for (int nt = 0; nt < 8; nt++) {
            p0 += acc[mt][nt][0] * acc[mt][nt][0] + acc[mt][nt][1] * acc[mt][nt][1];
            p1 += acc[mt][nt][2] * acc[mt][nt][2] + acc[mt][nt][3] * acc[mt][nt][3];
        }
        p0 += __shfl_xor_sync(0xffffffffu, p0, 1);
        p0 += __shfl_xor_sync(0xffffffffu, p0, 2);
        p1 += __shfl_xor_sync(0xffffffffu, p1, 1);
        p1 += __shfl_xor_sync(0xffffffffu, p1, 2);
        if (tq == 0) {
            snorm[wn * 128 + wm * 32 + mt * 16 + g]     = p0;
            snorm[wn * 128 + wm * 32 + mt * 16 + g + 8] = p1;
        }
    }
    __syncthreads();

    const int typ = bx >> 3;       // 0=q, 1=k, 2=v
    const int h   = bx & 7;

    #pragma unroll
    for (int mt = 0; mt < 2; mt++) {
        const int r0 = wm * 32 + mt * 16 + g;
        const int r1 = r0 + 8;
        const float inv0 = rsqrtf(snorm[r0] + snorm[128 + r0]);
        const float inv1 = rsqrtf(snorm[r1] + snorm[128 + r1]);

        if (typ == 0) {
            // q: scale 25/norm -> 2-term A-image
            const float s0 = SCALE_F * inv0, s1 = SCALE_F * inv1;
            const int baseW = ((wm * 2 + mt) * 32 + g * 4 + tq) * 4;
            #pragma unroll
            for (int ntp = 0; ntp < 4; ntp++) {
                uint32_t hw[4], lw[4];
                #pragma unroll
                for (int sub = 0; sub < 2; sub++) {
                    const int nt = ntp * 2 + sub;
                    split2(acc[mt][nt][0] * s0, acc[mt][nt][1] * s0, hw[sub*2],   lw[sub*2]);
                    split2(acc[mt][nt][2] * s1, acc[mt][nt][3] * s1, hw[sub*2+1], lw[sub*2+1]);
                }
                uint32_t* tb = (uint32_t*)(qp + ((size_t)(h * 16 + by) * 8 + wn * 4 + ntp) * 768);
                *reinterpret_cast<uint4*>(&tb[baseW])        = make_uint4(hw[0], hw[1], hw[2], hw[3]);
                *reinterpret_cast<uint4*>(&tb[1024 + baseW]) = make_uint4(lw[0], lw[1], lw[2], lw[3]);
            }
        } else if (typ == 1) {
            // k: scale 1/norm -> 2-term B-image
            const float s0 = inv0, s1 = inv1;
            const int bw0 = ((wm * 4 + mt * 2) * 32 + g * 4 + tq) * 2;
            #pragma unroll
            for (int ntp = 0; ntp < 4; ntp++) {
                const int nt0 = ntp * 2, nt1 = ntp * 2 + 1;
                uint32_t h00, l00, h01, l01, h10, l10, h11, l11;
                split2(acc[mt][nt0][0] * s0, acc[mt][nt0][1] * s0, h00, l00);
                split2(acc[mt][nt1][0] * s0, acc[mt][nt1][1] * s0, h01, l01);
                split2(acc[mt][nt0][2] * s1, acc[mt][nt0][3] * s1, h10, l10);
                split2(acc[mt][nt1][2] * s1, acc[mt][nt1][3] * s1, h11, l11);
                uint32_t* tb = (uint32_t*)(kp + ((size_t)(h * 16 + by) * 8 + wn * 4 + ntp) * 768);
                *reinterpret_cast<uint2*>(&tb[bw0])              = make_uint2(h00, h01);
                *reinterpret_cast<uint2*>(&tb[bw0 + 64])         = make_uint2(h10, h11);
                *reinterpret_cast<uint2*>(&tb[1024 + bw0])       = make_uint2(l00, l01);
                *reinterpret_cast<uint2*>(&tb[1024 + bw0 + 64])  = make_uint2(l10, l11);
            }
        } else {
            // v: raw -> x_ori; scaled -> vn A-image + B-image (hi only)
            const float s0 = inv0, s1 = inv1;
            const int baseW = ((wm * 2 + mt) * 32 + g * 4 + tq) * 4;
            const int bw0 = ((wm * 4 + mt * 2) * 32 + g * 4 + tq) * 2;
            #pragma unroll
            for (int ntp = 0; ntp < 4; ntp++) {
                const int nt0 = ntp * 2, nt1 = ntp * 2 + 1;
                // x_ori raw stores
                #pragma unroll
                for (int sub = 0; sub < 2; sub++) {
                    const int nt = ntp * 2 + sub;
                    const int col = wn * 64 + nt * 8 + tq * 2;
                    float* d0 = xori + (size_t)(by * 128 + r0) * (2 * Cc) + Cc + h * HD + col;
                    float* d1 = xori + (size_t)(by * 128 + r1) * (2 * Cc) + Cc + h * HD + col;
                    *reinterpret_cast<float2*>(d0) = make_float2(acc[mt][nt][0], acc[mt][nt][1]);
                    *reinterpret_cast<float2*>(d1) = make_float2(acc[mt][nt][2], acc[mt][nt][3]);
                }
                // vn A-image (hi)
                {
                    uint32_t hw[4];
                    hw[0] = packbf(acc[mt][nt0][0] * s0, acc[mt][nt0][1] * s0);
                    hw[1] = packbf(acc[mt][nt0][2] * s1, acc[mt][nt0][3] * s1);
                    hw[2] = packbf(acc[mt][nt1][0] * s0, acc[mt][nt1][1] * s0);
                    hw[3] = packbf(acc[mt][nt1][2] * s1, acc[mt][nt1][3] * s1);
                    uint32_t* tb = (uint32_t*)(vnA + ((size_t)by * 64 + h * 8 + wn * 4 + ntp) * 768);
                    *reinterpret_cast<uint4*>(&tb[baseW]) = make_uint4(hw[0], hw[1], hw[2], hw[3]);
                }
                // vn B-image (hi)
                {
                    uint32_t h00 = packbf(acc[mt][nt0][0] * s0, acc[mt][nt0][1] * s0);
                    uint32_t h01 = packbf(acc[mt][nt1][0] * s0, acc[mt][nt1][1] * s0);
                    uint32_t h10 = packbf(acc[mt][nt0][2] * s1, acc[mt][nt0][3] * s1);
                    uint32_t h11 = packbf(acc[mt][nt1][2] * s1, acc[mt][nt1][3] * s1);
                    uint32_t* tb = (uint32_t*)(vnB + ((size_t)by * 64 + h * 8 + wn * 4 + ntp) * 768);
                    *reinterpret_cast<uint2*>(&tb[bw0])      = make_uint2(h00, h01);
                    *reinterpret_cast<uint2*>(&tb[bw0 + 64]) = make_uint2(h10, h11);
                }
            }
        }
    }
}

// ---------------- packed bf16 GEMM (MODE 0/2/3), cp.async 3-stage ----------------
template<int MODE, int PROD>
__global__ __launch_bounds__(256, 2) void gemm_pk(
    const uint4* __restrict__ At, const uint4* __restrict__ Bt,
    int nK, int nKtotA, int nKtotB, int nRbA, int nRbB, int kzBits,
    float* __restrict__ C, int ldc, long long cZ,
    const float* __restrict__ cls, uint4* __restrict__ epk,
    float* __restrict__ rsOut, uint8_t* __restrict__ maskOut)
{
    int bx, by;
    if (MODE == 3) {
        int r = blockIdx.x, row = 0;
        while (r >= 16 - row) { r -= 16 - row; row++; }
        by = row; bx = row + r;
    } else { bx = blockIdx.x; by = blockIdx.y; }

    const int hz = blockIdx.z >> kzBits;
    const int kz = blockIdx.z & ((1 << kzBits) - 1);
    const uint4* Ab = At + ((size_t)(hz * nRbA + by) * nKtotA + (size_t)kz * nK) * 768;
    const uint4* Bb = Bt + ((size_t)(hz * nRbB + bx) * nKtotB + (size_t)kz * nK) * 768;

    __shared__ uint4 smA[3][512], smB[3][512];

    const int tid = threadIdx.x, lane = tid & 31, wid = tid >> 5;
    const int wm = wid >> 1, wn = wid & 1;

    float acc[2][8][4];
    #pragma unroll
    for (int mt = 0; mt < 2; mt++)
        #pragma unroll
        for (int nt = 0; nt < 8; nt++)
            #pragma unroll
            for (int r = 0; r < 4; r++) acc[mt][nt][r] = 0.f;

    auto stage_load = [&](int kb, int st) {
        const uint4* An = Ab + (size_t)kb * 768;
        const uint4* Bn = Bb + (size_t)kb * 768;
        cpa16(&smA[st][tid], An + tid);
        if (PROD >= 2) cpa16(&smA[st][256 + tid], An + 256 + tid);
        cpa16(&smB[st][tid], Bn + tid);
        if (PROD >= 3) cpa16(&smB[st][256 + tid], Bn + 256 + tid);
        CP_COMMIT();
    };

    stage_load(0, 0);
    if (nK > 1) stage_load(1, 1);

    int cur = 0;
    for (int kb = 0; kb < nK; kb++) {
        if (kb + 2 <= nK) CP_WAIT1(); else CP_WAIT0();
        __syncthreads();

        uint32_t af[2][2][4];
        #pragma unroll
        for (int mt = 0; mt < 2; mt++)
            *reinterpret_cast<uint4*>(af[0][mt]) =
                smA[cur][(wm * 2 + mt) * 32 + lane];
        if (PROD >= 2) {
            #pragma unroll
            for (int mt = 0; mt < 2; mt++)
                *reinterpret_cast<uint4*>(af[1][mt]) =
                    smA[cur][256 + (wm * 2 + mt) * 32 + lane];
        }

        const uint2* B2 = reinterpret_cast<const uint2*>(smB[cur]);
        uint2 b0[8];
        #pragma unroll
        for (int nt = 0; nt < 8; nt++) b0[nt] = B2[(wn * 8 + nt) * 32 + lane];
        #pragma unroll
        for (int nt = 0; nt < 8; nt++)
            #pragma unroll
            for (int mt = 0; mt < 2; mt++)
                mma_bf16(acc[mt][nt], af[0][mt], b0[nt].x, b0[nt].y);   // hi*hi
        if (PROD >= 2) {
            #pragma unroll
            for (int nt = 0; nt < 8; nt++)
                #pragma unroll
                for (int mt = 0; mt < 2; mt++)
                    mma_bf16(acc[mt][nt], af[1][mt], b0[nt].x, b0[nt].y);  // lo*hi
        }
        if (PROD >= 3) {
            uint2 b1[8];
            #pragma unroll
            for (int nt = 0; nt < 8; nt++) b1[nt] = B2[512 + (wn * 8 + nt) * 32 + lane];
            #pragma unroll
            for (int nt = 0; nt < 8; nt++)
                #pragma unroll
                for (int mt = 0; mt < 2; mt++)
                    mma_bf16(acc[mt][nt], af[0][mt], b1[nt].x, b1[nt].y);  // hi*lo
        }

        if (kb + 2 < nK) stage_load(kb + 2, (kb + 2) % 3);
        else CP_COMMIT();
        cur = (cur + 1 == 3) ? 0 : cur + 1;
    }

    const int g = lane >> 2, tq = lane & 3;

    if (MODE == 2) {
        #pragma unroll
        for (int mt = 0; mt < 2; mt++) {
            const int m = wm * 2 + mt;
            const int i0 = by * 128 + m * 16 + g;
            const int i1 = i0 + 8;
            const float tha = cls[i0] - 0.1f;
            const float thb = cls[i1] - 0.1f;
            float rs0 = 0.f, rs1 = 0.f;
            const int baseW = (m * 32 + g * 4 + tq) * 4;
            #pragma unroll
            for (int ntp = 0; ntp < 4; ntp++) {
                uint32_t hw[4];
                #pragma unroll
                for (int sub = 0; sub < 2; sub++) {
                    const int nt = ntp * 2 + sub;
                    const int j = bx * 128 + wn * 64 + nt * 8 + tq * 2;
                    const float cj0 = cls[j], cj1 = cls[j + 1];
                    float e00 = (cj0 > tha) ? __expf(acc[mt][nt][0] * cj0) : 1.f;
                    float e01 = (cj1 > tha) ? __expf(acc[mt][nt][1] * cj1) : 1.f;
                    float e10 = (cj0 > thb) ? __expf(acc[mt][nt][2] * cj0) : 1.f;
                    float e11 = (cj1 > thb) ? __expf(acc[mt][nt][3] * cj1) : 1.f;
                    rs0 += e00 + e01;
                    rs1 += e10 + e11;
                    hw[sub * 2]     = packbf(e00, e01);
                    hw[sub * 2 + 1] = packbf(e10, e11);
                }
                const size_t tIdx = (size_t)(hz * 16 + by) * 128 + bx * 8 + wn * 4 + ntp;
                uint32_t* tb = (uint32_t*)(epk + tIdx * 768);
                *reinterpret_cast<uint4*>(&tb[baseW]) =
                    make_uint4(hw[0], hw[1], hw[2], hw[3]);
            }
            rs0 += __shfl_xor_sync(0xffffffffu, rs0, 1);
            rs0 += __shfl_xor_sync(0xffffffffu, rs0, 2);
            rs1 += __shfl_xor_sync(0xffffffffu, rs1, 1);
            rs1 += __shfl_xor_sync(0xffffffffu, rs1, 2);
            if (tq == 0) {
                atomicAdd(&rsOut[hz * Nn + i0], rs0);
                atomicAdd(&rsOut[hz * Nn + i1], rs1);
            }
        }
    } else if (MODE == 3) {
        __syncthreads();
        uint8_t* sb = reinterpret_cast<uint8_t*>(smA);
        #pragma unroll
        for (int mt = 0; mt < 2; mt++)
            #pragma unroll
            for (int nt = 0; nt < 8; nt++) {
                const int r0 = wm * 32 + mt * 16 + g;
                const int c0 = wn * 64 + nt * 8 + tq * 2;
                sb[r0 * 144 + c0]           = acc[mt][nt][0] > 6.f;
                sb[r0 * 144 + c0 + 1]       = acc[mt][nt][1] > 6.f;
                sb[(r0 + 8) * 144 + c0]     = acc[mt][nt][2] > 6.f;
                sb[(r0 + 8) * 144 + c0 + 1] = acc[mt][nt][3] > 6.f;
            }
        __syncthreads();
        const int r = tid >> 1, hf = tid & 1;
        {
            const uint8_t* srcp = sb + r * 144 + hf * 64;
            uint4 v0 = *reinterpret_cast<const uint4*>(srcp);
            uint4 v1 = *reinterpret_cast<const uint4*>(srcp + 16);
            uint4 v2 = *reinterpret_cast<const uint4*>(srcp + 32);
            uint4 v3 = *reinterpret_cast<const uint4*>(srcp + 48);
            uint8_t* dst = maskOut + (size_t)(by * 128 + r) * Nn + bx * 128 + hf * 64;
            *reinterpret_cast<uint4*>(dst)      = v0;
            *reinterpret_cast<uint4*>(dst + 16) = v1;
            *reinterpret_cast<uint4*>(dst + 32) = v2;
            *reinterpret_cast<uint4*>(dst + 48) = v3;
        }
        {
            uint32_t wv[16];
            #pragma unroll
            for (int q = 0; q < 16; q++) {
                uint32_t b0 = sb[(hf * 64 + q * 4 + 0) * 144 + r];
                uint32_t b1 = sb[(hf * 64 + q * 4 + 1) * 144 + r];
                uint32_t b2 = sb[(hf * 64 + q * 4 + 2) * 144 + r];
                uint32_t b3 = sb[(hf * 64 + q * 4 + 3) * 144 + r];
                wv[q] = b0 | (b1 << 8) | (b2 << 16) | (b3 << 24);
            }
            uint8_t* dst = maskOut + (size_t)(bx * 128 + r) * Nn + by * 128 + hf * 64;
            #pragma unroll
            for (int q = 0; q < 4; q++)
                *reinterpret_cast<uint4*>(dst + q * 16) =
                    make_uint4(wv[q*4], wv[q*4+1], wv[q*4+2], wv[q*4+3]);
        }
    } else {
        float* Cz = C + (long long)blockIdx.z * cZ;
        #pragma unroll
        for (int mt = 0; mt < 2; mt++) {
            const int row0 = by * 128 + wm * 32 + mt * 16 + g;
            #pragma unroll
            for (int nt = 0; nt < 8; nt++) {
                const int col = bx * 128 + wn * 64 + nt * 8 + tq * 2;
                *reinterpret_cast<float2*>(&Cz[(long long)row0 * ldc + col]) =
                    make_float2(acc[mt][nt][0], acc[mt][nt][1]);
                *reinterpret_cast<float2*>(&Cz[(long long)(row0 + 8) * ldc + col]) =
                    make_float2(acc[mt][nt][2], acc[mt][nt][3]);
            }
        }
    }
}

// ---------------- combine split-K partials (x_ori handled by gemm_qkv) ----------------
__global__ __launch_bounds__(256) void combine_kernel(float* __restrict__ out)
{
    int idx = blockIdx.x * 256 + threadIdx.x;
    if (idx >= Nn * Cc / 4) return;
    const int n = idx >> 8, c4 = idx & 255;
    const int h = c4 >> 5, d4 = c4 & 31;
    const float4* p = reinterpret_cast<const float4*>(g_part);
    const size_t st = (size_t)Nn * 32;
    const size_t b = ((size_t)(h * 2) * Nn + n) * 32 + d4;
    float4 a0 = p[b], a1 = p[b + st];
    const float s = 1.f / g_rowsum[h * Nn + n];
    *reinterpret_cast<float4*>(out + (size_t)n * (2 * Cc) + h * 128 + d4 * 4) =
        make_float4((a0.x + a1.x) * s, (a0.y + a1.y) * s,
                    (a0.z + a1.z) * s, (a0.w + a1.w) * s);
}

// ---------------- simround2 merged: e in registers, single epk read ----------------
__global__ __launch_bounds__(256) void simr2_merged(float* __restrict__ out)
{
    const int blk = blockIdx.x;
    const int rowBlk = blk >> 3, m = blk & 7;
    const int tid = threadIdx.x;
    const int gg = tid >> 5;
    const int lane = tid & 31;
    const int i0 = blk * 16 + gg;
    const int i1 = i0 + 8;
    const int ubase = m * 32 + gg * 4;
    __shared__ float sinv[16];

    float irs0[8], irs1[8];
    #pragma unroll
    for (int h = 0; h < 8; h++) {
        irs0[h] = 1.f / g_rowsum[h * Nn + i0];
        irs1[h] = 1.f / g_rowsum[h * Nn + i1];
    }

    float e0r[64], e1r[64];
    float msum0 = 0.f, msum1 = 0.f;
    #pragma unroll
    for (int kt = 0; kt < 4; kt++) {
        const int kb = lane + kt * 32;
        float a0[16], a1[16];
        #pragma unroll
        for (int p = 0; p < 16; p++) { a0[p] = 0.f; a1[p] = 0.f; }
        #pragma unroll
        for (int h = 0; h < 8; h++) {
            const uint4* blob = g_epk + ((size_t)((h * 16 + rowBlk) * 128 + kb)) * 768;
            const float w0 = irs0[h], w1 = irs1[h];
            #pragma unroll
            for (int t = 0; t < 4; t++) {
                uint4 H = blob[ubase + t];
                a0[t*2+0]   += blo(H.x) * w0;
                a0[t*2+1]   += bhi(H.x) * w0;
                a1[t*2+0]   += blo(H.y) * w1;
                a1[t*2+1]   += bhi(H.y) * w1;
                a0[8+t*2+0] += blo(H.z) * w0;
                a0[8+t*2+1] += bhi(H.z) * w0;
                a1[8+t*2+0] += blo(H.w) * w1;
                a1[8+t*2+1] += bhi(H.w) * w1;
            }
        }
        const int j0 = kb * 16;
        uint4 mv0 = *reinterpret_cast<const uint4*>(g_mask + (size_t)i0 * Nn + j0);
        uint4 mv1 = *reinterpret_cast<const uint4*>(g_mask + (size_t)i1 * Nn + j0);
        const uint8_t* mb0 = reinterpret_cast<const uint8_t*>(&mv0);
        const uint8_t* mb1 = reinterpret_cast<const uint8_t*>(&mv1);
        #pragma unroll
        for (int p = 0; p < 16; p++) {
            float e0 = __expf(a0[p] * 0.125f);
            float e1 = __expf(a1[p] * 0.125f);
            e0r[kt * 16 + p] = e0;
            e1r[kt * 16 + p] = e1;
            if (mb0[p]) msum0 += e0;
            if (mb1[p]) msum1 += e1;
        }
    }
    #pragma unroll
    for (int o = 16; o > 0; o >>= 1) {
        msum0 += __shfl_xor_sync(0xffffffffu, msum0, o);
        msum1 += __shfl_xor_sync(0xffffffffu, msum1, o);
    }
    if (lane == 0) { sinv[gg] = 1.f / msum0; sinv[8 + gg] = 1.f / msum1; }
    __syncthreads();
    const float inv0 = sinv[gg], inv1 = sinv[8 + gg];

    #pragma unroll
    for (int kt = 0; kt < 4; kt++) {
        const int j0 = (lane + kt * 32) * 16;
        uint4 mv0 = *reinterpret_cast<const uint4*>(g_mask + (size_t)i0 * Nn + j0);
        uint4 mv1 = *reinterpret_cast<const uint4*>(g_mask + (size_t)i1 * Nn + j0);
        const uint8_t* mb0 = reinterpret_cast<const uint8_t*>(&mv0);
        const uint8_t* mb1 = reinterpret_cast<const uint8_t*>(&mv1);
        float* d0 = out + (size_t)i0 * Nn + j0;
        float* d1 = out + (size_t)i1 * Nn + j0;
        #pragma unroll
        for (int q = 0; q < 4; q++) {
            float4 o0, o1;
            o0.x = mb0[q*4+0] ? e0r[kt*16 + q*4+0] * inv0 : 0.f;
            o0.y = mb0[q*4+1] ? e0r[kt*16 + q*4+1] * inv0 : 0.f;
            o0.z = mb0[q*4+2] ? e0r[kt*16 + q*4+2] * inv0 : 0.f;
            o0.w = mb0[q*4+3] ? e0r[kt*16 + q*4+3] * inv0 : 0.f;
            o1.x = mb1[q*4+0] ? e1r[kt*16 + q*4+0] * inv1 : 0.f;
            o1.y = mb1[q*4+1] ? e1r[kt*16 + q*4+1] * inv1 : 0.f;
            o1.z = mb1[q*4+2] ? e1r[kt*16 + q*4+2] * inv1 : 0.f;
            o1.w = mb1[q*4+3] ? e1r[kt*16 + q*4+3] * inv1 : 0.f;
            *reinterpret_cast<float4*>(d0 + q * 4) = o0;
            *reinterpret_cast<float4*>(d1 + q * 4) = o1;
        }
    }
}

// ---------------- host launcher (multi-stream fork/join) ----------------
extern "C" void kernel_launch(void* const* d_in, const int* in_sizes, int n_in,
                              void* d_out, int out_size)
{
    const float* x   = (const float*)d_in[0];
    const float* cls = (const float*)d_in[1];
    const float* W   = (const float*)d_in[3];
    float* out = (float*)d_out;

    float *p_rs, *p_part;
    uint4 *p_xp, *p_Wp, *p_qp, *p_kp, *p_vnpA, *p_vnpB, *p_vTp, *p_epk;
    uint8_t* p_mask;
    cudaGetSymbolAddress((void**)&p_rs, g_rowsum);
    cudaGetSymbolAddress((void**)&p_part, g_part);
    cudaGetSymbolAddress((void**)&p_xp, g_xp);
    cudaGetSymbolAddress((void**)&p_Wp, g_Wp);
    cudaGetSymbolAddress((void**)&p_qp, g_qp);
    cudaGetSymbolAddress((void**)&p_kp, g_kp);
    cudaGetSymbolAddress((void**)&p_vnpA, g_vnpA);
    cudaGetSymbolAddress((void**)&p_vnpB, g_vnpB);
    cudaGetSymbolAddress((void**)&p_vTp, g_vTp);
    cudaGetSymbolAddress((void**)&p_epk, g_epk);
    cudaGetSymbolAddress((void**)&p_mask, g_mask);

    static cudaStream_t s1 = nullptr;
    static cudaEvent_t evFork = nullptr, evVtp = nullptr, evLog = nullptr, evEnd = nullptr;
    if (!s1) {
        cudaStreamCreateWithFlags(&s1, cudaStreamNonBlocking);
        cudaEventCreateWithFlags(&evFork, cudaEventDisableTiming);
        cudaEventCreateWithFlags(&evVtp, cudaEventDisableTiming);
        cudaEventCreateWithFlags(&evLog, cudaEventDisableTiming);
        cudaEventCreateWithFlags(&evEnd, cudaEventDisableTiming);
    }

    // ---- main stream ----
    cudaMemsetAsync(p_rs, 0, Hh * Nn * sizeof(float));
    pack_a<2><<<dim3(64, 16, 1), 256>>>(x, Cc, 0, p_xp, 64);
    pack_b<2><<<dim3(64, 24, 1), 256>>>(W, Cc, 0, p_Wp, 64);

    // 1. qkv GEMM with fused normalize + pack epilogue
    gemm_qkv<<<dim3(24, 16), 256>>>(p_xp, p_Wp, p_qp, p_kp, p_vnpA, p_vnpB, out);
    cudaEventRecord(evFork, 0);

    // ---- side stream: vT transpose-pack, sim mask, later simr2 ----
    cudaStreamWaitEvent(s1, evFork, 0);
    pack_vT<<<dim3(128, 8), 256, 0, s1>>>(out, p_vTp);
    cudaEventRecord(evVtp, s1);
    gemm_pk<3, 1><<<dim3(136, 1, 1), 256, 0, s1>>>(p_vnpA, p_vnpB, 64, 64, 64, 16, 16, 0,
                                                   nullptr, 0, 0, nullptr, nullptr, nullptr, p_mask);

    // ---- main stream: logits (q/k images already written by gemm_qkv) ----
    gemm_pk<2, 3><<<dim3(16, 16, 8), 256>>>(p_qp, p_kp, 8, 8, 8, 16, 16, 0,
                                            nullptr, 0, 0, cls, p_epk, p_rs, nullptr);
    cudaEventRecord(evLog, 0);

    // side stream: simr2
    cudaStreamWaitEvent(s1, evLog, 0);
    simr2_merged<<<128, 256, 0, s1>>>(out + (size_t)Nn * 2 * Cc);
    cudaEventRecord(evEnd, s1);

    // main stream: attn@V split-K x2 (1 product), combine
    cudaStreamWaitEvent(0, evVtp, 0);
    gemm_pk<0, 1><<<dim3(1, 16, 16), 256>>>(p_epk, p_vTp, 64, 128, 128, 16, 1, 1,
                                            p_part, HD, (long long)Nn * HD,
                                            nullptr, nullptr, nullptr, nullptr);
    combine_kernel<<<(Nn * Cc / 4 + 255) / 256, 256>>>(out);

    cudaStreamWaitEvent(0, evEnd, 0);
}

// round 15
// speedup vs baseline: 1.8454x; 1.1293x over previous
#include <cuda_runtime.h>
#include <math.h>
#include <stdint.h>

#define Nn 2048
#define Cc 1024
#define Hh 8
#define HD 128
#define SCALE_F 25.0f

// ---------------- scratch ----------------
__device__ float g_rowsum[Hh * Nn];
__device__ float g_part[(size_t)16 * Nn * HD];
__device__ uint8_t g_mask[(size_t)Nn * Nn];

// packed bf16 fragment images; tile = 128 rows x 16 k (stride 768 uint4)
__device__ uint4 g_xp [(size_t)16 * 64 * 768];
__device__ uint4 g_Wp [(size_t)24 * 64 * 768];
__device__ uint4 g_qp [(size_t)8 * 16 * 8 * 768];
__device__ uint4 g_kp [(size_t)8 * 16 * 8 * 768];    // hi plane only used
__device__ uint4 g_vnpA[(size_t)16 * 64 * 768];
__device__ uint4 g_vnpB[(size_t)16 * 64 * 768];
__device__ uint4 g_vTp[(size_t)8 * 128 * 768];
__device__ uint4 g_epk[(size_t)8 * 16 * 128 * 768];  // hi plane only used

// ---------------- helpers ----------------
__device__ __forceinline__ uint32_t packbf(float x, float y)
{
    uint32_t h;
    asm("cvt.rn.bf16x2.f32 %0, %1, %2;" : "=r"(h) : "f"(y), "f"(x));
    return h;
}
__device__ __forceinline__ float blo(uint32_t u) { return __uint_as_float(u << 16); }
__device__ __forceinline__ float bhi(uint32_t u) { return __uint_as_float(u & 0xFFFF0000u); }
__device__ __forceinline__ void split2(float x, float y, uint32_t& s0, uint32_t& s1)
{
    s0 = packbf(x, y);
    s1 = packbf(x - blo(s0), y - bhi(s0));
}

__device__ __forceinline__ void mma_bf16(float c[4], const uint32_t a[4],
                                         uint32_t b0, uint32_t b1)
{
    asm volatile(
        "mma.sync.aligned.m16n8k16.row.col.f32.bf16.bf16.f32 "
        "{%0,%1,%2,%3}, {%4,%5,%6,%7}, {%8,%9}, {%0,%1,%2,%3};"
        : "+f"(c[0]), "+f"(c[1]), "+f"(c[2]), "+f"(c[3])
        : "r"(a[0]), "r"(a[1]), "r"(a[2]), "r"(a[3]), "r"(b0), "r"(b1));
}

__device__ __forceinline__ void cpa16(void* smem, const void* gmem)
{
    uint32_t s = (uint32_t)__cvta_generic_to_shared(smem);
    asm volatile("cp.async.cg.shared.global [%0], [%1], 16;" :: "r"(s), "l"(gmem));
}
#define CP_COMMIT() asm volatile("cp.async.commit_group;")
#define CP_WAIT1()  asm volatile("cp.async.wait_group 1;")
#define CP_WAIT0()  asm volatile("cp.async.wait_group 0;")

// ---------------- pack kernels ----------------
template<int TERMS>
__global__ __launch_bounds__(256) void pack_a(
    const float* __restrict__ src, int lda, long long zstride, uint4* __restrict__ dst, int nKb)
{
    const int kb = blockIdx.x, rb = blockIdx.y, z = blockIdx.z;
    src += (long long)z * zstride;
    uint32_t* tb = (uint32_t*)(dst + ((size_t)(z * gridDim.y + rb) * nKb + kb) * 768);
    const int tid = threadIdx.x;
    #pragma unroll
    for (int t = 0; t < 2; t++) {
        int idx = tid + t * 256;
        int row = idx >> 2, k4 = (idx & 3) * 4;
        float4 v = *reinterpret_cast<const float4*>(
            &src[(long long)(rb * 128 + row) * lda + kb * 16 + k4]);
        int m = row >> 4, r16 = row & 15, g = r16 & 7, half = r16 >> 3;
        int tt = (k4 & 7) >> 1, reg = half + 2 * (k4 >> 3);
        int base = (m * 32 + g * 4 + tt) * 4 + reg;
        uint32_t s0, s1;
        split2(v.x, v.y, s0, s1);
        tb[base] = s0;
        if (TERMS >= 2) tb[1024 + base] = s1;
        split2(v.z, v.w, s0, s1);
        tb[base + 4] = s0;
        if (TERMS >= 2) tb[1024 + base + 4] = s1;
    }
}

template<int TERMS>
__global__ __launch_bounds__(256) void pack_b(
    const float* __restrict__ src, int ldb, long long zstride, uint4* __restrict__ dst, int nKb)
{
    const int kb = blockIdx.x, rb = blockIdx.y, z = blockIdx.z;
    src += (long long)z * zstride;
    uint32_t* tb = (uint32_t*)(dst + ((size_t)(z * gridDim.y + rb) * nKb + kb) * 768);
    const int tid = threadIdx.x;
    #pragma unroll
    for (int t = 0; t < 2; t++) {
        int idx = tid + t * 256;
        int row = idx >> 2, k4 = (idx & 3) * 4;
        float4 v = *reinterpret_cast<const float4*>(
            &src[(long long)(rb * 128 + row) * ldb + kb * 16 + k4]);
        int nb = row >> 3, g = row & 7;
        int tt = (k4 & 7) >> 1, reg = k4 >> 3;
        int base = (nb * 32 + g * 4 + tt) * 2 + reg;
        uint32_t s0, s1;
        split2(v.x, v.y, s0, s1);
        tb[base] = s0;
        if (TERMS >= 2) tb[1024 + base] = s1;
        split2(v.z, v.w, s0, s1);
        tb[base + 2] = s0;
        if (TERMS >= 2) tb[1024 + base + 2] = s1;
    }
}

// ---------------- pack vT from x_ori region of out (transpose gather) ----------------
__global__ __launch_bounds__(256) void pack_vT(
    const float* __restrict__ xori, uint4* __restrict__ dst)
{
    const int kb = blockIdx.x;    // 16-token tile
    const int h  = blockIdx.y;
    const int tid = threadIdx.x;
    __shared__ float sv[16][132];
    {
        const int tok = tid >> 4;
        const int dq  = (tid & 15) * 8;
        const float* src = xori + (size_t)(kb * 16 + tok) * (2 * Cc) + Cc + h * HD + dq;
        float4 a = *reinterpret_cast<const float4*>(src);
        float4 b = *reinterpret_cast<const float4*>(src + 4);
        sv[tok][dq + 0] = a.x; sv[tok][dq + 1] = a.y;
        sv[tok][dq + 2] = a.z; sv[tok][dq + 3] = a.w;
        sv[tok][dq + 4] = b.x; sv[tok][dq + 5] = b.y;
        sv[tok][dq + 6] = b.z; sv[tok][dq + 7] = b.w;
    }
    __syncthreads();
    uint32_t* tb = (uint32_t*)(dst + ((size_t)h * 128 + kb) * 768);
    uint32_t wv[4];
    #pragma unroll
    for (int q = 0; q < 4; q++) {
        const int w = tid * 4 + q;
        const int reg = w & 1;
        const int t   = (w >> 1) & 3;
        const int gg  = (w >> 3) & 7;
        const int nb  = w >> 6;
        const int d = nb * 8 + gg;
        const int tok = reg * 8 + t * 2;
        wv[q] = packbf(sv[tok][d], sv[tok + 1][d]);
    }
    *reinterpret_cast<uint4*>(&tb[tid * 4]) = make_uint4(wv[0], wv[1], wv[2], wv[3]);
}

// ---------------- qkv GEMM with fused normalize + pack epilogue ----------------
// bx+bxOff: 0..7 = q heads, 8..15 = k heads, 16..23 = v heads; by = token block.
__global__ __launch_bounds__(256, 2) void gemm_qkv(
    const uint4* __restrict__ At, const uint4* __restrict__ Bt, int bxOff,
    uint4* __restrict__ qp, uint4* __restrict__ kp,
    uint4* __restrict__ vnA, uint4* __restrict__ vnB,
    float* __restrict__ xori)
{
    const int bx = blockIdx.x + bxOff, by = blockIdx.y;
    const int nK = 64;
    const uint4* Ab = At + (size_t)by * nK * 768;
    const uint4* Bb = Bt + (size_t)bx * nK * 768;

    __shared__ uint4 smA[3][512], smB[3][512];

    const int tid = threadIdx.x, lane = tid & 31, wid = tid >> 5;
    const int wm = wid >> 1, wn = wid & 1;

    float acc[2][8][4];
    #pragma unroll
    for (int mt = 0; mt < 2; mt++)
        #pragma unroll
        for (int nt = 0; nt < 8; nt++)
            #pragma unroll
            for (int r = 0; r < 4; r++) acc[mt][nt][r] = 0.f;

    auto stage_load = [&](int kb, int st) {
        const uint4* An = Ab + (size_t)kb * 768;
        const uint4* Bn = Bb + (size_t)kb * 768;
        cpa16(&smA[st][tid], An + tid);
        cpa16(&smA[st][256 + tid], An + 256 + tid);
        cpa16(&smB[st][tid], Bn + tid);
        cpa16(&smB[st][256 + tid], Bn + 256 + tid);
        CP_COMMIT();
    };

    stage_load(0, 0);
    stage_load(1, 1);

    int cur = 0;
    for (int kb = 0; kb < nK; kb++) {
        if (kb + 2 <= nK) CP_WAIT1(); else CP_WAIT0();
        __syncthreads();

        uint32_t af[2][2][4];
        #pragma unroll
        for (int i = 0; i < 2; i++)
            #pragma unroll
            for (int mt = 0; mt < 2; mt++)
                *reinterpret_cast<uint4*>(af[i][mt]) =
                    smA[cur][i * 256 + (wm * 2 + mt) * 32 + lane];

        const uint2* B2 = reinterpret_cast<const uint2*>(smB[cur]);
        uint2 b0[8];
        #pragma unroll
        for (int nt = 0; nt < 8; nt++) b0[nt] = B2[(wn * 8 + nt) * 32 + lane];
        #pragma unroll
        for (int nt = 0; nt < 8; nt++)
            #pragma unroll
            for (int mt = 0; mt < 2; mt++)
                mma_bf16(acc[mt][nt], af[0][mt], b0[nt].x, b0[nt].y);   // hi*hi
        #pragma unroll
        for (int nt = 0; nt < 8; nt++)
            #pragma unroll
            for (int mt = 0; mt < 2; mt++)
                mma_bf16(acc[mt][nt], af[1][mt], b0[nt].x, b0[nt].y);   // lo*hi
        uint2 b1[8];
        #pragma unroll
        for (int nt = 0; nt < 8; nt++) b1[nt] = B2[512 + (wn * 8 + nt) * 32 + lane];
        #pragma unroll
        for (int nt = 0; nt < 8; nt++)
            #pragma unroll
            for (int mt = 0; mt < 2; mt++)
                mma_bf16(acc[mt][nt], af[0][mt], b1[nt].x, b1[nt].y);   // hi*lo

        if (kb + 2 < nK) stage_load(kb + 2, (kb + 2) % 3);
        else CP_COMMIT();
        cur = (cur + 1 == 3) ? 0 : cur + 1;
    }

    // ---- epilogue: per-row norms (cross-warp via smem), then pack/store ----
    const int g = lane >> 2, tq = lane & 3;
    __syncthreads();
    float* snorm = reinterpret_cast<float*>(smA);

    #pragma unroll
    for (int mt = 0; mt < 2; mt++) {
        float p0 = 0.f, p1 = 0.f;
        #pragma unroll
        for (int nt = 0; nt < 8; nt++) {
            p0 += acc[mt][nt][0] * acc[mt][nt][0] + acc[mt][nt][1] * acc[mt][nt][1];
            p1 += acc[mt][nt][2] * acc[mt][nt][2] + acc[mt][nt][3] * acc[mt][nt][3];
        }
        p0 += __shfl_xor_sync(0xffffffffu, p0, 1);
        p0 += __shfl_xor_sync(0xffffffffu, p0, 2);
        p1 += __shfl_xor_sync(0xffffffffu, p1, 1);
        p1 += __shfl_xor_sync(0xffffffffu, p1, 2);
        if (tq == 0) {
            snorm[wn * 128 + wm * 32 + mt * 16 + g]     = p0;
            snorm[wn * 128 + wm * 32 + mt * 16 + g + 8] = p1;
        }
    }
    __syncthreads();

    const int typ = bx >> 3;       // 0=q, 1=k, 2=v
    const int h   = bx & 7;

    #pragma unroll
    for (int mt = 0; mt < 2; mt++) {
        const int r0 = wm * 32 + mt * 16 + g;
        const int r1 = r0 + 8;
        const float inv0 = rsqrtf(snorm[r0] + snorm[128 + r0]);
        const float inv1 = rsqrtf(snorm[r1] + snorm[128 + r1]);

        if (typ == 0) {
            // q: scale 25/norm -> 2-term A-image
            const float s0 = SCALE_F * inv0, s1 = SCALE_F * inv1;
            const int baseW = ((wm * 2 + mt) * 32 + g * 4 + tq) * 4;
            #pragma unroll
            for (int ntp = 0; ntp < 4; ntp++) {
                uint32_t hw[4], lw[4];
                #pragma unroll
                for (int sub = 0; sub < 2; sub++) {
                    const int nt = ntp * 2 + sub;
                    split2(acc[mt][nt][0] * s0, acc[mt][nt][1] * s0, hw[sub*2],   lw[sub*2]);
                    split2(acc[mt][nt][2] * s1, acc[mt][nt][3] * s1, hw[sub*2+1], lw[sub*2+1]);
                }
                uint32_t* tb = (uint32_t*)(qp + ((size_t)(h * 16 + by) * 8 + wn * 4 + ntp) * 768);
                *reinterpret_cast<uint4*>(&tb[baseW])        = make_uint4(hw[0], hw[1], hw[2], hw[3]);
                *reinterpret_cast<uint4*>(&tb[1024 + baseW]) = make_uint4(lw[0], lw[1], lw[2], lw[3]);
            }
        } else if (typ == 1) {
            // k: scale 1/norm -> hi-only B-image
            const float s0 = inv0, s1 = inv1;
            const int bw0 = ((wm * 4 + mt * 2) * 32 + g * 4 + tq) * 2;
            #pragma unroll
            for (int ntp = 0; ntp < 4; ntp++) {
                const int nt0 = ntp * 2, nt1 = ntp * 2 + 1;
                uint32_t h00 = packbf(acc[mt][nt0][0] * s0, acc[mt][nt0][1] * s0);
                uint32_t h01 = packbf(acc[mt][nt1][0] * s0, acc[mt][nt1][1] * s0);
                uint32_t h10 = packbf(acc[mt][nt0][2] * s1, acc[mt][nt0][3] * s1);
                uint32_t h11 = packbf(acc[mt][nt1][2] * s1, acc[mt][nt1][3] * s1);
                uint32_t* tb = (uint32_t*)(kp + ((size_t)(h * 16 + by) * 8 + wn * 4 + ntp) * 768);
                *reinterpret_cast<uint2*>(&tb[bw0])      = make_uint2(h00, h01);
                *reinterpret_cast<uint2*>(&tb[bw0 + 64]) = make_uint2(h10, h11);
            }
        } else {
            // v: raw -> x_ori; scaled -> vn A-image + B-image (hi only)
            const float s0 = inv0, s1 = inv1;
            const int baseW = ((wm * 2 + mt) * 32 + g * 4 + tq) * 4;
            const int bw0 = ((wm * 4 + mt * 2) * 32 + g * 4 + tq) * 2;
            #pragma unroll
            for (int ntp = 0; ntp < 4; ntp++) {
                const int nt0 = ntp * 2, nt1 = ntp * 2 + 1;
                #pragma unroll
                for (int sub = 0; sub < 2; sub++) {
                    const int nt = ntp * 2 + sub;
                    const int col = wn * 64 + nt * 8 + tq * 2;
                    float* d0 = xori + (size_t)(by * 128 + r0) * (2 * Cc) + Cc + h * HD + col;
                    float* d1 = xori + (size_t)(by * 128 + r1) * (2 * Cc) + Cc + h * HD + col;
                    *reinterpret_cast<float2*>(d0) = make_float2(acc[mt][nt][0], acc[mt][nt][1]);
                    *reinterpret_cast<float2*>(d1) = make_float2(acc[mt][nt][2], acc[mt][nt][3]);
                }
                {
                    uint32_t hw[4];
                    hw[0] = packbf(acc[mt][nt0][0] * s0, acc[mt][nt0][1] * s0);
                    hw[1] = packbf(acc[mt][nt0][2] * s1, acc[mt][nt0][3] * s1);
                    hw[2] = packbf(acc[mt][nt1][0] * s0, acc[mt][nt1][1] * s0);
                    hw[3] = packbf(acc[mt][nt1][2] * s1, acc[mt][nt1][3] * s1);
                    uint32_t* tb = (uint32_t*)(vnA + ((size_t)by * 64 + h * 8 + wn * 4 + ntp) * 768);
                    *reinterpret_cast<uint4*>(&tb[baseW]) = make_uint4(hw[0], hw[1], hw[2], hw[3]);
                }
                {
                    uint32_t h00 = packbf(acc[mt][nt0][0] * s0, acc[mt][nt0][1] * s0);
                    uint32_t h01 = packbf(acc[mt][nt1][0] * s0, acc[mt][nt1][1] * s0);
                    uint32_t h10 = packbf(acc[mt][nt0][2] * s1, acc[mt][nt0][3] * s1);
                    uint32_t h11 = packbf(acc[mt][nt1][2] * s1, acc[mt][nt1][3] * s1);
                    uint32_t* tb = (uint32_t*)(vnB + ((size_t)by * 64 + h * 8 + wn * 4 + ntp) * 768);
                    *reinterpret_cast<uint2*>(&tb[bw0])      = make_uint2(h00, h01);
                    *reinterpret_cast<uint2*>(&tb[bw0 + 64]) = make_uint2(h10, h11);
                }
            }
        }
    }
}

// ---------------- packed bf16 GEMM (MODE 0/2/3), cp.async 3-stage ----------------
template<int MODE, int PROD>
__global__ __launch_bounds__(256, 2) void gemm_pk(
    const uint4* __restrict__ At, const uint4* __restrict__ Bt,
    int nK, int nKtotA, int nKtotB, int nRbA, int nRbB, int kzBits,
    float* __restrict__ C, int ldc, long long cZ,
    const float* __restrict__ cls, uint4* __restrict__ epk,
    float* __restrict__ rsOut, uint8_t* __restrict__ maskOut)
{
    int bx, by;
    if (MODE == 3) {
        int r = blockIdx.x, row = 0;
        while (r >= 16 - row) { r -= 16 - row; row++; }
        by = row; bx = row + r;
    } else { bx = blockIdx.x; by = blockIdx.y; }

    const int hz = blockIdx.z >> kzBits;
    const int kz = blockIdx.z & ((1 << kzBits) - 1);
    const uint4* Ab = At + ((size_t)(hz * nRbA + by) * nKtotA + (size_t)kz * nK) * 768;
    const uint4* Bb = Bt + ((size_t)(hz * nRbB + bx) * nKtotB + (size_t)kz * nK) * 768;

    __shared__ uint4 smA[3][512], smB[3][512];

    const int tid = threadIdx.x, lane = tid & 31, wid = tid >> 5;
    const int wm = wid >> 1, wn = wid & 1;

    float acc[2][8][4];
    #pragma unroll
    for (int mt = 0; mt < 2; mt++)
        #pragma unroll
        for (int nt = 0; nt < 8; nt++)
            #pragma unroll
            for (int r = 0; r < 4; r++) acc[mt][nt][r] = 0.f;

    auto stage_load = [&](int kb, int st) {
        const uint4* An = Ab + (size_t)kb * 768;
        const uint4* Bn = Bb + (size_t)kb * 768;
        cpa16(&smA[st][tid], An + tid);
        if (PROD >= 2) cpa16(&smA[st][256 + tid], An + 256 + tid);
        cpa16(&smB[st][tid], Bn + tid);
        if (PROD >= 3) cpa16(&smB[st][256 + tid], Bn + 256 + tid);
        CP_COMMIT();
    };

    stage_load(0, 0);
    if (nK > 1) stage_load(1, 1);

    int cur = 0;
    for (int kb = 0; kb < nK; kb++) {
        if (kb + 2 <= nK) CP_WAIT1(); else CP_WAIT0();
        __syncthreads();

        uint32_t af[2][2][4];
        #pragma unroll
        for (int mt = 0; mt < 2; mt++)
            *reinterpret_cast<uint4*>(af[0][mt]) =
                smA[cur][(wm * 2 + mt) * 32 + lane];
        if (PROD >= 2) {
            #pragma unroll
            for (int mt = 0; mt < 2; mt++)
                *reinterpret_cast<uint4*>(af[1][mt]) =
                    smA[cur][256 + (wm * 2 + mt) * 32 + lane];
        }

        const uint2* B2 = reinterpret_cast<const uint2*>(smB[cur]);
        uint2 b0[8];
        #pragma unroll
        for (int nt = 0; nt < 8; nt++) b0[nt] = B2[(wn * 8 + nt) * 32 + lane];
        #pragma unroll
        for (int nt = 0; nt < 8; nt++)
            #pragma unroll
            for (int mt = 0; mt < 2; mt++)
                mma_bf16(acc[mt][nt], af[0][mt], b0[nt].x, b0[nt].y);   // hi*hi
        if (PROD >= 2) {
            #pragma unroll
            for (int nt = 0; nt < 8; nt++)
                #pragma unroll
                for (int mt = 0; mt < 2; mt++)
                    mma_bf16(acc[mt][nt], af[1][mt], b0[nt].x, b0[nt].y);  // lo*hi
        }
        if (PROD >= 3) {
            uint2 b1[8];
            #pragma unroll
            for (int nt = 0; nt < 8; nt++) b1[nt] = B2[512 + (wn * 8 + nt) * 32 + lane];
            #pragma unroll
            for (int nt = 0; nt < 8; nt++)
                #pragma unroll
                for (int mt = 0; mt < 2; mt++)
                    mma_bf16(acc[mt][nt], af[0][mt], b1[nt].x, b1[nt].y);  // hi*lo
        }

        if (kb + 2 < nK) stage_load(kb + 2, (kb + 2) % 3);
        else CP_COMMIT();
        cur = (cur + 1 == 3) ? 0 : cur + 1;
    }

    const int g = lane >> 2, tq = lane & 3;

    if (MODE == 2) {
        #pragma unroll
        for (int mt = 0; mt < 2; mt++) {
            const int m = wm * 2 + mt;
            const int i0 = by * 128 + m * 16 + g;
            const int i1 = i0 + 8;
            const float tha = cls[i0] - 0.1f;
            const float thb = cls[i1] - 0.1f;
            float rs0 = 0.f, rs1 = 0.f;
            const int baseW = (m * 32 + g * 4 + tq) * 4;
            #pragma unroll
            for (int ntp = 0; ntp < 4; ntp++) {
                uint32_t hw[4];
                #pragma unroll
                for (int sub = 0; sub < 2; sub++) {
                    const int nt = ntp * 2 + sub;
                    const int j = bx * 128 + wn * 64 + nt * 8 + tq * 2;
                    const float cj0 = cls[j], cj1 = cls[j + 1];
                    float e00 = (cj0 > tha) ? __expf(acc[mt][nt][0] * cj0) : 1.f;
                    float e01 = (cj1 > tha) ? __expf(acc[mt][nt][1] * cj1) : 1.f;
                    float e10 = (cj0 > thb) ? __expf(acc[mt][nt][2] * cj0) : 1.f;
                    float e11 = (cj1 > thb) ? __expf(acc[mt][nt][3] * cj1) : 1.f;
                    rs0 += e00 + e01;
                    rs1 += e10 + e11;
                    hw[sub * 2]     = packbf(e00, e01);
                    hw[sub * 2 + 1] = packbf(e10, e11);
                }
                const size_t tIdx = (size_t)(hz * 16 + by) * 128 + bx * 8 + wn * 4 + ntp;
                uint32_t* tb = (uint32_t*)(epk + tIdx * 768);
                *reinterpret_cast<uint4*>(&tb[baseW]) =
                    make_uint4(hw[0], hw[1], hw[2], hw[3]);
            }
            rs0 += __shfl_xor_sync(0xffffffffu, rs0, 1);
            rs0 += __shfl_xor_sync(0xffffffffu, rs0, 2);
            rs1 += __shfl_xor_sync(0xffffffffu, rs1, 1);
            rs1 += __shfl_xor_sync(0xffffffffu, rs1, 2);
            if (tq == 0) {
                atomicAdd(&rsOut[hz * Nn + i0], rs0);
                atomicAdd(&rsOut[hz * Nn + i1], rs1);
            }
        }
    } else if (MODE == 3) {
        __syncthreads();
        uint8_t* sb = reinterpret_cast<uint8_t*>(smA);
        #pragma unroll
        for (int mt = 0; mt < 2; mt++)
            #pragma unroll
            for (int nt = 0; nt < 8; nt++) {
                const int r0 = wm * 32 + mt * 16 + g;
                const int c0 = wn * 64 + nt * 8 + tq * 2;
                sb[r0 * 144 + c0]           = acc[mt][nt][0] > 6.f;
                sb[r0 * 144 + c0 + 1]       = acc[mt][nt][1] > 6.f;
                sb[(r0 + 8) * 144 + c0]     = acc[mt][nt][2] > 6.f;
                sb[(r0 + 8) * 144 + c0 + 1] = acc[mt][nt][3] > 6.f;
            }
        __syncthreads();
        const int r = tid >> 1, hf = tid & 1;
        {
            const uint8_t* srcp = sb + r * 144 + hf * 64;
            uint4 v0 = *reinterpret_cast<const uint4*>(srcp);
            uint4 v1 = *reinterpret_cast<const uint4*>(srcp + 16);
            uint4 v2 = *reinterpret_cast<const uint4*>(srcp + 32);
            uint4 v3 = *reinterpret_cast<const uint4*>(srcp + 48);
            uint8_t* dst = maskOut + (size_t)(by * 128 + r) * Nn + bx * 128 + hf * 64;
            *reinterpret_cast<uint4*>(dst)      = v0;
            *reinterpret_cast<uint4*>(dst + 16) = v1;
            *reinterpret_cast<uint4*>(dst + 32) = v2;
            *reinterpret_cast<uint4*>(dst + 48) = v3;
        }
        {
            uint32_t wv[16];
            #pragma unroll
            for (int q = 0; q < 16; q++) {
                uint32_t b0 = sb[(hf * 64 + q * 4 + 0) * 144 + r];
                uint32_t b1 = sb[(hf * 64 + q * 4 + 1) * 144 + r];
                uint32_t b2 = sb[(hf * 64 + q * 4 + 2) * 144 + r];
                uint32_t b3 = sb[(hf * 64 + q * 4 + 3) * 144 + r];
                wv[q] = b0 | (b1 << 8) | (b2 << 16) | (b3 << 24);
            }
            uint8_t* dst = maskOut + (size_t)(bx * 128 + r) * Nn + by * 128 + hf * 64;
            #pragma unroll
            for (int q = 0; q < 4; q++)
                *reinterpret_cast<uint4*>(dst + q * 16) =
                    make_uint4(wv[q*4], wv[q*4+1], wv[q*4+2], wv[q*4+3]);
        }
    } else {
        float* Cz = C + (long long)blockIdx.z * cZ;
        #pragma unroll
        for (int mt = 0; mt < 2; mt++) {
            const int row0 = by * 128 + wm * 32 + mt * 16 + g;
            #pragma unroll
            for (int nt = 0; nt < 8; nt++) {
                const int col = bx * 128 + wn * 64 + nt * 8 + tq * 2;
                *reinterpret_cast<float2*>(&Cz[(long long)row0 * ldc + col]) =
                    make_float2(acc[mt][nt][0], acc[mt][nt][1]);
                *reinterpret_cast<float2*>(&Cz[(long long)(row0 + 8) * ldc + col]) =
                    make_float2(acc[mt][nt][2], acc[mt][nt][3]);
            }
        }
    }
}

// ---------------- combine split-K partials ----------------
__global__ __launch_bounds__(256) void combine_kernel(float* __restrict__ out)
{
    int idx = blockIdx.x * 256 + threadIdx.x;
    if (idx >= Nn * Cc / 4) return;
    const int n = idx >> 8, c4 = idx & 255;
    const int h = c4 >> 5, d4 = c4 & 31;
    const float4* p = reinterpret_cast<const float4*>(g_part);
    const size_t st = (size_t)Nn * 32;
    const size_t b = ((size_t)(h * 2) * Nn + n) * 32 + d4;
    float4 a0 = p[b], a1 = p[b + st];
    const float s = 1.f / g_rowsum[h * Nn + n];
    *reinterpret_cast<float4*>(out + (size_t)n * (2 * Cc) + h * 128 + d4 * 4) =
        make_float4((a0.x + a1.x) * s, (a0.y + a1.y) * s,
                    (a0.z + a1.z) * s, (a0.w + a1.w) * s);
}

// ---------------- simround2 merged ----------------
__global__ __launch_bounds__(256) void simr2_merged(float* __restrict__ out)
{
    const int blk = blockIdx.x;
    const int rowBlk = blk >> 3, m = blk & 7;
    const int tid = threadIdx.x;
    const int gg = tid >> 5;
    const int lane = tid & 31;
    const int i0 = blk * 16 + gg;
    const int i1 = i0 + 8;
    const int ubase = m * 32 + gg * 4;
    __shared__ float sinv[16];

    float irs0[8], irs1[8];
    #pragma unroll
    for (int h = 0; h < 8; h++) {
        irs0[h] = 1.f / g_rowsum[h * Nn + i0];
        irs1[h] = 1.f / g_rowsum[h * Nn + i1];
    }

    float e0r[64], e1r[64];
    float msum0 = 0.f, msum1 = 0.f;
    #pragma unroll
    for (int kt = 0; kt < 4; kt++) {
        const int kb = lane + kt * 32;
        float a0[16], a1[16];
        #pragma unroll
        for (int p = 0; p < 16; p++) { a0[p] = 0.f; a1[p] = 0.f; }
        #pragma unroll
        for (int h = 0; h < 8; h++) {
            const uint4* blob = g_epk + ((size_t)((h * 16 + rowBlk) * 128 + kb)) * 768;
            const float w0 = irs0[h], w1 = irs1[h];
            #pragma unroll
            for (int t = 0; t < 4; t++) {
                uint4 H = blob[ubase + t];
                a0[t*2+0]   += blo(H.x) * w0;
                a0[t*2+1]   += bhi(H.x) * w0;
                a1[t*2+0]   += blo(H.y) * w1;
                a1[t*2+1]   += bhi(H.y) * w1;
                a0[8+t*2+0] += blo(H.z) * w0;
                a0[8+t*2+1] += bhi(H.z) * w0;
                a1[8+t*2+0] += blo(H.w) * w1;
                a1[8+t*2+1] += bhi(H.w) * w1;
            }
        }
        const int j0 = kb * 16;
        uint4 mv0 = *reinterpret_cast<const uint4*>(g_mask + (size_t)i0 * Nn + j0);
        uint4 mv1 = *reinterpret_cast<const uint4*>(g_mask + (size_t)i1 * Nn + j0);
        const uint8_t* mb0 = reinterpret_cast<const uint8_t*>(&mv0);
        const uint8_t* mb1 = reinterpret_cast<const uint8_t*>(&mv1);
        #pragma unroll
        for (int p = 0; p < 16; p++) {
            float e0 = __expf(a0[p] * 0.125f);
            float e1 = __expf(a1[p] * 0.125f);
            e0r[kt * 16 + p] = e0;
            e1r[kt * 16 + p] = e1;
            if (mb0[p]) msum0 += e0;
            if (mb1[p]) msum1 += e1;
        }
    }
    #pragma unroll
    for (int o = 16; o > 0; o >>= 1) {
        msum0 += __shfl_xor_sync(0xffffffffu, msum0, o);
        msum1 += __shfl_xor_sync(0xffffffffu, msum1, o);
    }
    if (lane == 0) { sinv[gg] = 1.f / msum0; sinv[8 + gg] = 1.f / msum1; }
    __syncthreads();
    const float inv0 = sinv[gg], inv1 = sinv[8 + gg];

    #pragma unroll
    for (int kt = 0; kt < 4; kt++) {
        const int j0 = (lane + kt * 32) * 16;
        uint4 mv0 = *reinterpret_cast<const uint4*>(g_mask + (size_t)i0 * Nn + j0);
        uint4 mv1 = *reinterpret_cast<const uint4*>(g_mask + (size_t)i1 * Nn + j0);
        const uint8_t* mb0 = reinterpret_cast<const uint8_t*>(&mv0);
        const uint8_t* mb1 = reinterpret_cast<const uint8_t*>(&mv1);
        float* d0 = out + (size_t)i0 * Nn + j0;
        float* d1 = out + (size_t)i1 * Nn + j0;
        #pragma unroll
        for (int q = 0; q < 4; q++) {
            float4 o0, o1;
            o0.x = mb0[q*4+0] ? e0r[kt*16 + q*4+0] * inv0 : 0.f;
            o0.y = mb0[q*4+1] ? e0r[kt*16 + q*4+1] * inv0 : 0.f;
            o0.z = mb0[q*4+2] ? e0r[kt*16 + q*4+2] * inv0 : 0.f;
            o0.w = mb0[q*4+3] ? e0r[kt*16 + q*4+3] * inv0 : 0.f;
            o1.x = mb1[q*4+0] ? e1r[kt*16 + q*4+0] * inv1 : 0.f;
            o1.y = mb1[q*4+1] ? e1r[kt*16 + q*4+1] * inv1 : 0.f;
            o1.z = mb1[q*4+2] ? e1r[kt*16 + q*4+2] * inv1 : 0.f;
            o1.w = mb1[q*4+3] ? e1r[kt*16 + q*4+3] * inv1 : 0.f;
            *reinterpret_cast<float4*>(d0 + q * 4) = o0;
            *reinterpret_cast<float4*>(d1 + q * 4) = o1;
        }
    }
}

// ---------------- host launcher (multi-stream fork/join) ----------------
extern "C" void kernel_launch(void* const* d_in, const int* in_sizes, int n_in,
                              void* d_out, int out_size)
{
    const float* x   = (const float*)d_in[0];
    const float* cls = (const float*)d_in[1];
    const float* W   = (const float*)d_in[3];
    float* out = (float*)d_out;

    float *p_rs, *p_part;
    uint4 *p_xp, *p_Wp, *p_qp, *p_kp, *p_vnpA, *p_vnpB, *p_vTp, *p_epk;
    uint8_t* p_mask;
    cudaGetSymbolAddress((void**)&p_rs, g_rowsum);
    cudaGetSymbolAddress((void**)&p_part, g_part);
    cudaGetSymbolAddress((void**)&p_xp, g_xp);
    cudaGetSymbolAddress((void**)&p_Wp, g_Wp);
    cudaGetSymbolAddress((void**)&p_qp, g_qp);
    cudaGetSymbolAddress((void**)&p_kp, g_kp);
    cudaGetSymbolAddress((void**)&p_vnpA, g_vnpA);
    cudaGetSymbolAddress((void**)&p_vnpB, g_vnpB);
    cudaGetSymbolAddress((void**)&p_vTp, g_vTp);
    cudaGetSymbolAddress((void**)&p_epk, g_epk);
    cudaGetSymbolAddress((void**)&p_mask, g_mask);

    static cudaStream_t s1 = nullptr;
    static cudaEvent_t evV = nullptr, evVtp = nullptr, evLog = nullptr, evEnd = nullptr;
    if (!s1) {
        cudaStreamCreateWithFlags(&s1, cudaStreamNonBlocking);
        cudaEventCreateWithFlags(&evV, cudaEventDisableTiming);
        cudaEventCreateWithFlags(&evVtp, cudaEventDisableTiming);
        cudaEventCreateWithFlags(&evLog, cudaEventDisableTiming);
        cudaEventCreateWithFlags(&evEnd, cudaEventDisableTiming);
    }

    // ---- main stream ----
    cudaMemsetAsync(p_rs, 0, Hh * Nn * sizeof(float));
    pack_a<2><<<dim3(64, 16, 1), 256>>>(x, Cc, 0, p_xp, 64);
    pack_b<2><<<dim3(64, 24, 1), 256>>>(W, Cc, 0, p_Wp, 64);

    // 1a. qkv GEMM, v tiles only (128 CTAs, partial wave)
    gemm_qkv<<<dim3(8, 16), 256>>>(p_xp, p_Wp, 16, p_qp, p_kp, p_vnpA, p_vnpB, out);
    cudaEventRecord(evV, 0);

    // ---- side stream: vT pack + sim mask fill idle slots of qk wave ----
    cudaStreamWaitEvent(s1, evV, 0);
    pack_vT<<<dim3(128, 8), 256, 0, s1>>>(out, p_vTp);
    cudaEventRecord(evVtp, s1);
    gemm_pk<3, 1><<<dim3(136, 1, 1), 256, 0, s1>>>(p_vnpA, p_vnpB, 64, 64, 64, 16, 16, 0,
                                                   nullptr, 0, 0, nullptr, nullptr, nullptr, p_mask);

    // 1b. qkv GEMM, q/k tiles (256 CTAs)
    gemm_qkv<<<dim3(16, 16), 256>>>(p_xp, p_Wp, 0, p_qp, p_kp, p_vnpA, p_vnpB, out);

    // 2. logits (2 products: (q_hi+q_lo) * k_hi) + fused masked-exp epilogue
    gemm_pk<2, 2><<<dim3(16, 16, 8), 256>>>(p_qp, p_kp, 8, 8, 8, 16, 16, 0,
                                            nullptr, 0, 0, cls, p_epk, p_rs, nullptr);
    cudaEventRecord(evLog, 0);

    // side stream: simr2
    cudaStreamWaitEvent(s1, evLog, 0);
    simr2_merged<<<128, 256, 0, s1>>>(out + (size_t)Nn * 2 * Cc);
    cudaEventRecord(evEnd, s1);

    // main stream: attn@V split-K x2 (1 product), combine
    cudaStreamWaitEvent(0, evVtp, 0);
    gemm_pk<0, 1><<<dim3(1, 16, 16), 256>>>(p_epk, p_vTp, 64, 128, 128, 16, 1, 1,
                                            p_part, HD, (long long)Nn * HD,
                                            nullptr, nullptr, nullptr, nullptr);
    combine_kernel<<<(Nn * Cc / 4 + 255) / 256, 256>>>(out);

    cudaStreamWaitEvent(0, evEnd, 0);
}